// round 7
// baseline (speedup 1.0000x reference)
#include <cuda_runtime.h>
#include <cuda_fp16.h>
#include <cstdint>

// Problem constants
#define BB 512
#define NN 256
#define DD 128
#define BND ((size_t)BB * NN * DD)

static __device__ __half g_W1h[DD * DD], g_W1l[DD * DD];
static __device__ __half g_W2h[DD * DD], g_W2l[DD * DD];
static __device__ __half g_Mh[BND], g_Ml[BND];       // mirror split
static __device__ __half g_Sh[BND], g_Sl[BND];       // sat_out split
static __device__ __half g_Kh[BND], g_Kl[BND];       // K2C split (COMPACT rows)
static __device__ int g_idx[BB * NN];                // compact pos -> j
static __device__ int g_nv[BB];                      // valid count per batch
static __device__ int g_mwidth1;

#define SCALE 0.08838834764831845f  // 1/sqrt(128)

// ============================ PTX helpers ==================================
__device__ __forceinline__ uint32_t smem_u32(const void* p) {
    uint32_t a;
    asm("{ .reg .u64 t; cvta.to.shared.u64 t, %1; cvt.u32.u64 %0, t; }" : "=r"(a) : "l"(p));
    return a;
}

#define LDSM_X4(r, a) \
    asm volatile("ldmatrix.sync.aligned.m8n8.x4.shared.b16 {%0,%1,%2,%3}, [%4];" \
        : "=r"((r)[0]), "=r"((r)[1]), "=r"((r)[2]), "=r"((r)[3]) : "r"(a))
#define LDSM_X4T(r, a) \
    asm volatile("ldmatrix.sync.aligned.m8n8.x4.trans.shared.b16 {%0,%1,%2,%3}, [%4];" \
        : "=r"((r)[0]), "=r"((r)[1]), "=r"((r)[2]), "=r"((r)[3]) : "r"(a))

__device__ __forceinline__ void mma_fp16(float* c, const uint32_t* a, uint32_t b0, uint32_t b1) {
    asm volatile(
        "mma.sync.aligned.m16n8k16.row.col.f32.f16.f16.f32 "
        "{%0,%1,%2,%3}, {%4,%5,%6,%7}, {%8,%9}, {%0,%1,%2,%3};"
        : "+f"(c[0]), "+f"(c[1]), "+f"(c[2]), "+f"(c[3])
        : "r"(a[0]), "r"(a[1]), "r"(a[2]), "r"(a[3]), "r"(b0), "r"(b1));
}

__device__ __forceinline__ void split_pack(float x, float y, uint32_t& h, uint32_t& l) {
    __half hx = __float2half(x);
    __half hy = __float2half(y);
    __half lx = __float2half(x - __half2float(hx));
    __half ly = __float2half(y - __half2float(hy));
    __half2 hh; hh.x = hx; hh.y = hy;
    __half2 ll; ll.x = lx; ll.y = ly;
    h = *(uint32_t*)&hh;
    l = *(uint32_t*)&ll;
}

// ======================= mask canonicalization + compaction ================
__global__ void detect_mask_kernel(const unsigned int* __restrict__ m) {
    __shared__ int red[256];
    int tid = threadIdx.x;
    int p = 0;
    for (int i = tid; i < (BB * NN) / 4; i += 256) {
        unsigned int w = m[i];
        if (w != 0u && w != 1u && w != 0x3F800000u) p = 1;
    }
    red[tid] = p;
    __syncthreads();
    for (int s = 128; s > 0; s >>= 1) {
        if (tid < s) red[tid] |= red[tid + s];
        __syncthreads();
    }
    if (tid == 0) g_mwidth1 = red[0];
}

__global__ void decode_compact_kernel(const void* __restrict__ m) {
    int b = blockIdx.x;
    int tid = threadIdx.x;
    int w = tid >> 5, l = tid & 31;
    __shared__ int wcnt[8], woff[8];
    int i = b * NN + tid;
    int valid;
    if (g_mwidth1) valid = (((const unsigned char*)m)[i] != 0);
    else           valid = (((const unsigned int*)m)[i] != 0u);
    unsigned bal = __ballot_sync(0xffffffffu, valid);
    int pre = __popc(bal & ((1u << l) - 1u));
    if (l == 31) wcnt[w] = __popc(bal);
    g_idx[i] = 0;   // prefill pads with a safe (valid) index
    __syncthreads();
    if (tid == 0) {
        int s = 0;
        for (int k = 0; k < 8; k++) { woff[k] = s; s += wcnt[k]; }
        g_nv[b] = s;
    }
    __syncthreads();
    if (valid) g_idx[b * NN + woff[w] + pre] = tid;
}

// ======================= weight contraction (scaled + split) ===============
// grid (128, 2), block 512: 4 k-chunks x 128 cols, smem reduce.
__global__ void prep_w_kernel(const float* __restrict__ Wq1, const float* __restrict__ Wk1,
                              const float* __restrict__ Wq2, const float* __restrict__ Wk2) {
    int a = blockIdx.x;
    int c = threadIdx.x & 127, kc = threadIdx.x >> 7;
    __shared__ float red[512];
    const float* X = (blockIdx.y == 0) ? Wq1 : Wq2;
    const float* Y = (blockIdx.y == 0) ? Wk1 : Wk2;
    float acc = 0.f;
#pragma unroll 8
    for (int k = kc * 32; k < kc * 32 + 32; k++)
        acc = fmaf(X[k * DD + c], Y[k * DD + a], acc);
    red[kc * 128 + c] = acc;
    __syncthreads();
    if (kc == 0) {
        float v = (red[c] + red[128 + c]) + (red[256 + c] + red[384 + c]);
        v *= SCALE;
        __half h = __float2half(v);
        __half lo = __float2half(v - __half2float(h));
        int idx = a * DD + c;
        if (blockIdx.y == 0) { g_W1h[idx] = h; g_W1l[idx] = lo; }
        else                 { g_W2h[idx] = h; g_W2l[idx] = lo; }
    }
}

// ======================= fused: M split + T GEMM + gate + sat_out ==========
// CTA = 128 rows. Converts M to split fp16 (writes g_Mh/g_Ml), computes
// T = Mh @ (W1h + W1l) in registers, alpha = rowdot(S, T), and emits
// sat_out (fp32 to d_out) plus its split (g_Sh/g_Sl). No T traffic at all.
#define GT_A   0
#define GT_WH  34816
#define GT_WL  69632
#define GT_SMEM 104448

__global__ __launch_bounds__(256, 1)
void gemm_T_fused(const float* __restrict__ M, const float* __restrict__ S,
                  float* __restrict__ SO) {
    extern __shared__ char smem[];
    __shared__ float s_red[256];
    uint32_t sbase = smem_u32(smem);
    int tid = threadIdx.x;
    int w = tid >> 5, l = tid & 31;
    size_t n0 = (size_t)blockIdx.x * 128;

    // stage W1 split
    for (int idx = tid; idx < 2048; idx += 256) {
        int row = idx >> 4, c8 = idx & 15;
        *(uint4*)(smem + GT_WH + row * 272 + c8 * 16) =
            *(const uint4*)(g_W1h + row * DD + c8 * 8);
        *(uint4*)(smem + GT_WL + row * 272 + c8 * 16) =
            *(const uint4*)(g_W1l + row * DD + c8 * 8);
    }
    // convert M rows: global fp32 -> split fp16 (global) + Mh smem tile
    for (int idx = tid; idx < 8192; idx += 256) {
        int row = idx >> 6, c2 = idx & 63;
        float2 v = ((const float2*)(M + (n0 + row) * DD))[c2];
        uint32_t h, lo;
        split_pack(v.x, v.y, h, lo);
        ((uint32_t*)(g_Mh + (n0 + row) * DD))[c2] = h;
        ((uint32_t*)(g_Ml + (n0 + row) * DD))[c2] = lo;
        *(uint32_t*)(smem + GT_A + row * 272 + c2 * 4) = h;
    }
    __syncthreads();

    int mw = w & 3, nwp = w >> 2;
    int r0 = mw * 32, c0 = nwp * 64;
    float acc[2][8][4];
#pragma unroll
    for (int i = 0; i < 2; i++)
#pragma unroll
        for (int j = 0; j < 8; j++)
#pragma unroll
            for (int q = 0; q < 4; q++) acc[i][j][q] = 0.f;

    uint32_t halfOff = (uint32_t)((l >> 4) << 3);
#pragma unroll 1
    for (int ks = 0; ks < 8; ks++) {
        int k0 = 16 * ks;
        uint32_t aH0[4], aH1[4];
        uint32_t aaddr0 = sbase + GT_A + (r0 + (l & 15)) * 272 + (k0 + halfOff) * 2;
        LDSM_X4(aH0, aaddr0);
        LDSM_X4(aH1, aaddr0 + 16 * 272);
#pragma unroll
        for (int np = 0; np < 4; np++) {
            uint32_t baddr = sbase + GT_WH + (uint32_t)(k0 + (l & 15)) * 272 +
                             (uint32_t)(c0 + 16 * np + halfOff) * 2;
            uint32_t bH[4], bL[4];
            LDSM_X4T(bH, baddr);
            LDSM_X4T(bL, baddr + (GT_WL - GT_WH));
            mma_fp16(acc[0][2 * np],     aH0, bH[0], bH[1]);
            mma_fp16(acc[0][2 * np],     aH0, bL[0], bL[1]);
            mma_fp16(acc[0][2 * np + 1], aH0, bH[2], bH[3]);
            mma_fp16(acc[0][2 * np + 1], aH0, bL[2], bL[3]);
            mma_fp16(acc[1][2 * np],     aH1, bH[0], bH[1]);
            mma_fp16(acc[1][2 * np],     aH1, bL[0], bL[1]);
            mma_fp16(acc[1][2 * np + 1], aH1, bH[2], bH[3]);
            mma_fp16(acc[1][2 * np + 1], aH1, bL[2], bL[3]);
        }
    }

    // --- epilogue: alpha = rowdot(S, T), then sat_out + split ---
    int g = l >> 2, t = l & 3;
    float p[2][2] = {{0.f, 0.f}, {0.f, 0.f}};
#pragma unroll
    for (int mt = 0; mt < 2; mt++) {
        size_t rA = n0 + r0 + mt * 16 + g, rB = rA + 8;
#pragma unroll
        for (int nt = 0; nt < 8; nt++) {
            int col = c0 + nt * 8 + 2 * t;
            float2 sa = *(const float2*)(S + rA * DD + col);
            float2 sb = *(const float2*)(S + rB * DD + col);
            p[mt][0] += sa.x * acc[mt][nt][0] + sa.y * acc[mt][nt][1];
            p[mt][1] += sb.x * acc[mt][nt][2] + sb.y * acc[mt][nt][3];
        }
    }
#pragma unroll
    for (int mt = 0; mt < 2; mt++)
#pragma unroll
        for (int q = 0; q < 2; q++) {
            p[mt][q] += __shfl_xor_sync(0xffffffffu, p[mt][q], 1);
            p[mt][q] += __shfl_xor_sync(0xffffffffu, p[mt][q], 2);
        }
    if (t == 0) {
#pragma unroll
        for (int mt = 0; mt < 2; mt++) {
            s_red[nwp * 128 + r0 + mt * 16 + g] = p[mt][0];
            s_red[nwp * 128 + r0 + mt * 16 + g + 8] = p[mt][1];
        }
    }
    __syncthreads();

#pragma unroll
    for (int mt = 0; mt < 2; mt++) {
        int riA = r0 + mt * 16 + g, riB = riA + 8;
        float alA = s_red[riA] + s_red[128 + riA];
        float alB = s_red[riB] + s_red[128 + riB];
        size_t rA = n0 + riA, rB = n0 + riB;
#pragma unroll
        for (int nt = 0; nt < 8; nt++) {
            int col = c0 + nt * 8 + 2 * t;
            float2 sa = *(const float2*)(S + rA * DD + col);
            float2 ma = *(const float2*)(M + rA * DD + col);
            float2 oa;
            oa.x = fmaf(alA, ma.x - sa.x, sa.x);
            oa.y = fmaf(alA, ma.y - sa.y, sa.y);
            *(float2*)(SO + rA * DD + col) = oa;
            uint32_t h, lo;
            split_pack(oa.x, oa.y, h, lo);
            *(uint32_t*)(g_Sh + rA * DD + col) = h;
            *(uint32_t*)(g_Sl + rA * DD + col) = lo;

            float2 sb = *(const float2*)(S + rB * DD + col);
            float2 mb = *(const float2*)(M + rB * DD + col);
            float2 ob;
            ob.x = fmaf(alB, mb.x - sb.x, sb.x);
            ob.y = fmaf(alB, mb.y - sb.y, sb.y);
            *(float2*)(SO + rB * DD + col) = ob;
            split_pack(ob.x, ob.y, h, lo);
            *(uint32_t*)(g_Sh + rB * DD + col) = h;
            *(uint32_t*)(g_Sl + rB * DD + col) = lo;
        }
    }
}

// ======================= K2C GEMM (3-term, gathered, compact out) ==========
#define GK_AH  0
#define GK_AL  34816
#define GK_WH  69632
#define GK_WL  104448
#define GK_SMEM 139264

__global__ __launch_bounds__(256, 1)
void gemm_K2C_kernel() {
    int b = blockIdx.x >> 1;
    int pos0 = (blockIdx.x & 1) * 128;
    if (pos0 >= g_nv[b]) return;
    extern __shared__ char smem[];
    uint32_t sbase = smem_u32(smem);
    int tid = threadIdx.x;
    int w = tid >> 5, l = tid & 31;

    for (int idx = tid; idx < 2048; idx += 256) {
        int row = idx >> 4, c8 = idx & 15;
        int j = g_idx[b * NN + pos0 + row];
        size_t srow = ((size_t)b * NN + j) * DD;
        *(uint4*)(smem + GK_AH + row * 272 + c8 * 16) = *(const uint4*)(g_Sh + srow + c8 * 8);
        *(uint4*)(smem + GK_AL + row * 272 + c8 * 16) = *(const uint4*)(g_Sl + srow + c8 * 8);
        *(uint4*)(smem + GK_WH + row * 272 + c8 * 16) = *(const uint4*)(g_W2h + row * DD + c8 * 8);
        *(uint4*)(smem + GK_WL + row * 272 + c8 * 16) = *(const uint4*)(g_W2l + row * DD + c8 * 8);
    }
    __syncthreads();

    int mw = w & 3, nwp = w >> 2;
    int r0 = mw * 32, c0 = nwp * 64;
    float acc[2][8][4];
#pragma unroll
    for (int i = 0; i < 2; i++)
#pragma unroll
        for (int j = 0; j < 8; j++)
#pragma unroll
            for (int q = 0; q < 4; q++) acc[i][j][q] = 0.f;

    uint32_t halfOff = (uint32_t)((l >> 4) << 3);
#pragma unroll 1
    for (int ks = 0; ks < 8; ks++) {
        int k0 = 16 * ks;
        uint32_t aH0[4], aL0[4], aH1[4], aL1[4];
        uint32_t aaddr0 = sbase + GK_AH + (r0 + (l & 15)) * 272 + (k0 + halfOff) * 2;
        LDSM_X4(aH0, aaddr0);
        LDSM_X4(aL0, aaddr0 + (GK_AL - GK_AH));
        LDSM_X4(aH1, aaddr0 + 16 * 272);
        LDSM_X4(aL1, aaddr0 + 16 * 272 + (GK_AL - GK_AH));
#pragma unroll
        for (int np = 0; np < 4; np++) {
            uint32_t baddr = sbase + GK_WH + (uint32_t)(k0 + (l & 15)) * 272 +
                             (uint32_t)(c0 + 16 * np + halfOff) * 2;
            uint32_t bH[4], bL[4];
            LDSM_X4T(bH, baddr);
            LDSM_X4T(bL, baddr + (GK_WL - GK_WH));
            mma_fp16(acc[0][2 * np],     aH0, bH[0], bH[1]);
            mma_fp16(acc[0][2 * np],     aH0, bL[0], bL[1]);
            mma_fp16(acc[0][2 * np],     aL0, bH[0], bH[1]);
            mma_fp16(acc[0][2 * np + 1], aH0, bH[2], bH[3]);
            mma_fp16(acc[0][2 * np + 1], aH0, bL[2], bL[3]);
            mma_fp16(acc[0][2 * np + 1], aL0, bH[2], bH[3]);
            mma_fp16(acc[1][2 * np],     aH1, bH[0], bH[1]);
            mma_fp16(acc[1][2 * np],     aH1, bL[0], bL[1]);
            mma_fp16(acc[1][2 * np],     aL1, bH[0], bH[1]);
            mma_fp16(acc[1][2 * np + 1], aH1, bH[2], bH[3]);
            mma_fp16(acc[1][2 * np + 1], aH1, bL[2], bL[3]);
            mma_fp16(acc[1][2 * np + 1], aL1, bH[2], bH[3]);
        }
    }

    int g = l >> 2, t = l & 3;
#pragma unroll
    for (int mt = 0; mt < 2; mt++)
#pragma unroll
        for (int nt = 0; nt < 8; nt++) {
            size_t rowA = (size_t)b * NN + pos0 + r0 + mt * 16 + g;
            size_t rowB = rowA + 8;
            int col = c0 + nt * 8 + 2 * t;
            uint32_t h, lo;
            split_pack(acc[mt][nt][0], acc[mt][nt][1], h, lo);
            *(uint32_t*)(g_Kh + rowA * DD + col) = h;
            *(uint32_t*)(g_Kl + rowA * DD + col) = lo;
            split_pack(acc[mt][nt][2], acc[mt][nt][3], h, lo);
            *(uint32_t*)(g_Kh + rowB * DD + col) = h;
            *(uint32_t*)(g_Kl + rowB * DD + col) = lo;
        }
}

// ======================= fused attention (compacted keys) ==================
#define SM_QH  0
#define SM_QL  17408
#define SM_KH  34816
#define SM_KL  104448
#define SM_PH  0
#define SM_VH  34816
#define SM_VL  104448
#define SMEM_ATTN 174080

#define BETA_CHUNK(ACC, CBASE, NSTEPS) do {                                         \
    _Pragma("unroll")                                                               \
    for (int ks = 0; ks < 8; ks++) {                                                \
        int k0 = 16 * ks;                                                           \
        uint32_t aH[4], aL[4];                                                      \
        uint32_t aaddr = sbase + SM_QH + aRow * 272 + (k0 + halfOff) * 2;           \
        LDSM_X4(aH, aaddr);                                                         \
        LDSM_X4(aL, aaddr + (SM_QL - SM_QH));                                       \
        _Pragma("unroll")                                                           \
        for (int np = 0; np < 4; np++) {                                            \
            if (np >= (NSTEPS)) break;                                              \
            uint32_t baddr = sbase + SM_KH +                                        \
                (uint32_t)((CBASE) + nw * 64 + 16 * np + bRowBase) * 272 +          \
                (k0 + bColHalf) * 2;                                                \
            uint32_t bH[4], bL[4];                                                  \
            LDSM_X4(bH, baddr);                                                     \
            LDSM_X4(bL, baddr + (SM_KL - SM_KH));                                   \
            mma_fp16(ACC[2 * np],     aH, bH[0], bH[1]);                            \
            mma_fp16(ACC[2 * np],     aH, bL[0], bL[1]);                            \
            mma_fp16(ACC[2 * np],     aL, bH[0], bH[1]);                            \
            mma_fp16(ACC[2 * np + 1], aH, bH[2], bH[3]);                            \
            mma_fp16(ACC[2 * np + 1], aH, bL[2], bL[3]);                            \
            mma_fp16(ACC[2 * np + 1], aL, bH[2], bH[3]);                            \
        }                                                                           \
    }                                                                               \
} while (0)

__global__ __launch_bounds__(256, 1)
void attn_kernel(float* __restrict__ O) {
    extern __shared__ char smem[];
    __shared__ float s_bias[256];
    __shared__ float s_red[256];
    __shared__ int s_idx[256];
    uint32_t sbase = smem_u32(smem);

    int tid = threadIdx.x;
    int w = tid >> 5, l = tid & 31;
    int g = l >> 2, t = l & 3;
    int mw = w & 3, nw = w >> 2;
    int b = blockIdx.y;
    int i0 = blockIdx.x * 64;
    size_t boff = (size_t)b * NN * DD;

    int nv = g_nv[b];
    int kpadN = (nv + 15) & ~15;

    s_idx[tid] = g_idx[b * NN + tid];
    s_bias[tid] = (tid < nv) ? 0.f : -1e30f;

    // stage Q (64 rows of M split)
    for (int idx = tid; idx < 64 * 16; idx += 256) {
        int row = idx >> 4, c8 = idx & 15;
        size_t src = boff + (size_t)(i0 + row) * DD + c8 * 8;
        *(uint4*)(smem + SM_QH + row * 272 + c8 * 16) = *(const uint4*)(g_Mh + src);
        *(uint4*)(smem + SM_QL + row * 272 + c8 * 16) = *(const uint4*)(g_Ml + src);
    }
    // stage K compact rows [0, kpadN) (zero pads)
    {
        uint4 z = make_uint4(0, 0, 0, 0);
        for (int idx = tid; idx < kpadN * 16; idx += 256) {
            int row = idx >> 4, c8 = idx & 15;
            uint4 vh = z, vl = z;
            if (row < nv) {
                size_t src = boff + (size_t)row * DD + c8 * 8;
                vh = *(const uint4*)(g_Kh + src);
                vl = *(const uint4*)(g_Kl + src);
            }
            *(uint4*)(smem + SM_KH + row * 272 + c8 * 16) = vh;
            *(uint4*)(smem + SM_KL + row * 272 + c8 * 16) = vl;
        }
    }
    __syncthreads();

    // --- beta GEMM over valid 16-col tiles only ---
    uint32_t aRow = (uint32_t)(16 * mw + (l & 15));
    uint32_t halfOff = (uint32_t)((l >> 4) << 3);
    uint32_t bRowBase = (uint32_t)(((l >> 4) << 3) + (l & 7));
    uint32_t bColHalf = (uint32_t)(((l >> 3) & 1) << 3);

    int base0 = nw * 64, base1 = 128 + nw * 64;
    int ns0 = min(4, max(0, (kpadN - base0) >> 4));
    int ns1 = min(4, max(0, (kpadN - base1) >> 4));

    float acc0[8][4], acc1[8][4];
#pragma unroll
    for (int j = 0; j < 8; j++)
#pragma unroll
        for (int q = 0; q < 4; q++) { acc0[j][q] = 0.f; acc1[j][q] = 0.f; }

    if (ns0 > 0) BETA_CHUNK(acc0, 0, ns0);
    if (ns1 > 0) BETA_CHUNK(acc1, 128, ns1);

    // --- masked softmax (rows rowA, rowB) ---
    int rowA = 16 * mw + g, rowB = rowA + 8;
    float mx0 = -3.0e38f, mx1 = -3.0e38f;
#pragma unroll
    for (int j = 0; j < 8; j++) {
        float2 bv = *(const float2*)&s_bias[nw * 64 + j * 8 + 2 * t];
        acc0[j][0] += bv.x; acc0[j][1] += bv.y;
        acc0[j][2] += bv.x; acc0[j][3] += bv.y;
        mx0 = fmaxf(mx0, fmaxf(acc0[j][0], acc0[j][1]));
        mx1 = fmaxf(mx1, fmaxf(acc0[j][2], acc0[j][3]));
    }
    if (kpadN > 128) {
#pragma unroll
        for (int j = 0; j < 8; j++) {
            float2 bv = *(const float2*)&s_bias[128 + nw * 64 + j * 8 + 2 * t];
            acc1[j][0] += bv.x; acc1[j][1] += bv.y;
            acc1[j][2] += bv.x; acc1[j][3] += bv.y;
            mx0 = fmaxf(mx0, fmaxf(acc1[j][0], acc1[j][1]));
            mx1 = fmaxf(mx1, fmaxf(acc1[j][2], acc1[j][3]));
        }
    }
    mx0 = fmaxf(mx0, __shfl_xor_sync(0xffffffffu, mx0, 1));
    mx0 = fmaxf(mx0, __shfl_xor_sync(0xffffffffu, mx0, 2));
    mx1 = fmaxf(mx1, __shfl_xor_sync(0xffffffffu, mx1, 1));
    mx1 = fmaxf(mx1, __shfl_xor_sync(0xffffffffu, mx1, 2));
    if (t == 0) {
        s_red[nw * 64 + rowA] = mx0;
        s_red[nw * 64 + rowB] = mx1;
    }
    __syncthreads();
    float M0 = fmaxf(s_red[rowA], s_red[64 + rowA]);
    float M1 = fmaxf(s_red[rowB], s_red[64 + rowB]);
    float s0 = 0.f, s1 = 0.f;
#pragma unroll
    for (int j = 0; j < 8; j++) {
        acc0[j][0] = __expf(acc0[j][0] - M0); s0 += acc0[j][0];
        acc0[j][1] = __expf(acc0[j][1] - M0); s0 += acc0[j][1];
        acc0[j][2] = __expf(acc0[j][2] - M1); s1 += acc0[j][2];
        acc0[j][3] = __expf(acc0[j][3] - M1); s1 += acc0[j][3];
    }
    if (kpadN > 128) {
#pragma unroll
        for (int j = 0; j < 8; j++) {
            acc1[j][0] = __expf(acc1[j][0] - M0); s0 += acc1[j][0];
            acc1[j][1] = __expf(acc1[j][1] - M0); s0 += acc1[j][1];
            acc1[j][2] = __expf(acc1[j][2] - M1); s1 += acc1[j][2];
            acc1[j][3] = __expf(acc1[j][3] - M1); s1 += acc1[j][3];
        }
    }
    s0 += __shfl_xor_sync(0xffffffffu, s0, 1);
    s0 += __shfl_xor_sync(0xffffffffu, s0, 2);
    s1 += __shfl_xor_sync(0xffffffffu, s1, 1);
    s1 += __shfl_xor_sync(0xffffffffu, s1, 2);
    __syncthreads();
    if (t == 0) {
        s_red[128 + nw * 64 + rowA] = s0;
        s_red[128 + nw * 64 + rowB] = s1;
    }
    __syncthreads();
    float inv0 = __fdividef(1.f, s_red[128 + rowA] + s_red[128 + 64 + rowA]);
    float inv1 = __fdividef(1.f, s_red[128 + rowB] + s_red[128 + 64 + rowB]);

    // --- write P (fp16 hi only) over retired Q region ---
    {
        char* ph = smem + SM_PH;
#pragma unroll
        for (int j = 0; j < 8; j++) {
            int col = nw * 64 + j * 8 + 2 * t;
            __half2 a; a.x = __float2half(acc0[j][0] * inv0); a.y = __float2half(acc0[j][1] * inv0);
            *(uint32_t*)(ph + rowA * 528 + col * 2) = *(uint32_t*)&a;
            __half2 c; c.x = __float2half(acc0[j][2] * inv1); c.y = __float2half(acc0[j][3] * inv1);
            *(uint32_t*)(ph + rowB * 528 + col * 2) = *(uint32_t*)&c;
        }
        if (kpadN > 128) {
#pragma unroll
            for (int j = 0; j < 8; j++) {
                int col = 128 + nw * 64 + j * 8 + 2 * t;
                __half2 a; a.x = __float2half(acc1[j][0] * inv0); a.y = __float2half(acc1[j][1] * inv0);
                *(uint32_t*)(ph + rowA * 528 + col * 2) = *(uint32_t*)&a;
                __half2 c; c.x = __float2half(acc1[j][2] * inv1); c.y = __float2half(acc1[j][3] * inv1);
                *(uint32_t*)(ph + rowB * 528 + col * 2) = *(uint32_t*)&c;
            }
        }
    }
    // --- stage V gathered (overlays retired K) ---
    {
        uint4 z = make_uint4(0, 0, 0, 0);
        for (int idx = tid; idx < kpadN * 16; idx += 256) {
            int row = idx >> 4, c8 = idx & 15;
            uint4 vh = z, vl = z;
            if (row < nv) {
                size_t src = boff + (size_t)s_idx[row] * DD + c8 * 8;
                vh = *(const uint4*)(g_Mh + src);
                vl = *(const uint4*)(g_Ml + src);
            }
            *(uint4*)(smem + SM_VH + row * 272 + c8 * 16) = vh;
            *(uint4*)(smem + SM_VL + row * 272 + c8 * 16) = vl;
        }
    }
    __syncthreads();

    // --- PV GEMM: 2-term (P hi * (Vh + Vl)), k up to kpadN ---
    int d0 = 64 * nw;
    float o[8][4];
#pragma unroll
    for (int i = 0; i < 8; i++)
#pragma unroll
        for (int j = 0; j < 4; j++) o[i][j] = 0.f;

    int ksteps = kpadN >> 4;
#pragma unroll 1
    for (int ks = 0; ks < ksteps; ks++) {
        int k0 = 16 * ks;
        uint32_t aH[4];
        LDSM_X4(aH, sbase + SM_PH + aRow * 528 + (k0 + halfOff) * 2);
#pragma unroll
        for (int np = 0; np < 4; np++) {
            uint32_t baddr = sbase + SM_VH + (uint32_t)(k0 + (l & 15)) * 272 +
                             (uint32_t)(d0 + 16 * np + halfOff) * 2;
            uint32_t bH[4], bL[4];
            LDSM_X4T(bH, baddr);
            LDSM_X4T(bL, baddr + (SM_VL - SM_VH));
            mma_fp16(o[2 * np],     aH, bH[0], bH[1]);
            mma_fp16(o[2 * np],     aH, bL[0], bL[1]);
            mma_fp16(o[2 * np + 1], aH, bH[2], bH[3]);
            mma_fp16(o[2 * np + 1], aH, bL[2], bL[3]);
        }
    }

    float* Ob = O + ((size_t)b * NN + i0) * DD;
#pragma unroll
    for (int nt = 0; nt < 8; nt++) {
        int col = d0 + 8 * nt + 2 * t;
        *(float2*)&Ob[(size_t)rowA * DD + col] = make_float2(o[nt][0], o[nt][1]);
        *(float2*)&Ob[(size_t)rowB * DD + col] = make_float2(o[nt][2], o[nt][3]);
    }
}

// ---------------------------------------------------------------------------
extern "C" void kernel_launch(void* const* d_in, const int* in_sizes, int n_in,
                              void* d_out, int out_size) {
    (void)in_sizes; (void)n_in; (void)out_size;
    const float* mirror    = (const float*)d_in[0];
    const float* satellite = (const float*)d_in[1];
    const void*  mask      = d_in[2];
    const float* Wq1 = (const float*)d_in[3];
    const float* Wk1 = (const float*)d_in[4];
    const float* Wq2 = (const float*)d_in[5];
    const float* Wk2 = (const float*)d_in[6];
    float* sat_out = (float*)d_out;
    float* mir_out = (float*)d_out + BND;

    cudaFuncSetAttribute(gemm_T_fused,    cudaFuncAttributeMaxDynamicSharedMemorySize, GT_SMEM);
    cudaFuncSetAttribute(gemm_K2C_kernel, cudaFuncAttributeMaxDynamicSharedMemorySize, GK_SMEM);
    cudaFuncSetAttribute(attn_kernel,     cudaFuncAttributeMaxDynamicSharedMemorySize, SMEM_ATTN);

    detect_mask_kernel<<<1, 256>>>((const unsigned int*)mask);
    decode_compact_kernel<<<BB, 256>>>(mask);
    prep_w_kernel<<<dim3(128, 2), 512>>>(Wq1, Wk1, Wq2, Wk2);

    gemm_T_fused<<<(BB * NN) / 128, 256, GT_SMEM>>>(mirror, satellite, sat_out);
    gemm_K2C_kernel<<<(BB * NN) / 128, 256, GK_SMEM>>>();
    attn_kernel<<<dim3(NN / 64, BB), 256, SMEM_ATTN>>>(mir_out);
}

// round 8
// speedup vs baseline: 1.0167x; 1.0167x over previous
#include <cuda_runtime.h>
#include <cuda_fp16.h>
#include <cstdint>

// Problem constants
#define BB 512
#define NN 256
#define DD 128
#define BND ((size_t)BB * NN * DD)

static __device__ __half g_W1h[DD * DD], g_W1l[DD * DD];
static __device__ __half g_W2h[DD * DD], g_W2l[DD * DD];
static __device__ __half g_Mh[BND], g_Ml[BND];       // mirror split
static __device__ __half g_Sh[BND], g_Sl[BND];       // sat_out split
static __device__ __half g_Kh[BND], g_Kl[BND];       // K2C split (COMPACT rows)
static __device__ int g_idx[BB * NN];                // compact pos -> j
static __device__ int g_nv[BB];                      // valid count per batch
static __device__ int g_mwidth1;

#define SCALE 0.08838834764831845f  // 1/sqrt(128)

// ============================ PTX helpers ==================================
__device__ __forceinline__ uint32_t smem_u32(const void* p) {
    uint32_t a;
    asm("{ .reg .u64 t; cvta.to.shared.u64 t, %1; cvt.u32.u64 %0, t; }" : "=r"(a) : "l"(p));
    return a;
}

#define LDSM_X4(r, a) \
    asm volatile("ldmatrix.sync.aligned.m8n8.x4.shared.b16 {%0,%1,%2,%3}, [%4];" \
        : "=r"((r)[0]), "=r"((r)[1]), "=r"((r)[2]), "=r"((r)[3]) : "r"(a))
#define LDSM_X4T(r, a) \
    asm volatile("ldmatrix.sync.aligned.m8n8.x4.trans.shared.b16 {%0,%1,%2,%3}, [%4];" \
        : "=r"((r)[0]), "=r"((r)[1]), "=r"((r)[2]), "=r"((r)[3]) : "r"(a))

__device__ __forceinline__ void mma_fp16(float* c, const uint32_t* a, uint32_t b0, uint32_t b1) {
    asm volatile(
        "mma.sync.aligned.m16n8k16.row.col.f32.f16.f16.f32 "
        "{%0,%1,%2,%3}, {%4,%5,%6,%7}, {%8,%9}, {%0,%1,%2,%3};"
        : "+f"(c[0]), "+f"(c[1]), "+f"(c[2]), "+f"(c[3])
        : "r"(a[0]), "r"(a[1]), "r"(a[2]), "r"(a[3]), "r"(b0), "r"(b1));
}

__device__ __forceinline__ void split_pack(float x, float y, uint32_t& h, uint32_t& l) {
    __half hx = __float2half(x);
    __half hy = __float2half(y);
    __half lx = __float2half(x - __half2float(hx));
    __half ly = __float2half(y - __half2float(hy));
    __half2 hh; hh.x = hx; hh.y = hy;
    __half2 ll; ll.x = lx; ll.y = ly;
    h = *(uint32_t*)&hh;
    l = *(uint32_t*)&ll;
}

// ======================= mask canonicalization + compaction ================
__global__ void detect_mask_kernel(const unsigned int* __restrict__ m) {
    __shared__ int red[256];
    int tid = threadIdx.x;
    int p = 0;
    for (int i = tid; i < (BB * NN) / 4; i += 256) {
        unsigned int w = m[i];
        if (w != 0u && w != 1u && w != 0x3F800000u) p = 1;
    }
    red[tid] = p;
    __syncthreads();
    for (int s = 128; s > 0; s >>= 1) {
        if (tid < s) red[tid] |= red[tid + s];
        __syncthreads();
    }
    if (tid == 0) g_mwidth1 = red[0];
}

__global__ void decode_compact_kernel(const void* __restrict__ m) {
    int b = blockIdx.x;
    int tid = threadIdx.x;
    int w = tid >> 5, l = tid & 31;
    __shared__ int wcnt[8], woff[8];
    int i = b * NN + tid;
    int valid;
    if (g_mwidth1) valid = (((const unsigned char*)m)[i] != 0);
    else           valid = (((const unsigned int*)m)[i] != 0u);
    unsigned bal = __ballot_sync(0xffffffffu, valid);
    int pre = __popc(bal & ((1u << l) - 1u));
    if (l == 31) wcnt[w] = __popc(bal);
    g_idx[i] = 0;   // prefill pads with a safe (valid) index
    __syncthreads();
    if (tid == 0) {
        int s = 0;
        for (int k = 0; k < 8; k++) { woff[k] = s; s += wcnt[k]; }
        g_nv[b] = s;
    }
    __syncthreads();
    if (valid) g_idx[b * NN + woff[w] + pre] = tid;
}

// ======================= weight contraction (scaled + split) ===============
__global__ void prep_w_kernel(const float* __restrict__ Wq1, const float* __restrict__ Wk1,
                              const float* __restrict__ Wq2, const float* __restrict__ Wk2) {
    int a = blockIdx.x;
    int c = threadIdx.x & 127, kc = threadIdx.x >> 7;
    __shared__ float red[512];
    const float* X = (blockIdx.y == 0) ? Wq1 : Wq2;
    const float* Y = (blockIdx.y == 0) ? Wk1 : Wk2;
    float acc = 0.f;
#pragma unroll 8
    for (int k = kc * 32; k < kc * 32 + 32; k++)
        acc = fmaf(X[k * DD + c], Y[k * DD + a], acc);
    red[kc * 128 + c] = acc;
    __syncthreads();
    if (kc == 0) {
        float v = (red[c] + red[128 + c]) + (red[256 + c] + red[384 + c]);
        v *= SCALE;
        __half h = __float2half(v);
        __half lo = __float2half(v - __half2float(h));
        int idx = a * DD + c;
        if (blockIdx.y == 0) { g_W1h[idx] = h; g_W1l[idx] = lo; }
        else                 { g_W2h[idx] = h; g_W2l[idx] = lo; }
    }
}

// ======================= fused: M split + T GEMM + gate + sat_out ==========
// CTA = 64 rows (grid 2048), 2 CTAs/SM.  T in registers; alpha = rowdot(S,T);
// emits sat_out fp32 + split, and M split as a side product.
#define GT_A    0
#define GT_WH   17408
#define GT_WL   52224
#define GT_SMEM 87040

__global__ __launch_bounds__(256, 2)
void gemm_T_fused(const float* __restrict__ M, const float* __restrict__ S,
                  float* __restrict__ SO) {
    extern __shared__ char smem[];
    __shared__ float s_red[128];
    uint32_t sbase = smem_u32(smem);
    int tid = threadIdx.x;
    int w = tid >> 5, l = tid & 31;
    size_t n0 = (size_t)blockIdx.x * 64;

    // stage W1 split
    for (int idx = tid; idx < 2048; idx += 256) {
        int row = idx >> 4, c8 = idx & 15;
        *(uint4*)(smem + GT_WH + row * 272 + c8 * 16) =
            *(const uint4*)(g_W1h + row * DD + c8 * 8);
        *(uint4*)(smem + GT_WL + row * 272 + c8 * 16) =
            *(const uint4*)(g_W1l + row * DD + c8 * 8);
    }
    // convert M rows: fp32 -> split fp16 (global) + Mh smem tile
    for (int idx = tid; idx < 4096; idx += 256) {
        int row = idx >> 6, c2 = idx & 63;
        float2 v = ((const float2*)(M + (n0 + row) * DD))[c2];
        uint32_t h, lo;
        split_pack(v.x, v.y, h, lo);
        ((uint32_t*)(g_Mh + (n0 + row) * DD))[c2] = h;
        ((uint32_t*)(g_Ml + (n0 + row) * DD))[c2] = lo;
        *(uint32_t*)(smem + GT_A + row * 272 + c2 * 4) = h;
    }
    __syncthreads();

    int mw = w & 3, nwp = w >> 2;
    int r0 = mw * 16, c0 = nwp * 64;
    float acc[8][4];
#pragma unroll
    for (int j = 0; j < 8; j++)
#pragma unroll
        for (int q = 0; q < 4; q++) acc[j][q] = 0.f;

    uint32_t halfOff = (uint32_t)((l >> 4) << 3);
#pragma unroll 1
    for (int ks = 0; ks < 8; ks++) {
        int k0 = 16 * ks;
        uint32_t aH[4];
        LDSM_X4(aH, sbase + GT_A + (r0 + (l & 15)) * 272 + (k0 + halfOff) * 2);
#pragma unroll
        for (int np = 0; np < 4; np++) {
            uint32_t baddr = sbase + GT_WH + (uint32_t)(k0 + (l & 15)) * 272 +
                             (uint32_t)(c0 + 16 * np + halfOff) * 2;
            uint32_t bH[4], bL[4];
            LDSM_X4T(bH, baddr);
            LDSM_X4T(bL, baddr + (GT_WL - GT_WH));
            mma_fp16(acc[2 * np],     aH, bH[0], bH[1]);
            mma_fp16(acc[2 * np],     aH, bL[0], bL[1]);
            mma_fp16(acc[2 * np + 1], aH, bH[2], bH[3]);
            mma_fp16(acc[2 * np + 1], aH, bL[2], bL[3]);
        }
    }

    // --- epilogue: alpha = rowdot(S, T), then sat_out + split ---
    int g = l >> 2, t = l & 3;
    int rowA = r0 + g, rowB = rowA + 8;
    float p0 = 0.f, p1 = 0.f;
    {
        size_t rA = n0 + rowA, rB = n0 + rowB;
#pragma unroll
        for (int nt = 0; nt < 8; nt++) {
            int col = c0 + nt * 8 + 2 * t;
            float2 sa = *(const float2*)(S + rA * DD + col);
            float2 sb = *(const float2*)(S + rB * DD + col);
            p0 += sa.x * acc[nt][0] + sa.y * acc[nt][1];
            p1 += sb.x * acc[nt][2] + sb.y * acc[nt][3];
        }
    }
    p0 += __shfl_xor_sync(0xffffffffu, p0, 1);
    p0 += __shfl_xor_sync(0xffffffffu, p0, 2);
    p1 += __shfl_xor_sync(0xffffffffu, p1, 1);
    p1 += __shfl_xor_sync(0xffffffffu, p1, 2);
    if (t == 0) {
        s_red[nwp * 64 + rowA] = p0;
        s_red[nwp * 64 + rowB] = p1;
    }
    __syncthreads();

    float alA = s_red[rowA] + s_red[64 + rowA];
    float alB = s_red[rowB] + s_red[64 + rowB];
    size_t rA = n0 + rowA, rB = n0 + rowB;
#pragma unroll
    for (int nt = 0; nt < 8; nt++) {
        int col = c0 + nt * 8 + 2 * t;
        float2 sa = *(const float2*)(S + rA * DD + col);
        float2 ma = *(const float2*)(M + rA * DD + col);
        float2 oa;
        oa.x = fmaf(alA, ma.x - sa.x, sa.x);
        oa.y = fmaf(alA, ma.y - sa.y, sa.y);
        *(float2*)(SO + rA * DD + col) = oa;
        uint32_t h, lo;
        split_pack(oa.x, oa.y, h, lo);
        *(uint32_t*)(g_Sh + rA * DD + col) = h;
        *(uint32_t*)(g_Sl + rA * DD + col) = lo;

        float2 sb = *(const float2*)(S + rB * DD + col);
        float2 mb = *(const float2*)(M + rB * DD + col);
        float2 ob;
        ob.x = fmaf(alB, mb.x - sb.x, sb.x);
        ob.y = fmaf(alB, mb.y - sb.y, sb.y);
        *(float2*)(SO + rB * DD + col) = ob;
        split_pack(ob.x, ob.y, h, lo);
        *(uint32_t*)(g_Sh + rB * DD + col) = h;
        *(uint32_t*)(g_Sl + rB * DD + col) = lo;
    }
}

// ======================= K2C GEMM (3-term, gathered, compact out) ==========
// CTA = 64 compact rows (grid BB*4, early exit), 2 CTAs/SM.
#define GK_AH   0
#define GK_AL   17408
#define GK_WH   34816
#define GK_WL   69632
#define GK_SMEM 104448

__global__ __launch_bounds__(256, 2)
void gemm_K2C_kernel() {
    int b = blockIdx.x >> 2;
    int pos0 = (blockIdx.x & 3) * 64;
    if (pos0 >= g_nv[b]) return;
    extern __shared__ char smem[];
    uint32_t sbase = smem_u32(smem);
    int tid = threadIdx.x;
    int w = tid >> 5, l = tid & 31;

    for (int idx = tid; idx < 1024; idx += 256) {
        int row = idx >> 4, c8 = idx & 15;
        int j = g_idx[b * NN + pos0 + row];
        size_t srow = ((size_t)b * NN + j) * DD;
        *(uint4*)(smem + GK_AH + row * 272 + c8 * 16) = *(const uint4*)(g_Sh + srow + c8 * 8);
        *(uint4*)(smem + GK_AL + row * 272 + c8 * 16) = *(const uint4*)(g_Sl + srow + c8 * 8);
    }
    for (int idx = tid; idx < 2048; idx += 256) {
        int row = idx >> 4, c8 = idx & 15;
        *(uint4*)(smem + GK_WH + row * 272 + c8 * 16) = *(const uint4*)(g_W2h + row * DD + c8 * 8);
        *(uint4*)(smem + GK_WL + row * 272 + c8 * 16) = *(const uint4*)(g_W2l + row * DD + c8 * 8);
    }
    __syncthreads();

    int mw = w & 3, nwp = w >> 2;
    int r0 = mw * 16, c0 = nwp * 64;
    float acc[8][4];
#pragma unroll
    for (int j = 0; j < 8; j++)
#pragma unroll
        for (int q = 0; q < 4; q++) acc[j][q] = 0.f;

    uint32_t halfOff = (uint32_t)((l >> 4) << 3);
#pragma unroll 1
    for (int ks = 0; ks < 8; ks++) {
        int k0 = 16 * ks;
        uint32_t aH[4], aL[4];
        uint32_t aaddr = sbase + GK_AH + (r0 + (l & 15)) * 272 + (k0 + halfOff) * 2;
        LDSM_X4(aH, aaddr);
        LDSM_X4(aL, aaddr + (GK_AL - GK_AH));
#pragma unroll
        for (int np = 0; np < 4; np++) {
            uint32_t baddr = sbase + GK_WH + (uint32_t)(k0 + (l & 15)) * 272 +
                             (uint32_t)(c0 + 16 * np + halfOff) * 2;
            uint32_t bH[4], bL[4];
            LDSM_X4T(bH, baddr);
            LDSM_X4T(bL, baddr + (GK_WL - GK_WH));
            mma_fp16(acc[2 * np],     aH, bH[0], bH[1]);
            mma_fp16(acc[2 * np],     aH, bL[0], bL[1]);
            mma_fp16(acc[2 * np],     aL, bH[0], bH[1]);
            mma_fp16(acc[2 * np + 1], aH, bH[2], bH[3]);
            mma_fp16(acc[2 * np + 1], aH, bL[2], bL[3]);
            mma_fp16(acc[2 * np + 1], aL, bH[2], bH[3]);
        }
    }

    int g = l >> 2, t = l & 3;
#pragma unroll
    for (int nt = 0; nt < 8; nt++) {
        size_t rowA = (size_t)b * NN + pos0 + r0 + g;
        size_t rowB = rowA + 8;
        int col = c0 + nt * 8 + 2 * t;
        uint32_t h, lo;
        split_pack(acc[nt][0], acc[nt][1], h, lo);
        *(uint32_t*)(g_Kh + rowA * DD + col) = h;
        *(uint32_t*)(g_Kl + rowA * DD + col) = lo;
        split_pack(acc[nt][2], acc[nt][3], h, lo);
        *(uint32_t*)(g_Kh + rowB * DD + col) = h;
        *(uint32_t*)(g_Kl + rowB * DD + col) = lo;
    }
}

// ======================= fused attention (compacted keys) ==================
#define SM_QH  0
#define SM_QL  17408
#define SM_KH  34816
#define SM_KL  104448
#define SM_PH  0
#define SM_VH  34816
#define SM_VL  104448
#define SMEM_ATTN 174080

#define BETA_CHUNK(ACC, CBASE, NSTEPS) do {                                         \
    _Pragma("unroll")                                                               \
    for (int ks = 0; ks < 8; ks++) {                                                \
        int k0 = 16 * ks;                                                           \
        uint32_t aH[4], aL[4];                                                      \
        uint32_t aaddr = sbase + SM_QH + aRow * 272 + (k0 + halfOff) * 2;           \
        LDSM_X4(aH, aaddr);                                                         \
        LDSM_X4(aL, aaddr + (SM_QL - SM_QH));                                       \
        _Pragma("unroll")                                                           \
        for (int np = 0; np < 4; np++) {                                            \
            if (np >= (NSTEPS)) break;                                              \
            uint32_t baddr = sbase + SM_KH +                                        \
                (uint32_t)((CBASE) + nw * 64 + 16 * np + bRowBase) * 272 +          \
                (k0 + bColHalf) * 2;                                                \
            uint32_t bH[4], bL[4];                                                  \
            LDSM_X4(bH, baddr);                                                     \
            LDSM_X4(bL, baddr + (SM_KL - SM_KH));                                   \
            mma_fp16(ACC[2 * np],     aH, bH[0], bH[1]);                            \
            mma_fp16(ACC[2 * np],     aH, bL[0], bL[1]);                            \
            mma_fp16(ACC[2 * np],     aL, bH[0], bH[1]);                            \
            mma_fp16(ACC[2 * np + 1], aH, bH[2], bH[3]);                            \
            mma_fp16(ACC[2 * np + 1], aH, bL[2], bL[3]);                            \
            mma_fp16(ACC[2 * np + 1], aL, bH[2], bH[3]);                            \
        }                                                                           \
    }                                                                               \
} while (0)

__global__ __launch_bounds__(256, 1)
void attn_kernel(float* __restrict__ O) {
    extern __shared__ char smem[];
    __shared__ float s_bias[256];
    __shared__ float s_red[256];
    __shared__ int s_idx[256];
    uint32_t sbase = smem_u32(smem);

    int tid = threadIdx.x;
    int w = tid >> 5, l = tid & 31;
    int g = l >> 2, t = l & 3;
    int mw = w & 3, nw = w >> 2;
    int b = blockIdx.y;
    int i0 = blockIdx.x * 64;
    size_t boff = (size_t)b * NN * DD;

    int nv = g_nv[b];
    int kpadN = (nv + 15) & ~15;

    s_idx[tid] = g_idx[b * NN + tid];
    s_bias[tid] = (tid < nv) ? 0.f : -1e30f;

    // stage Q (64 rows of M split)
    for (int idx = tid; idx < 64 * 16; idx += 256) {
        int row = idx >> 4, c8 = idx & 15;
        size_t src = boff + (size_t)(i0 + row) * DD + c8 * 8;
        *(uint4*)(smem + SM_QH + row * 272 + c8 * 16) = *(const uint4*)(g_Mh + src);
        *(uint4*)(smem + SM_QL + row * 272 + c8 * 16) = *(const uint4*)(g_Ml + src);
    }
    // stage K compact rows [0, kpadN) (zero pads)
    {
        uint4 z = make_uint4(0, 0, 0, 0);
        for (int idx = tid; idx < kpadN * 16; idx += 256) {
            int row = idx >> 4, c8 = idx & 15;
            uint4 vh = z, vl = z;
            if (row < nv) {
                size_t src = boff + (size_t)row * DD + c8 * 8;
                vh = *(const uint4*)(g_Kh + src);
                vl = *(const uint4*)(g_Kl + src);
            }
            *(uint4*)(smem + SM_KH + row * 272 + c8 * 16) = vh;
            *(uint4*)(smem + SM_KL + row * 272 + c8 * 16) = vl;
        }
    }
    __syncthreads();

    // --- beta GEMM over valid 16-col tiles only ---
    uint32_t aRow = (uint32_t)(16 * mw + (l & 15));
    uint32_t halfOff = (uint32_t)((l >> 4) << 3);
    uint32_t bRowBase = (uint32_t)(((l >> 4) << 3) + (l & 7));
    uint32_t bColHalf = (uint32_t)(((l >> 3) & 1) << 3);

    int base0 = nw * 64, base1 = 128 + nw * 64;
    int ns0 = min(4, max(0, (kpadN - base0) >> 4));
    int ns1 = min(4, max(0, (kpadN - base1) >> 4));

    float acc0[8][4], acc1[8][4];
#pragma unroll
    for (int j = 0; j < 8; j++)
#pragma unroll
        for (int q = 0; q < 4; q++) { acc0[j][q] = 0.f; acc1[j][q] = 0.f; }

    if (ns0 > 0) BETA_CHUNK(acc0, 0, ns0);
    if (ns1 > 0) BETA_CHUNK(acc1, 128, ns1);

    // --- masked softmax (rows rowA, rowB) ---
    int rowA = 16 * mw + g, rowB = rowA + 8;
    float mx0 = -3.0e38f, mx1 = -3.0e38f;
#pragma unroll
    for (int j = 0; j < 8; j++) {
        float2 bv = *(const float2*)&s_bias[nw * 64 + j * 8 + 2 * t];
        acc0[j][0] += bv.x; acc0[j][1] += bv.y;
        acc0[j][2] += bv.x; acc0[j][3] += bv.y;
        mx0 = fmaxf(mx0, fmaxf(acc0[j][0], acc0[j][1]));
        mx1 = fmaxf(mx1, fmaxf(acc0[j][2], acc0[j][3]));
    }
    if (kpadN > 128) {
#pragma unroll
        for (int j = 0; j < 8; j++) {
            float2 bv = *(const float2*)&s_bias[128 + nw * 64 + j * 8 + 2 * t];
            acc1[j][0] += bv.x; acc1[j][1] += bv.y;
            acc1[j][2] += bv.x; acc1[j][3] += bv.y;
            mx0 = fmaxf(mx0, fmaxf(acc1[j][0], acc1[j][1]));
            mx1 = fmaxf(mx1, fmaxf(acc1[j][2], acc1[j][3]));
        }
    }
    mx0 = fmaxf(mx0, __shfl_xor_sync(0xffffffffu, mx0, 1));
    mx0 = fmaxf(mx0, __shfl_xor_sync(0xffffffffu, mx0, 2));
    mx1 = fmaxf(mx1, __shfl_xor_sync(0xffffffffu, mx1, 1));
    mx1 = fmaxf(mx1, __shfl_xor_sync(0xffffffffu, mx1, 2));
    if (t == 0) {
        s_red[nw * 64 + rowA] = mx0;
        s_red[nw * 64 + rowB] = mx1;
    }
    __syncthreads();
    float M0 = fmaxf(s_red[rowA], s_red[64 + rowA]);
    float M1 = fmaxf(s_red[rowB], s_red[64 + rowB]);
    float s0 = 0.f, s1 = 0.f;
#pragma unroll
    for (int j = 0; j < 8; j++) {
        acc0[j][0] = __expf(acc0[j][0] - M0); s0 += acc0[j][0];
        acc0[j][1] = __expf(acc0[j][1] - M0); s0 += acc0[j][1];
        acc0[j][2] = __expf(acc0[j][2] - M1); s1 += acc0[j][2];
        acc0[j][3] = __expf(acc0[j][3] - M1); s1 += acc0[j][3];
    }
    if (kpadN > 128) {
#pragma unroll
        for (int j = 0; j < 8; j++) {
            acc1[j][0] = __expf(acc1[j][0] - M0); s0 += acc1[j][0];
            acc1[j][1] = __expf(acc1[j][1] - M0); s0 += acc1[j][1];
            acc1[j][2] = __expf(acc1[j][2] - M1); s1 += acc1[j][2];
            acc1[j][3] = __expf(acc1[j][3] - M1); s1 += acc1[j][3];
        }
    }
    s0 += __shfl_xor_sync(0xffffffffu, s0, 1);
    s0 += __shfl_xor_sync(0xffffffffu, s0, 2);
    s1 += __shfl_xor_sync(0xffffffffu, s1, 1);
    s1 += __shfl_xor_sync(0xffffffffu, s1, 2);
    __syncthreads();
    if (t == 0) {
        s_red[128 + nw * 64 + rowA] = s0;
        s_red[128 + nw * 64 + rowB] = s1;
    }
    __syncthreads();
    float inv0 = __fdividef(1.f, s_red[128 + rowA] + s_red[128 + 64 + rowA]);
    float inv1 = __fdividef(1.f, s_red[128 + rowB] + s_red[128 + 64 + rowB]);

    // --- write P (fp16 hi only) over retired Q region ---
    {
        char* ph = smem + SM_PH;
#pragma unroll
        for (int j = 0; j < 8; j++) {
            int col = nw * 64 + j * 8 + 2 * t;
            __half2 a; a.x = __float2half(acc0[j][0] * inv0); a.y = __float2half(acc0[j][1] * inv0);
            *(uint32_t*)(ph + rowA * 528 + col * 2) = *(uint32_t*)&a;
            __half2 c; c.x = __float2half(acc0[j][2] * inv1); c.y = __float2half(acc0[j][3] * inv1);
            *(uint32_t*)(ph + rowB * 528 + col * 2) = *(uint32_t*)&c;
        }
        if (kpadN > 128) {
#pragma unroll
            for (int j = 0; j < 8; j++) {
                int col = 128 + nw * 64 + j * 8 + 2 * t;
                __half2 a; a.x = __float2half(acc1[j][0] * inv0); a.y = __float2half(acc1[j][1] * inv0);
                *(uint32_t*)(ph + rowA * 528 + col * 2) = *(uint32_t*)&a;
                __half2 c; c.x = __float2half(acc1[j][2] * inv1); c.y = __float2half(acc1[j][3] * inv1);
                *(uint32_t*)(ph + rowB * 528 + col * 2) = *(uint32_t*)&c;
            }
        }
    }
    // --- stage V gathered (overlays retired K) ---
    {
        uint4 z = make_uint4(0, 0, 0, 0);
        for (int idx = tid; idx < kpadN * 16; idx += 256) {
            int row = idx >> 4, c8 = idx & 15;
            uint4 vh = z, vl = z;
            if (row < nv) {
                size_t src = boff + (size_t)s_idx[row] * DD + c8 * 8;
                vh = *(const uint4*)(g_Mh + src);
                vl = *(const uint4*)(g_Ml + src);
            }
            *(uint4*)(smem + SM_VH + row * 272 + c8 * 16) = vh;
            *(uint4*)(smem + SM_VL + row * 272 + c8 * 16) = vl;
        }
    }
    __syncthreads();

    // --- PV GEMM: 2-term (P hi * (Vh + Vl)), k up to kpadN ---
    int d0 = 64 * nw;
    float o[8][4];
#pragma unroll
    for (int i = 0; i < 8; i++)
#pragma unroll
        for (int j = 0; j < 4; j++) o[i][j] = 0.f;

    int ksteps = kpadN >> 4;
#pragma unroll 1
    for (int ks = 0; ks < ksteps; ks++) {
        int k0 = 16 * ks;
        uint32_t aH[4];
        LDSM_X4(aH, sbase + SM_PH + aRow * 528 + (k0 + halfOff) * 2);
#pragma unroll
        for (int np = 0; np < 4; np++) {
            uint32_t baddr = sbase + SM_VH + (uint32_t)(k0 + (l & 15)) * 272 +
                             (uint32_t)(d0 + 16 * np + halfOff) * 2;
            uint32_t bH[4], bL[4];
            LDSM_X4T(bH, baddr);
            LDSM_X4T(bL, baddr + (SM_VL - SM_VH));
            mma_fp16(o[2 * np],     aH, bH[0], bH[1]);
            mma_fp16(o[2 * np],     aH, bL[0], bL[1]);
            mma_fp16(o[2 * np + 1], aH, bH[2], bH[3]);
            mma_fp16(o[2 * np + 1], aH, bL[2], bL[3]);
        }
    }

    float* Ob = O + ((size_t)b * NN + i0) * DD;
#pragma unroll
    for (int nt = 0; nt < 8; nt++) {
        int col = d0 + 8 * nt + 2 * t;
        *(float2*)&Ob[(size_t)rowA * DD + col] = make_float2(o[nt][0], o[nt][1]);
        *(float2*)&Ob[(size_t)rowB * DD + col] = make_float2(o[nt][2], o[nt][3]);
    }
}

// ---------------------------------------------------------------------------
extern "C" void kernel_launch(void* const* d_in, const int* in_sizes, int n_in,
                              void* d_out, int out_size) {
    (void)in_sizes; (void)n_in; (void)out_size;
    const float* mirror    = (const float*)d_in[0];
    const float* satellite = (const float*)d_in[1];
    const void*  mask      = d_in[2];
    const float* Wq1 = (const float*)d_in[3];
    const float* Wk1 = (const float*)d_in[4];
    const float* Wq2 = (const float*)d_in[5];
    const float* Wk2 = (const float*)d_in[6];
    float* sat_out = (float*)d_out;
    float* mir_out = (float*)d_out + BND;

    cudaFuncSetAttribute(gemm_T_fused,    cudaFuncAttributeMaxDynamicSharedMemorySize, GT_SMEM);
    cudaFuncSetAttribute(gemm_K2C_kernel, cudaFuncAttributeMaxDynamicSharedMemorySize, GK_SMEM);
    cudaFuncSetAttribute(attn_kernel,     cudaFuncAttributeMaxDynamicSharedMemorySize, SMEM_ATTN);

    detect_mask_kernel<<<1, 256>>>((const unsigned int*)mask);
    decode_compact_kernel<<<BB, 256>>>(mask);
    prep_w_kernel<<<dim3(128, 2), 512>>>(Wq1, Wk1, Wq2, Wk2);

    gemm_T_fused<<<(BB * NN) / 64, 256, GT_SMEM>>>(mirror, satellite, sat_out);
    gemm_K2C_kernel<<<BB * 4, 256, GK_SMEM>>>();
    attn_kernel<<<dim3(NN / 64, BB), 256, SMEM_ATTN>>>(mir_out);
}

// round 9
// speedup vs baseline: 1.0867x; 1.0689x over previous
#include <cuda_runtime.h>
#include <cuda_fp16.h>
#include <cstdint>

// Problem constants
#define BB 512
#define NN 256
#define DD 128
#define BND ((size_t)BB * NN * DD)

static __device__ __half g_W1h[DD * DD], g_W1l[DD * DD];
static __device__ __half g_W2h[DD * DD], g_W2l[DD * DD];
static __device__ __half g_Mh[BND], g_Ml[BND];       // mirror split
static __device__ __half g_Sh[BND], g_Sl[BND];       // sat_out split
static __device__ __half g_Kh[BND], g_Kl[BND];       // K2C split (COMPACT rows)
static __device__ int g_idx[BB * NN];                // compact pos -> j
static __device__ int g_nv[BB];                      // valid count per batch
static __device__ int g_mwidth1;

#define SCALE 0.08838834764831845f  // 1/sqrt(128)

// ============================ PTX helpers ==================================
__device__ __forceinline__ uint32_t smem_u32(const void* p) {
    uint32_t a;
    asm("{ .reg .u64 t; cvta.to.shared.u64 t, %1; cvt.u32.u64 %0, t; }" : "=r"(a) : "l"(p));
    return a;
}

#define LDSM_X4(r, a) \
    asm volatile("ldmatrix.sync.aligned.m8n8.x4.shared.b16 {%0,%1,%2,%3}, [%4];" \
        : "=r"((r)[0]), "=r"((r)[1]), "=r"((r)[2]), "=r"((r)[3]) : "r"(a))
#define LDSM_X4T(r, a) \
    asm volatile("ldmatrix.sync.aligned.m8n8.x4.trans.shared.b16 {%0,%1,%2,%3}, [%4];" \
        : "=r"((r)[0]), "=r"((r)[1]), "=r"((r)[2]), "=r"((r)[3]) : "r"(a))

__device__ __forceinline__ void mma_fp16(float* c, const uint32_t* a, uint32_t b0, uint32_t b1) {
    asm volatile(
        "mma.sync.aligned.m16n8k16.row.col.f32.f16.f16.f32 "
        "{%0,%1,%2,%3}, {%4,%5,%6,%7}, {%8,%9}, {%0,%1,%2,%3};"
        : "+f"(c[0]), "+f"(c[1]), "+f"(c[2]), "+f"(c[3])
        : "r"(a[0]), "r"(a[1]), "r"(a[2]), "r"(a[3]), "r"(b0), "r"(b1));
}

__device__ __forceinline__ void split_pack(float x, float y, uint32_t& h, uint32_t& l) {
    __half hx = __float2half(x);
    __half hy = __float2half(y);
    __half lx = __float2half(x - __half2float(hx));
    __half ly = __float2half(y - __half2float(hy));
    __half2 hh; hh.x = hx; hh.y = hy;
    __half2 ll; ll.x = lx; ll.y = ly;
    h = *(uint32_t*)&hh;
    l = *(uint32_t*)&ll;
}

// ======================= mask canonicalization + compaction ================
__global__ void detect_mask_kernel(const unsigned int* __restrict__ m) {
    __shared__ int red[256];
    int tid = threadIdx.x;
    int p = 0;
    for (int i = tid; i < (BB * NN) / 4; i += 256) {
        unsigned int w = m[i];
        if (w != 0u && w != 1u && w != 0x3F800000u) p = 1;
    }
    red[tid] = p;
    __syncthreads();
    for (int s = 128; s > 0; s >>= 1) {
        if (tid < s) red[tid] |= red[tid + s];
        __syncthreads();
    }
    if (tid == 0) g_mwidth1 = red[0];
}

__global__ void decode_compact_kernel(const void* __restrict__ m) {
    int b = blockIdx.x;
    int tid = threadIdx.x;
    int w = tid >> 5, l = tid & 31;
    __shared__ int wcnt[8], woff[8];
    int i = b * NN + tid;
    int valid;
    if (g_mwidth1) valid = (((const unsigned char*)m)[i] != 0);
    else           valid = (((const unsigned int*)m)[i] != 0u);
    unsigned bal = __ballot_sync(0xffffffffu, valid);
    int pre = __popc(bal & ((1u << l) - 1u));
    if (l == 31) wcnt[w] = __popc(bal);
    g_idx[i] = 0;   // prefill pads with a safe (valid) index
    __syncthreads();
    if (tid == 0) {
        int s = 0;
        for (int k = 0; k < 8; k++) { woff[k] = s; s += wcnt[k]; }
        g_nv[b] = s;
    }
    __syncthreads();
    if (valid) g_idx[b * NN + woff[w] + pre] = tid;
}

// ======================= weight contraction (scaled + split) ===============
__global__ void prep_w_kernel(const float* __restrict__ Wq1, const float* __restrict__ Wk1,
                              const float* __restrict__ Wq2, const float* __restrict__ Wk2) {
    int a = blockIdx.x;
    int c = threadIdx.x & 127, kc = threadIdx.x >> 7;
    __shared__ float red[512];
    const float* X = (blockIdx.y == 0) ? Wq1 : Wq2;
    const float* Y = (blockIdx.y == 0) ? Wk1 : Wk2;
    float acc = 0.f;
#pragma unroll 8
    for (int k = kc * 32; k < kc * 32 + 32; k++)
        acc = fmaf(X[k * DD + c], Y[k * DD + a], acc);
    red[kc * 128 + c] = acc;
    __syncthreads();
    if (kc == 0) {
        float v = (red[c] + red[128 + c]) + (red[256 + c] + red[384 + c]);
        v *= SCALE;
        __half h = __float2half(v);
        __half lo = __float2half(v - __half2float(h));
        int idx = a * DD + c;
        if (blockIdx.y == 0) { g_W1h[idx] = h; g_W1l[idx] = lo; }
        else                 { g_W2h[idx] = h; g_W2l[idx] = lo; }
    }
}

// ======================= fused: M split + T GEMM + gate + sat_out ==========
// Persistent: 296 CTAs (2/SM) stage W1 ONCE, then stride over 2048 64-row
// tiles.  T in registers; alpha = rowdot(S,T); emits sat_out fp32 + split,
// and M split as a side product.
#define GT_A    0
#define GT_WH   17408
#define GT_WL   52224
#define GT_SMEM 87040

__global__ __launch_bounds__(256, 2)
void gemm_T_fused(const float* __restrict__ M, const float* __restrict__ S,
                  float* __restrict__ SO) {
    extern __shared__ char smem[];
    __shared__ float s_red[128];
    uint32_t sbase = smem_u32(smem);
    int tid = threadIdx.x;
    int w = tid >> 5, l = tid & 31;

    // stage W1 split ONCE
    for (int idx = tid; idx < 2048; idx += 256) {
        int row = idx >> 4, c8 = idx & 15;
        *(uint4*)(smem + GT_WH + row * 272 + c8 * 16) =
            *(const uint4*)(g_W1h + row * DD + c8 * 8);
        *(uint4*)(smem + GT_WL + row * 272 + c8 * 16) =
            *(const uint4*)(g_W1l + row * DD + c8 * 8);
    }

    int mw = w & 3, nwp = w >> 2;
    int r0 = mw * 16, c0 = nwp * 64;
    int g = l >> 2, t = l & 3;
    uint32_t halfOff = (uint32_t)((l >> 4) << 3);

    for (int item = blockIdx.x; item < 2048; item += gridDim.x) {
        size_t n0 = (size_t)item * 64;

        // convert M rows: fp32 -> split fp16 (global) + Mh smem tile
        for (int idx = tid; idx < 4096; idx += 256) {
            int row = idx >> 6, c2 = idx & 63;
            float2 v = ((const float2*)(M + (n0 + row) * DD))[c2];
            uint32_t h, lo;
            split_pack(v.x, v.y, h, lo);
            ((uint32_t*)(g_Mh + (n0 + row) * DD))[c2] = h;
            ((uint32_t*)(g_Ml + (n0 + row) * DD))[c2] = lo;
            *(uint32_t*)(smem + GT_A + row * 272 + c2 * 4) = h;
        }
        __syncthreads();

        float acc[8][4];
#pragma unroll
        for (int j = 0; j < 8; j++)
#pragma unroll
            for (int q = 0; q < 4; q++) acc[j][q] = 0.f;

#pragma unroll 1
        for (int ks = 0; ks < 8; ks++) {
            int k0 = 16 * ks;
            uint32_t aH[4];
            LDSM_X4(aH, sbase + GT_A + (r0 + (l & 15)) * 272 + (k0 + halfOff) * 2);
#pragma unroll
            for (int np = 0; np < 4; np++) {
                uint32_t baddr = sbase + GT_WH + (uint32_t)(k0 + (l & 15)) * 272 +
                                 (uint32_t)(c0 + 16 * np + halfOff) * 2;
                uint32_t bH[4], bL[4];
                LDSM_X4T(bH, baddr);
                LDSM_X4T(bL, baddr + (GT_WL - GT_WH));
                mma_fp16(acc[2 * np],     aH, bH[0], bH[1]);
                mma_fp16(acc[2 * np],     aH, bL[0], bL[1]);
                mma_fp16(acc[2 * np + 1], aH, bH[2], bH[3]);
                mma_fp16(acc[2 * np + 1], aH, bL[2], bL[3]);
            }
        }

        // --- epilogue: alpha = rowdot(S, T), then sat_out + split ---
        int rowA = r0 + g, rowB = rowA + 8;
        float p0 = 0.f, p1 = 0.f;
        {
            size_t rA = n0 + rowA, rB = n0 + rowB;
#pragma unroll
            for (int nt = 0; nt < 8; nt++) {
                int col = c0 + nt * 8 + 2 * t;
                float2 sa = *(const float2*)(S + rA * DD + col);
                float2 sb = *(const float2*)(S + rB * DD + col);
                p0 += sa.x * acc[nt][0] + sa.y * acc[nt][1];
                p1 += sb.x * acc[nt][2] + sb.y * acc[nt][3];
            }
        }
        p0 += __shfl_xor_sync(0xffffffffu, p0, 1);
        p0 += __shfl_xor_sync(0xffffffffu, p0, 2);
        p1 += __shfl_xor_sync(0xffffffffu, p1, 1);
        p1 += __shfl_xor_sync(0xffffffffu, p1, 2);
        if (t == 0) {
            s_red[nwp * 64 + rowA] = p0;
            s_red[nwp * 64 + rowB] = p1;
        }
        __syncthreads();

        float alA = s_red[rowA] + s_red[64 + rowA];
        float alB = s_red[rowB] + s_red[64 + rowB];
        size_t rA = n0 + rowA, rB = n0 + rowB;
#pragma unroll
        for (int nt = 0; nt < 8; nt++) {
            int col = c0 + nt * 8 + 2 * t;
            float2 sa = *(const float2*)(S + rA * DD + col);
            float2 ma = *(const float2*)(M + rA * DD + col);
            float2 oa;
            oa.x = fmaf(alA, ma.x - sa.x, sa.x);
            oa.y = fmaf(alA, ma.y - sa.y, sa.y);
            *(float2*)(SO + rA * DD + col) = oa;
            uint32_t h, lo;
            split_pack(oa.x, oa.y, h, lo);
            *(uint32_t*)(g_Sh + rA * DD + col) = h;
            *(uint32_t*)(g_Sl + rA * DD + col) = lo;

            float2 sb = *(const float2*)(S + rB * DD + col);
            float2 mb = *(const float2*)(M + rB * DD + col);
            float2 ob;
            ob.x = fmaf(alB, mb.x - sb.x, sb.x);
            ob.y = fmaf(alB, mb.y - sb.y, sb.y);
            *(float2*)(SO + rB * DD + col) = ob;
            split_pack(ob.x, ob.y, h, lo);
            *(uint32_t*)(g_Sh + rB * DD + col) = h;
            *(uint32_t*)(g_Sl + rB * DD + col) = lo;
        }
        __syncthreads();   // iter-n reads done before iter-n+1 staging
    }
}

// ======================= K2C GEMM (3-term, gathered, compact out) ==========
// Persistent: 296 CTAs stage W2 ONCE, then stride over (b, 64-row-quadrant)
// work items with uniform early skip of all-padding tiles.
#define GK_AH   0
#define GK_AL   17408
#define GK_WH   34816
#define GK_WL   69632
#define GK_SMEM 104448

__global__ __launch_bounds__(256, 2)
void gemm_K2C_kernel() {
    extern __shared__ char smem[];
    uint32_t sbase = smem_u32(smem);
    int tid = threadIdx.x;
    int w = tid >> 5, l = tid & 31;

    // stage W2 split ONCE
    for (int idx = tid; idx < 2048; idx += 256) {
        int row = idx >> 4, c8 = idx & 15;
        *(uint4*)(smem + GK_WH + row * 272 + c8 * 16) = *(const uint4*)(g_W2h + row * DD + c8 * 8);
        *(uint4*)(smem + GK_WL + row * 272 + c8 * 16) = *(const uint4*)(g_W2l + row * DD + c8 * 8);
    }
    __syncthreads();

    int mw = w & 3, nwp = w >> 2;
    int r0 = mw * 16, c0 = nwp * 64;
    int g = l >> 2, t = l & 3;
    uint32_t halfOff = (uint32_t)((l >> 4) << 3);

    for (int item = blockIdx.x; item < BB * 4; item += gridDim.x) {
        int b = item >> 2;
        int pos0 = (item & 3) * 64;
        if (pos0 >= g_nv[b]) continue;   // uniform across block

        for (int idx = tid; idx < 1024; idx += 256) {
            int row = idx >> 4, c8 = idx & 15;
            int j = g_idx[b * NN + pos0 + row];
            size_t srow = ((size_t)b * NN + j) * DD;
            *(uint4*)(smem + GK_AH + row * 272 + c8 * 16) = *(const uint4*)(g_Sh + srow + c8 * 8);
            *(uint4*)(smem + GK_AL + row * 272 + c8 * 16) = *(const uint4*)(g_Sl + srow + c8 * 8);
        }
        __syncthreads();

        float acc[8][4];
#pragma unroll
        for (int j = 0; j < 8; j++)
#pragma unroll
            for (int q = 0; q < 4; q++) acc[j][q] = 0.f;

#pragma unroll 1
        for (int ks = 0; ks < 8; ks++) {
            int k0 = 16 * ks;
            uint32_t aH[4], aL[4];
            uint32_t aaddr = sbase + GK_AH + (r0 + (l & 15)) * 272 + (k0 + halfOff) * 2;
            LDSM_X4(aH, aaddr);
            LDSM_X4(aL, aaddr + (GK_AL - GK_AH));
#pragma unroll
            for (int np = 0; np < 4; np++) {
                uint32_t baddr = sbase + GK_WH + (uint32_t)(k0 + (l & 15)) * 272 +
                                 (uint32_t)(c0 + 16 * np + halfOff) * 2;
                uint32_t bH[4], bL[4];
                LDSM_X4T(bH, baddr);
                LDSM_X4T(bL, baddr + (GK_WL - GK_WH));
                mma_fp16(acc[2 * np],     aH, bH[0], bH[1]);
                mma_fp16(acc[2 * np],     aH, bL[0], bL[1]);
                mma_fp16(acc[2 * np],     aL, bH[0], bH[1]);
                mma_fp16(acc[2 * np + 1], aH, bH[2], bH[3]);
                mma_fp16(acc[2 * np + 1], aH, bL[2], bL[3]);
                mma_fp16(acc[2 * np + 1], aL, bH[2], bH[3]);
            }
        }

#pragma unroll
        for (int nt = 0; nt < 8; nt++) {
            size_t rowA = (size_t)b * NN + pos0 + r0 + g;
            size_t rowB = rowA + 8;
            int col = c0 + nt * 8 + 2 * t;
            uint32_t h, lo;
            split_pack(acc[nt][0], acc[nt][1], h, lo);
            *(uint32_t*)(g_Kh + rowA * DD + col) = h;
            *(uint32_t*)(g_Kl + rowA * DD + col) = lo;
            split_pack(acc[nt][2], acc[nt][3], h, lo);
            *(uint32_t*)(g_Kh + rowB * DD + col) = h;
            *(uint32_t*)(g_Kl + rowB * DD + col) = lo;
        }
        __syncthreads();   // MMA reads done before next iter staging
    }
}

// ======================= fused attention (compacted keys) ==================
#define SM_QH  0
#define SM_QL  17408
#define SM_KH  34816
#define SM_KL  104448
#define SM_PH  0
#define SM_VH  34816
#define SM_VL  104448
#define SMEM_ATTN 174080

#define BETA_CHUNK(ACC, CBASE, NSTEPS) do {                                         \
    _Pragma("unroll")                                                               \
    for (int ks = 0; ks < 8; ks++) {                                                \
        int k0 = 16 * ks;                                                           \
        uint32_t aH[4], aL[4];                                                      \
        uint32_t aaddr = sbase + SM_QH + aRow * 272 + (k0 + halfOff) * 2;           \
        LDSM_X4(aH, aaddr);                                                         \
        LDSM_X4(aL, aaddr + (SM_QL - SM_QH));                                       \
        _Pragma("unroll")                                                           \
        for (int np = 0; np < 4; np++) {                                            \
            if (np >= (NSTEPS)) break;                                              \
            uint32_t baddr = sbase + SM_KH +                                        \
                (uint32_t)((CBASE) + nw * 64 + 16 * np + bRowBase) * 272 +          \
                (k0 + bColHalf) * 2;                                                \
            uint32_t bH[4], bL[4];                                                  \
            LDSM_X4(bH, baddr);                                                     \
            LDSM_X4(bL, baddr + (SM_KL - SM_KH));                                   \
            mma_fp16(ACC[2 * np],     aH, bH[0], bH[1]);                            \
            mma_fp16(ACC[2 * np],     aH, bL[0], bL[1]);                            \
            mma_fp16(ACC[2 * np],     aL, bH[0], bH[1]);                            \
            mma_fp16(ACC[2 * np + 1], aH, bH[2], bH[3]);                            \
            mma_fp16(ACC[2 * np + 1], aH, bL[2], bL[3]);                            \
            mma_fp16(ACC[2 * np + 1], aL, bH[2], bH[3]);                            \
        }                                                                           \
    }                                                                               \
} while (0)

__global__ __launch_bounds__(256, 1)
void attn_kernel(float* __restrict__ O) {
    extern __shared__ char smem[];
    __shared__ float s_bias[256];
    __shared__ float s_red[256];
    __shared__ int s_idx[256];
    uint32_t sbase = smem_u32(smem);

    int tid = threadIdx.x;
    int w = tid >> 5, l = tid & 31;
    int g = l >> 2, t = l & 3;
    int mw = w & 3, nw = w >> 2;
    int b = blockIdx.y;
    int i0 = blockIdx.x * 64;
    size_t boff = (size_t)b * NN * DD;

    int nv = g_nv[b];
    int kpadN = (nv + 15) & ~15;

    s_idx[tid] = g_idx[b * NN + tid];
    s_bias[tid] = (tid < nv) ? 0.f : -1e30f;

    // stage Q (64 rows of M split)
    for (int idx = tid; idx < 64 * 16; idx += 256) {
        int row = idx >> 4, c8 = idx & 15;
        size_t src = boff + (size_t)(i0 + row) * DD + c8 * 8;
        *(uint4*)(smem + SM_QH + row * 272 + c8 * 16) = *(const uint4*)(g_Mh + src);
        *(uint4*)(smem + SM_QL + row * 272 + c8 * 16) = *(const uint4*)(g_Ml + src);
    }
    // stage K compact rows [0, kpadN) (zero pads)
    {
        uint4 z = make_uint4(0, 0, 0, 0);
        for (int idx = tid; idx < kpadN * 16; idx += 256) {
            int row = idx >> 4, c8 = idx & 15;
            uint4 vh = z, vl = z;
            if (row < nv) {
                size_t src = boff + (size_t)row * DD + c8 * 8;
                vh = *(const uint4*)(g_Kh + src);
                vl = *(const uint4*)(g_Kl + src);
            }
            *(uint4*)(smem + SM_KH + row * 272 + c8 * 16) = vh;
            *(uint4*)(smem + SM_KL + row * 272 + c8 * 16) = vl;
        }
    }
    __syncthreads();

    // --- beta GEMM over valid 16-col tiles only ---
    uint32_t aRow = (uint32_t)(16 * mw + (l & 15));
    uint32_t halfOff = (uint32_t)((l >> 4) << 3);
    uint32_t bRowBase = (uint32_t)(((l >> 4) << 3) + (l & 7));
    uint32_t bColHalf = (uint32_t)(((l >> 3) & 1) << 3);

    int base0 = nw * 64, base1 = 128 + nw * 64;
    int ns0 = min(4, max(0, (kpadN - base0) >> 4));
    int ns1 = min(4, max(0, (kpadN - base1) >> 4));

    float acc0[8][4], acc1[8][4];
#pragma unroll
    for (int j = 0; j < 8; j++)
#pragma unroll
        for (int q = 0; q < 4; q++) { acc0[j][q] = 0.f; acc1[j][q] = 0.f; }

    if (ns0 > 0) BETA_CHUNK(acc0, 0, ns0);
    if (ns1 > 0) BETA_CHUNK(acc1, 128, ns1);

    // --- masked softmax (rows rowA, rowB) ---
    int rowA = 16 * mw + g, rowB = rowA + 8;
    float mx0 = -3.0e38f, mx1 = -3.0e38f;
#pragma unroll
    for (int j = 0; j < 8; j++) {
        float2 bv = *(const float2*)&s_bias[nw * 64 + j * 8 + 2 * t];
        acc0[j][0] += bv.x; acc0[j][1] += bv.y;
        acc0[j][2] += bv.x; acc0[j][3] += bv.y;
        mx0 = fmaxf(mx0, fmaxf(acc0[j][0], acc0[j][1]));
        mx1 = fmaxf(mx1, fmaxf(acc0[j][2], acc0[j][3]));
    }
    if (kpadN > 128) {
#pragma unroll
        for (int j = 0; j < 8; j++) {
            float2 bv = *(const float2*)&s_bias[128 + nw * 64 + j * 8 + 2 * t];
            acc1[j][0] += bv.x; acc1[j][1] += bv.y;
            acc1[j][2] += bv.x; acc1[j][3] += bv.y;
            mx0 = fmaxf(mx0, fmaxf(acc1[j][0], acc1[j][1]));
            mx1 = fmaxf(mx1, fmaxf(acc1[j][2], acc1[j][3]));
        }
    }
    mx0 = fmaxf(mx0, __shfl_xor_sync(0xffffffffu, mx0, 1));
    mx0 = fmaxf(mx0, __shfl_xor_sync(0xffffffffu, mx0, 2));
    mx1 = fmaxf(mx1, __shfl_xor_sync(0xffffffffu, mx1, 1));
    mx1 = fmaxf(mx1, __shfl_xor_sync(0xffffffffu, mx1, 2));
    if (t == 0) {
        s_red[nw * 64 + rowA] = mx0;
        s_red[nw * 64 + rowB] = mx1;
    }
    __syncthreads();
    float M0 = fmaxf(s_red[rowA], s_red[64 + rowA]);
    float M1 = fmaxf(s_red[rowB], s_red[64 + rowB]);
    float s0 = 0.f, s1 = 0.f;
#pragma unroll
    for (int j = 0; j < 8; j++) {
        acc0[j][0] = __expf(acc0[j][0] - M0); s0 += acc0[j][0];
        acc0[j][1] = __expf(acc0[j][1] - M0); s0 += acc0[j][1];
        acc0[j][2] = __expf(acc0[j][2] - M1); s1 += acc0[j][2];
        acc0[j][3] = __expf(acc0[j][3] - M1); s1 += acc0[j][3];
    }
    if (kpadN > 128) {
#pragma unroll
        for (int j = 0; j < 8; j++) {
            acc1[j][0] = __expf(acc1[j][0] - M0); s0 += acc1[j][0];
            acc1[j][1] = __expf(acc1[j][1] - M0); s0 += acc1[j][1];
            acc1[j][2] = __expf(acc1[j][2] - M1); s1 += acc1[j][2];
            acc1[j][3] = __expf(acc1[j][3] - M1); s1 += acc1[j][3];
        }
    }
    s0 += __shfl_xor_sync(0xffffffffu, s0, 1);
    s0 += __shfl_xor_sync(0xffffffffu, s0, 2);
    s1 += __shfl_xor_sync(0xffffffffu, s1, 1);
    s1 += __shfl_xor_sync(0xffffffffu, s1, 2);
    __syncthreads();
    if (t == 0) {
        s_red[128 + nw * 64 + rowA] = s0;
        s_red[128 + nw * 64 + rowB] = s1;
    }
    __syncthreads();
    float inv0 = __fdividef(1.f, s_red[128 + rowA] + s_red[128 + 64 + rowA]);
    float inv1 = __fdividef(1.f, s_red[128 + rowB] + s_red[128 + 64 + rowB]);

    // --- write P (fp16 hi only) over retired Q region ---
    {
        char* ph = smem + SM_PH;
#pragma unroll
        for (int j = 0; j < 8; j++) {
            int col = nw * 64 + j * 8 + 2 * t;
            __half2 a; a.x = __float2half(acc0[j][0] * inv0); a.y = __float2half(acc0[j][1] * inv0);
            *(uint32_t*)(ph + rowA * 528 + col * 2) = *(uint32_t*)&a;
            __half2 c; c.x = __float2half(acc0[j][2] * inv1); c.y = __float2half(acc0[j][3] * inv1);
            *(uint32_t*)(ph + rowB * 528 + col * 2) = *(uint32_t*)&c;
        }
        if (kpadN > 128) {
#pragma unroll
            for (int j = 0; j < 8; j++) {
                int col = 128 + nw * 64 + j * 8 + 2 * t;
                __half2 a; a.x = __float2half(acc1[j][0] * inv0); a.y = __float2half(acc1[j][1] * inv0);
                *(uint32_t*)(ph + rowA * 528 + col * 2) = *(uint32_t*)&a;
                __half2 c; c.x = __float2half(acc1[j][2] * inv1); c.y = __float2half(acc1[j][3] * inv1);
                *(uint32_t*)(ph + rowB * 528 + col * 2) = *(uint32_t*)&c;
            }
        }
    }
    // --- stage V gathered (overlays retired K) ---
    {
        uint4 z = make_uint4(0, 0, 0, 0);
        for (int idx = tid; idx < kpadN * 16; idx += 256) {
            int row = idx >> 4, c8 = idx & 15;
            uint4 vh = z, vl = z;
            if (row < nv) {
                size_t src = boff + (size_t)s_idx[row] * DD + c8 * 8;
                vh = *(const uint4*)(g_Mh + src);
                vl = *(const uint4*)(g_Ml + src);
            }
            *(uint4*)(smem + SM_VH + row * 272 + c8 * 16) = vh;
            *(uint4*)(smem + SM_VL + row * 272 + c8 * 16) = vl;
        }
    }
    __syncthreads();

    // --- PV GEMM: 2-term (P hi * (Vh + Vl)), k up to kpadN ---
    int d0 = 64 * nw;
    float o[8][4];
#pragma unroll
    for (int i = 0; i < 8; i++)
#pragma unroll
        for (int j = 0; j < 4; j++) o[i][j] = 0.f;

    int ksteps = kpadN >> 4;
#pragma unroll 1
    for (int ks = 0; ks < ksteps; ks++) {
        int k0 = 16 * ks;
        uint32_t aH[4];
        LDSM_X4(aH, sbase + SM_PH + aRow * 528 + (k0 + halfOff) * 2);
#pragma unroll
        for (int np = 0; np < 4; np++) {
            uint32_t baddr = sbase + SM_VH + (uint32_t)(k0 + (l & 15)) * 272 +
                             (uint32_t)(d0 + 16 * np + halfOff) * 2;
            uint32_t bH[4], bL[4];
            LDSM_X4T(bH, baddr);
            LDSM_X4T(bL, baddr + (SM_VL - SM_VH));
            mma_fp16(o[2 * np],     aH, bH[0], bH[1]);
            mma_fp16(o[2 * np],     aH, bL[0], bL[1]);
            mma_fp16(o[2 * np + 1], aH, bH[2], bH[3]);
            mma_fp16(o[2 * np + 1], aH, bL[2], bL[3]);
        }
    }

    float* Ob = O + ((size_t)b * NN + i0) * DD;
#pragma unroll
    for (int nt = 0; nt < 8; nt++) {
        int col = d0 + 8 * nt + 2 * t;
        *(float2*)&Ob[(size_t)rowA * DD + col] = make_float2(o[nt][0], o[nt][1]);
        *(float2*)&Ob[(size_t)rowB * DD + col] = make_float2(o[nt][2], o[nt][3]);
    }
}

// ---------------------------------------------------------------------------
extern "C" void kernel_launch(void* const* d_in, const int* in_sizes, int n_in,
                              void* d_out, int out_size) {
    (void)in_sizes; (void)n_in; (void)out_size;
    const float* mirror    = (const float*)d_in[0];
    const float* satellite = (const float*)d_in[1];
    const void*  mask      = d_in[2];
    const float* Wq1 = (const float*)d_in[3];
    const float* Wk1 = (const float*)d_in[4];
    const float* Wq2 = (const float*)d_in[5];
    const float* Wk2 = (const float*)d_in[6];
    float* sat_out = (float*)d_out;
    float* mir_out = (float*)d_out + BND;

    cudaFuncSetAttribute(gemm_T_fused,    cudaFuncAttributeMaxDynamicSharedMemorySize, GT_SMEM);
    cudaFuncSetAttribute(gemm_K2C_kernel, cudaFuncAttributeMaxDynamicSharedMemorySize, GK_SMEM);
    cudaFuncSetAttribute(attn_kernel,     cudaFuncAttributeMaxDynamicSharedMemorySize, SMEM_ATTN);

    detect_mask_kernel<<<1, 256>>>((const unsigned int*)mask);
    decode_compact_kernel<<<BB, 256>>>(mask);
    prep_w_kernel<<<dim3(128, 2), 512>>>(Wq1, Wk1, Wq2, Wk2);

    gemm_T_fused<<<296, 256, GT_SMEM>>>(mirror, satellite, sat_out);
    gemm_K2C_kernel<<<296, 256, GK_SMEM>>>();
    attn_kernel<<<dim3(NN / 64, BB), 256, SMEM_ATTN>>>(mir_out);
}

// round 10
// speedup vs baseline: 1.3227x; 1.2172x over previous
#include <cuda_runtime.h>
#include <cuda_fp16.h>
#include <cstdint>

// Problem constants
#define BB 512
#define NN 256
#define DD 128
#define BND ((size_t)BB * NN * DD)

static __device__ __half g_W1h[DD * DD], g_W1l[DD * DD];
static __device__ __half g_W2h[DD * DD], g_W2l[DD * DD];
static __device__ __half g_Mh[BND], g_Ml[BND];       // mirror split
static __device__ __half g_Sh[BND], g_Sl[BND];       // sat_out split
static __device__ __half g_Kh[BND], g_Kl[BND];       // K2C split (COMPACT rows)
static __device__ int g_idx[BB * NN];                // compact pos -> j
static __device__ int g_nv[BB];                      // valid count per batch
static __device__ int g_mwidth1;

#define SCALE 0.08838834764831845f  // 1/sqrt(128)

// ============================ PTX helpers ==================================
__device__ __forceinline__ uint32_t smem_u32(const void* p) {
    uint32_t a;
    asm("{ .reg .u64 t; cvta.to.shared.u64 t, %1; cvt.u32.u64 %0, t; }" : "=r"(a) : "l"(p));
    return a;
}

#define LDSM_X4(r, a) \
    asm volatile("ldmatrix.sync.aligned.m8n8.x4.shared.b16 {%0,%1,%2,%3}, [%4];" \
        : "=r"((r)[0]), "=r"((r)[1]), "=r"((r)[2]), "=r"((r)[3]) : "r"(a))
#define LDSM_X4T(r, a) \
    asm volatile("ldmatrix.sync.aligned.m8n8.x4.trans.shared.b16 {%0,%1,%2,%3}, [%4];" \
        : "=r"((r)[0]), "=r"((r)[1]), "=r"((r)[2]), "=r"((r)[3]) : "r"(a))

__device__ __forceinline__ void mma_fp16(float* c, const uint32_t* a, uint32_t b0, uint32_t b1) {
    asm volatile(
        "mma.sync.aligned.m16n8k16.row.col.f32.f16.f16.f32 "
        "{%0,%1,%2,%3}, {%4,%5,%6,%7}, {%8,%9}, {%0,%1,%2,%3};"
        : "+f"(c[0]), "+f"(c[1]), "+f"(c[2]), "+f"(c[3])
        : "r"(a[0]), "r"(a[1]), "r"(a[2]), "r"(a[3]), "r"(b0), "r"(b1));
}

__device__ __forceinline__ void split_pack(float x, float y, uint32_t& h, uint32_t& l) {
    __half hx = __float2half(x);
    __half hy = __float2half(y);
    __half lx = __float2half(x - __half2float(hx));
    __half ly = __float2half(y - __half2float(hy));
    __half2 hh; hh.x = hx; hh.y = hy;
    __half2 ll; ll.x = lx; ll.y = ly;
    h = *(uint32_t*)&hh;
    l = *(uint32_t*)&ll;
}

// ======================= mask canonicalization + compaction ================
__global__ void detect_mask_kernel(const unsigned int* __restrict__ m) {
    __shared__ int red[256];
    int tid = threadIdx.x;
    int p = 0;
    for (int i = tid; i < (BB * NN) / 4; i += 256) {
        unsigned int w = m[i];
        if (w != 0u && w != 1u && w != 0x3F800000u) p = 1;
    }
    red[tid] = p;
    __syncthreads();
    for (int s = 128; s > 0; s >>= 1) {
        if (tid < s) red[tid] |= red[tid + s];
        __syncthreads();
    }
    if (tid == 0) g_mwidth1 = red[0];
}

__global__ void decode_compact_kernel(const void* __restrict__ m) {
    int b = blockIdx.x;
    int tid = threadIdx.x;
    int w = tid >> 5, l = tid & 31;
    __shared__ int wcnt[8], woff[8];
    int i = b * NN + tid;
    int valid;
    if (g_mwidth1) valid = (((const unsigned char*)m)[i] != 0);
    else           valid = (((const unsigned int*)m)[i] != 0u);
    unsigned bal = __ballot_sync(0xffffffffu, valid);
    int pre = __popc(bal & ((1u << l) - 1u));
    if (l == 31) wcnt[w] = __popc(bal);
    g_idx[i] = 0;   // prefill pads with a safe (valid) index
    __syncthreads();
    if (tid == 0) {
        int s = 0;
        for (int k = 0; k < 8; k++) { woff[k] = s; s += wcnt[k]; }
        g_nv[b] = s;
    }
    __syncthreads();
    if (valid) g_idx[b * NN + woff[w] + pre] = tid;
}

// ======================= weight contraction (scaled + split) ===============
__global__ void prep_w_kernel(const float* __restrict__ Wq1, const float* __restrict__ Wk1,
                              const float* __restrict__ Wq2, const float* __restrict__ Wk2) {
    int a = blockIdx.x;
    int c = threadIdx.x & 127, kc = threadIdx.x >> 7;
    __shared__ float red[512];
    const float* X = (blockIdx.y == 0) ? Wq1 : Wq2;
    const float* Y = (blockIdx.y == 0) ? Wk1 : Wk2;
    float acc = 0.f;
#pragma unroll 8
    for (int k = kc * 32; k < kc * 32 + 32; k++)
        acc = fmaf(X[k * DD + c], Y[k * DD + a], acc);
    red[kc * 128 + c] = acc;
    __syncthreads();
    if (kc == 0) {
        float v = (red[c] + red[128 + c]) + (red[256 + c] + red[384 + c]);
        v *= SCALE;
        __half h = __float2half(v);
        __half lo = __float2half(v - __half2float(h));
        int idx = a * DD + c;
        if (blockIdx.y == 0) { g_W1h[idx] = h; g_W1l[idx] = lo; }
        else                 { g_W2h[idx] = h; g_W2l[idx] = lo; }
    }
}

// ======================= fused: M split + T GEMM + gate + sat_out ==========
// Persistent: 296 CTAs (2/SM) stage W1 ONCE, then stride over 2048 64-row
// tiles.  T in registers; alpha = rowdot(S,T); emits sat_out fp32 + split,
// and M split as a side product.
#define GT_A    0
#define GT_WH   17408
#define GT_WL   52224
#define GT_SMEM 87040

__global__ __launch_bounds__(256, 2)
void gemm_T_fused(const float* __restrict__ M, const float* __restrict__ S,
                  float* __restrict__ SO) {
    extern __shared__ char smem[];
    __shared__ float s_red[128];
    uint32_t sbase = smem_u32(smem);
    int tid = threadIdx.x;
    int w = tid >> 5, l = tid & 31;

    // stage W1 split ONCE
    for (int idx = tid; idx < 2048; idx += 256) {
        int row = idx >> 4, c8 = idx & 15;
        *(uint4*)(smem + GT_WH + row * 272 + c8 * 16) =
            *(const uint4*)(g_W1h + row * DD + c8 * 8);
        *(uint4*)(smem + GT_WL + row * 272 + c8 * 16) =
            *(const uint4*)(g_W1l + row * DD + c8 * 8);
    }

    int mw = w & 3, nwp = w >> 2;
    int r0 = mw * 16, c0 = nwp * 64;
    int g = l >> 2, t = l & 3;
    uint32_t halfOff = (uint32_t)((l >> 4) << 3);

    for (int item = blockIdx.x; item < 2048; item += gridDim.x) {
        size_t n0 = (size_t)item * 64;

        // convert M rows: fp32 -> split fp16 (global) + Mh smem tile
        for (int idx = tid; idx < 4096; idx += 256) {
            int row = idx >> 6, c2 = idx & 63;
            float2 v = ((const float2*)(M + (n0 + row) * DD))[c2];
            uint32_t h, lo;
            split_pack(v.x, v.y, h, lo);
            ((uint32_t*)(g_Mh + (n0 + row) * DD))[c2] = h;
            ((uint32_t*)(g_Ml + (n0 + row) * DD))[c2] = lo;
            *(uint32_t*)(smem + GT_A + row * 272 + c2 * 4) = h;
        }
        __syncthreads();

        float acc[8][4];
#pragma unroll
        for (int j = 0; j < 8; j++)
#pragma unroll
            for (int q = 0; q < 4; q++) acc[j][q] = 0.f;

#pragma unroll 1
        for (int ks = 0; ks < 8; ks++) {
            int k0 = 16 * ks;
            uint32_t aH[4];
            LDSM_X4(aH, sbase + GT_A + (r0 + (l & 15)) * 272 + (k0 + halfOff) * 2);
#pragma unroll
            for (int np = 0; np < 4; np++) {
                uint32_t baddr = sbase + GT_WH + (uint32_t)(k0 + (l & 15)) * 272 +
                                 (uint32_t)(c0 + 16 * np + halfOff) * 2;
                uint32_t bH[4], bL[4];
                LDSM_X4T(bH, baddr);
                LDSM_X4T(bL, baddr + (GT_WL - GT_WH));
                mma_fp16(acc[2 * np],     aH, bH[0], bH[1]);
                mma_fp16(acc[2 * np],     aH, bL[0], bL[1]);
                mma_fp16(acc[2 * np + 1], aH, bH[2], bH[3]);
                mma_fp16(acc[2 * np + 1], aH, bL[2], bL[3]);
            }
        }

        // --- epilogue: alpha = rowdot(S, T), then sat_out + split ---
        int rowA = r0 + g, rowB = rowA + 8;
        float p0 = 0.f, p1 = 0.f;
        {
            size_t rA = n0 + rowA, rB = n0 + rowB;
#pragma unroll
            for (int nt = 0; nt < 8; nt++) {
                int col = c0 + nt * 8 + 2 * t;
                float2 sa = *(const float2*)(S + rA * DD + col);
                float2 sb = *(const float2*)(S + rB * DD + col);
                p0 += sa.x * acc[nt][0] + sa.y * acc[nt][1];
                p1 += sb.x * acc[nt][2] + sb.y * acc[nt][3];
            }
        }
        p0 += __shfl_xor_sync(0xffffffffu, p0, 1);
        p0 += __shfl_xor_sync(0xffffffffu, p0, 2);
        p1 += __shfl_xor_sync(0xffffffffu, p1, 1);
        p1 += __shfl_xor_sync(0xffffffffu, p1, 2);
        if (t == 0) {
            s_red[nwp * 64 + rowA] = p0;
            s_red[nwp * 64 + rowB] = p1;
        }
        __syncthreads();

        float alA = s_red[rowA] + s_red[64 + rowA];
        float alB = s_red[rowB] + s_red[64 + rowB];
        size_t rA = n0 + rowA, rB = n0 + rowB;
#pragma unroll
        for (int nt = 0; nt < 8; nt++) {
            int col = c0 + nt * 8 + 2 * t;
            float2 sa = *(const float2*)(S + rA * DD + col);
            float2 ma = *(const float2*)(M + rA * DD + col);
            float2 oa;
            oa.x = fmaf(alA, ma.x - sa.x, sa.x);
            oa.y = fmaf(alA, ma.y - sa.y, sa.y);
            *(float2*)(SO + rA * DD + col) = oa;
            uint32_t h, lo;
            split_pack(oa.x, oa.y, h, lo);
            *(uint32_t*)(g_Sh + rA * DD + col) = h;
            *(uint32_t*)(g_Sl + rA * DD + col) = lo;

            float2 sb = *(const float2*)(S + rB * DD + col);
            float2 mb = *(const float2*)(M + rB * DD + col);
            float2 ob;
            ob.x = fmaf(alB, mb.x - sb.x, sb.x);
            ob.y = fmaf(alB, mb.y - sb.y, sb.y);
            *(float2*)(SO + rB * DD + col) = ob;
            split_pack(ob.x, ob.y, h, lo);
            *(uint32_t*)(g_Sh + rB * DD + col) = h;
            *(uint32_t*)(g_Sl + rB * DD + col) = lo;
        }
        __syncthreads();   // iter-n reads done before iter-n+1 staging
    }
}

// ======================= K2C GEMM (3-term, gathered, compact out) ==========
// Persistent: 296 CTAs stage W2 ONCE, then stride over (b, 64-row-quadrant)
// work items with uniform early skip of all-padding tiles.
#define GK_AH   0
#define GK_AL   17408
#define GK_WH   34816
#define GK_WL   69632
#define GK_SMEM 104448

__global__ __launch_bounds__(256, 2)
void gemm_K2C_kernel() {
    extern __shared__ char smem[];
    uint32_t sbase = smem_u32(smem);
    int tid = threadIdx.x;
    int w = tid >> 5, l = tid & 31;

    // stage W2 split ONCE
    for (int idx = tid; idx < 2048; idx += 256) {
        int row = idx >> 4, c8 = idx & 15;
        *(uint4*)(smem + GK_WH + row * 272 + c8 * 16) = *(const uint4*)(g_W2h + row * DD + c8 * 8);
        *(uint4*)(smem + GK_WL + row * 272 + c8 * 16) = *(const uint4*)(g_W2l + row * DD + c8 * 8);
    }
    __syncthreads();

    int mw = w & 3, nwp = w >> 2;
    int r0 = mw * 16, c0 = nwp * 64;
    int g = l >> 2, t = l & 3;
    uint32_t halfOff = (uint32_t)((l >> 4) << 3);

    for (int item = blockIdx.x; item < BB * 4; item += gridDim.x) {
        int b = item >> 2;
        int pos0 = (item & 3) * 64;
        if (pos0 >= g_nv[b]) continue;   // uniform across block

        for (int idx = tid; idx < 1024; idx += 256) {
            int row = idx >> 4, c8 = idx & 15;
            int j = g_idx[b * NN + pos0 + row];
            size_t srow = ((size_t)b * NN + j) * DD;
            *(uint4*)(smem + GK_AH + row * 272 + c8 * 16) = *(const uint4*)(g_Sh + srow + c8 * 8);
            *(uint4*)(smem + GK_AL + row * 272 + c8 * 16) = *(const uint4*)(g_Sl + srow + c8 * 8);
        }
        __syncthreads();

        float acc[8][4];
#pragma unroll
        for (int j = 0; j < 8; j++)
#pragma unroll
            for (int q = 0; q < 4; q++) acc[j][q] = 0.f;

#pragma unroll 1
        for (int ks = 0; ks < 8; ks++) {
            int k0 = 16 * ks;
            uint32_t aH[4], aL[4];
            uint32_t aaddr = sbase + GK_AH + (r0 + (l & 15)) * 272 + (k0 + halfOff) * 2;
            LDSM_X4(aH, aaddr);
            LDSM_X4(aL, aaddr + (GK_AL - GK_AH));
#pragma unroll
            for (int np = 0; np < 4; np++) {
                uint32_t baddr = sbase + GK_WH + (uint32_t)(k0 + (l & 15)) * 272 +
                                 (uint32_t)(c0 + 16 * np + halfOff) * 2;
                uint32_t bH[4], bL[4];
                LDSM_X4T(bH, baddr);
                LDSM_X4T(bL, baddr + (GK_WL - GK_WH));
                mma_fp16(acc[2 * np],     aH, bH[0], bH[1]);
                mma_fp16(acc[2 * np],     aH, bL[0], bL[1]);
                mma_fp16(acc[2 * np],     aL, bH[0], bH[1]);
                mma_fp16(acc[2 * np + 1], aH, bH[2], bH[3]);
                mma_fp16(acc[2 * np + 1], aH, bL[2], bL[3]);
                mma_fp16(acc[2 * np + 1], aL, bH[2], bH[3]);
            }
        }

#pragma unroll
        for (int nt = 0; nt < 8; nt++) {
            size_t rowA = (size_t)b * NN + pos0 + r0 + g;
            size_t rowB = rowA + 8;
            int col = c0 + nt * 8 + 2 * t;
            uint32_t h, lo;
            split_pack(acc[nt][0], acc[nt][1], h, lo);
            *(uint32_t*)(g_Kh + rowA * DD + col) = h;
            *(uint32_t*)(g_Kl + rowA * DD + col) = lo;
            split_pack(acc[nt][2], acc[nt][3], h, lo);
            *(uint32_t*)(g_Kh + rowB * DD + col) = h;
            *(uint32_t*)(g_Kl + rowB * DD + col) = lo;
        }
        __syncthreads();   // MMA reads done before next iter staging
    }
}

// ======================= fused attention (compacted keys) ==================
// CTA = (batch b, 128 i-rows).  512 threads = 16 warps: 8 m-warps x 2 n-warps.
// smem: Q 128 rows h/l (34816 each), K 256 rows h/l (69632 each).
// P (528-stride, 128 rows = 67584) overlays Q; V overlays K.
#define SM_QH  0
#define SM_QL  34816
#define SM_KH  69632
#define SM_KL  139264
#define SM_PH  0
#define SM_VH  69632
#define SM_VL  139264
#define SMEM_ATTN 208896

#define BETA_CHUNK(ACC, CBASE, NSTEPS) do {                                         \
    _Pragma("unroll")                                                               \
    for (int ks = 0; ks < 8; ks++) {                                                \
        int k0 = 16 * ks;                                                           \
        uint32_t aH[4], aL[4];                                                      \
        uint32_t aaddr = sbase + SM_QH + aRow * 272 + (k0 + halfOff) * 2;           \
        LDSM_X4(aH, aaddr);                                                         \
        LDSM_X4(aL, aaddr + (SM_QL - SM_QH));                                       \
        _Pragma("unroll")                                                           \
        for (int np = 0; np < 4; np++) {                                            \
            if (np >= (NSTEPS)) break;                                              \
            uint32_t baddr = sbase + SM_KH +                                        \
                (uint32_t)((CBASE) + nw * 64 + 16 * np + bRowBase) * 272 +          \
                (k0 + bColHalf) * 2;                                                \
            uint32_t bH[4], bL[4];                                                  \
            LDSM_X4(bH, baddr);                                                     \
            LDSM_X4(bL, baddr + (SM_KL - SM_KH));                                   \
            mma_fp16(ACC[2 * np],     aH, bH[0], bH[1]);                            \
            mma_fp16(ACC[2 * np],     aH, bL[0], bL[1]);                            \
            mma_fp16(ACC[2 * np],     aL, bH[0], bH[1]);                            \
            mma_fp16(ACC[2 * np + 1], aH, bH[2], bH[3]);                            \
            mma_fp16(ACC[2 * np + 1], aH, bL[2], bL[3]);                            \
            mma_fp16(ACC[2 * np + 1], aL, bH[2], bH[3]);                            \
        }                                                                           \
    }                                                                               \
} while (0)

__global__ __launch_bounds__(512, 1)
void attn_kernel(float* __restrict__ O) {
    extern __shared__ char smem[];
    __shared__ float s_bias[256];
    __shared__ float s_red[512];
    __shared__ int s_idx[256];
    uint32_t sbase = smem_u32(smem);

    int tid = threadIdx.x;
    int w = tid >> 5, l = tid & 31;
    int g = l >> 2, t = l & 3;
    int mw = w & 7, nw = w >> 3;
    int b = blockIdx.y;
    int i0 = blockIdx.x * 128;
    size_t boff = (size_t)b * NN * DD;

    int nv = g_nv[b];
    int kpadN = (nv + 15) & ~15;

    if (tid < 256) {
        s_idx[tid] = g_idx[b * NN + tid];
        s_bias[tid] = (tid < nv) ? 0.f : -1e30f;
    }

    // stage Q (128 rows of M split)
    for (int idx = tid; idx < 128 * 16; idx += 512) {
        int row = idx >> 4, c8 = idx & 15;
        size_t src = boff + (size_t)(i0 + row) * DD + c8 * 8;
        *(uint4*)(smem + SM_QH + row * 272 + c8 * 16) = *(const uint4*)(g_Mh + src);
        *(uint4*)(smem + SM_QL + row * 272 + c8 * 16) = *(const uint4*)(g_Ml + src);
    }
    // stage K compact rows [0, kpadN) (zero pads)
    {
        uint4 z = make_uint4(0, 0, 0, 0);
        for (int idx = tid; idx < kpadN * 16; idx += 512) {
            int row = idx >> 4, c8 = idx & 15;
            uint4 vh = z, vl = z;
            if (row < nv) {
                size_t src = boff + (size_t)row * DD + c8 * 8;
                vh = *(const uint4*)(g_Kh + src);
                vl = *(const uint4*)(g_Kl + src);
            }
            *(uint4*)(smem + SM_KH + row * 272 + c8 * 16) = vh;
            *(uint4*)(smem + SM_KL + row * 272 + c8 * 16) = vl;
        }
    }
    __syncthreads();

    // --- beta GEMM over valid 16-col tiles only ---
    uint32_t aRow = (uint32_t)(16 * mw + (l & 15));
    uint32_t halfOff = (uint32_t)((l >> 4) << 3);
    uint32_t bRowBase = (uint32_t)(((l >> 4) << 3) + (l & 7));
    uint32_t bColHalf = (uint32_t)(((l >> 3) & 1) << 3);

    int base0 = nw * 64, base1 = 128 + nw * 64;
    int ns0 = min(4, max(0, (kpadN - base0) >> 4));
    int ns1 = min(4, max(0, (kpadN - base1) >> 4));

    float acc0[8][4], acc1[8][4];
#pragma unroll
    for (int j = 0; j < 8; j++)
#pragma unroll
        for (int q = 0; q < 4; q++) { acc0[j][q] = 0.f; acc1[j][q] = 0.f; }

    if (ns0 > 0) BETA_CHUNK(acc0, 0, ns0);
    if (ns1 > 0) BETA_CHUNK(acc1, 128, ns1);

    // --- masked softmax (rows rowA, rowB in 0..127) ---
    int rowA = 16 * mw + g, rowB = rowA + 8;
    float mx0 = -3.0e38f, mx1 = -3.0e38f;
#pragma unroll
    for (int j = 0; j < 8; j++) {
        float2 bv = *(const float2*)&s_bias[nw * 64 + j * 8 + 2 * t];
        acc0[j][0] += bv.x; acc0[j][1] += bv.y;
        acc0[j][2] += bv.x; acc0[j][3] += bv.y;
        mx0 = fmaxf(mx0, fmaxf(acc0[j][0], acc0[j][1]));
        mx1 = fmaxf(mx1, fmaxf(acc0[j][2], acc0[j][3]));
    }
    if (kpadN > 128) {
#pragma unroll
        for (int j = 0; j < 8; j++) {
            float2 bv = *(const float2*)&s_bias[128 + nw * 64 + j * 8 + 2 * t];
            acc1[j][0] += bv.x; acc1[j][1] += bv.y;
            acc1[j][2] += bv.x; acc1[j][3] += bv.y;
            mx0 = fmaxf(mx0, fmaxf(acc1[j][0], acc1[j][1]));
            mx1 = fmaxf(mx1, fmaxf(acc1[j][2], acc1[j][3]));
        }
    }
    mx0 = fmaxf(mx0, __shfl_xor_sync(0xffffffffu, mx0, 1));
    mx0 = fmaxf(mx0, __shfl_xor_sync(0xffffffffu, mx0, 2));
    mx1 = fmaxf(mx1, __shfl_xor_sync(0xffffffffu, mx1, 1));
    mx1 = fmaxf(mx1, __shfl_xor_sync(0xffffffffu, mx1, 2));
    if (t == 0) {
        s_red[nw * 128 + rowA] = mx0;
        s_red[nw * 128 + rowB] = mx1;
    }
    __syncthreads();
    float M0 = fmaxf(s_red[rowA], s_red[128 + rowA]);
    float M1 = fmaxf(s_red[rowB], s_red[128 + rowB]);
    float s0 = 0.f, s1 = 0.f;
#pragma unroll
    for (int j = 0; j < 8; j++) {
        acc0[j][0] = __expf(acc0[j][0] - M0); s0 += acc0[j][0];
        acc0[j][1] = __expf(acc0[j][1] - M0); s0 += acc0[j][1];
        acc0[j][2] = __expf(acc0[j][2] - M1); s1 += acc0[j][2];
        acc0[j][3] = __expf(acc0[j][3] - M1); s1 += acc0[j][3];
    }
    if (kpadN > 128) {
#pragma unroll
        for (int j = 0; j < 8; j++) {
            acc1[j][0] = __expf(acc1[j][0] - M0); s0 += acc1[j][0];
            acc1[j][1] = __expf(acc1[j][1] - M0); s0 += acc1[j][1];
            acc1[j][2] = __expf(acc1[j][2] - M1); s1 += acc1[j][2];
            acc1[j][3] = __expf(acc1[j][3] - M1); s1 += acc1[j][3];
        }
    }
    s0 += __shfl_xor_sync(0xffffffffu, s0, 1);
    s0 += __shfl_xor_sync(0xffffffffu, s0, 2);
    s1 += __shfl_xor_sync(0xffffffffu, s1, 1);
    s1 += __shfl_xor_sync(0xffffffffu, s1, 2);
    __syncthreads();
    if (t == 0) {
        s_red[256 + nw * 128 + rowA] = s0;
        s_red[256 + nw * 128 + rowB] = s1;
    }
    __syncthreads();
    float inv0 = __fdividef(1.f, s_red[256 + rowA] + s_red[256 + 128 + rowA]);
    float inv1 = __fdividef(1.f, s_red[256 + rowB] + s_red[256 + 128 + rowB]);

    // --- write P (fp16 hi only) over retired Q region ---
    {
        char* ph = smem + SM_PH;
#pragma unroll
        for (int j = 0; j < 8; j++) {
            int col = nw * 64 + j * 8 + 2 * t;
            __half2 a; a.x = __float2half(acc0[j][0] * inv0); a.y = __float2half(acc0[j][1] * inv0);
            *(uint32_t*)(ph + rowA * 528 + col * 2) = *(uint32_t*)&a;
            __half2 c; c.x = __float2half(acc0[j][2] * inv1); c.y = __float2half(acc0[j][3] * inv1);
            *(uint32_t*)(ph + rowB * 528 + col * 2) = *(uint32_t*)&c;
        }
        if (kpadN > 128) {
#pragma unroll
            for (int j = 0; j < 8; j++) {
                int col = 128 + nw * 64 + j * 8 + 2 * t;
                __half2 a; a.x = __float2half(acc1[j][0] * inv0); a.y = __float2half(acc1[j][1] * inv0);
                *(uint32_t*)(ph + rowA * 528 + col * 2) = *(uint32_t*)&a;
                __half2 c; c.x = __float2half(acc1[j][2] * inv1); c.y = __float2half(acc1[j][3] * inv1);
                *(uint32_t*)(ph + rowB * 528 + col * 2) = *(uint32_t*)&c;
            }
        }
    }
    // --- stage V gathered (overlays retired K) ---
    {
        uint4 z = make_uint4(0, 0, 0, 0);
        for (int idx = tid; idx < kpadN * 16; idx += 512) {
            int row = idx >> 4, c8 = idx & 15;
            uint4 vh = z, vl = z;
            if (row < nv) {
                size_t src = boff + (size_t)s_idx[row] * DD + c8 * 8;
                vh = *(const uint4*)(g_Mh + src);
                vl = *(const uint4*)(g_Ml + src);
            }
            *(uint4*)(smem + SM_VH + row * 272 + c8 * 16) = vh;
            *(uint4*)(smem + SM_VL + row * 272 + c8 * 16) = vl;
        }
    }
    __syncthreads();

    // --- PV GEMM: 2-term (P hi * (Vh + Vl)), k up to kpadN ---
    int d0 = 64 * nw;
    float o[8][4];
#pragma unroll
    for (int i = 0; i < 8; i++)
#pragma unroll
        for (int j = 0; j < 4; j++) o[i][j] = 0.f;

    int ksteps = kpadN >> 4;
#pragma unroll 1
    for (int ks = 0; ks < ksteps; ks++) {
        int k0 = 16 * ks;
        uint32_t aH[4];
        LDSM_X4(aH, sbase + SM_PH + aRow * 528 + (k0 + halfOff) * 2);
#pragma unroll
        for (int np = 0; np < 4; np++) {
            uint32_t baddr = sbase + SM_VH + (uint32_t)(k0 + (l & 15)) * 272 +
                             (uint32_t)(d0 + 16 * np + halfOff) * 2;
            uint32_t bH[4], bL[4];
            LDSM_X4T(bH, baddr);
            LDSM_X4T(bL, baddr + (SM_VL - SM_VH));
            mma_fp16(o[2 * np],     aH, bH[0], bH[1]);
            mma_fp16(o[2 * np],     aH, bL[0], bL[1]);
            mma_fp16(o[2 * np + 1], aH, bH[2], bH[3]);
            mma_fp16(o[2 * np + 1], aH, bL[2], bL[3]);
        }
    }

    float* Ob = O + ((size_t)b * NN + i0) * DD;
#pragma unroll
    for (int nt = 0; nt < 8; nt++) {
        int col = d0 + 8 * nt + 2 * t;
        *(float2*)&Ob[(size_t)rowA * DD + col] = make_float2(o[nt][0], o[nt][1]);
        *(float2*)&Ob[(size_t)rowB * DD + col] = make_float2(o[nt][2], o[nt][3]);
    }
}

// ---------------------------------------------------------------------------
extern "C" void kernel_launch(void* const* d_in, const int* in_sizes, int n_in,
                              void* d_out, int out_size) {
    (void)in_sizes; (void)n_in; (void)out_size;
    const float* mirror    = (const float*)d_in[0];
    const float* satellite = (const float*)d_in[1];
    const void*  mask      = d_in[2];
    const float* Wq1 = (const float*)d_in[3];
    const float* Wk1 = (const float*)d_in[4];
    const float* Wq2 = (const float*)d_in[5];
    const float* Wk2 = (const float*)d_in[6];
    float* sat_out = (float*)d_out;
    float* mir_out = (float*)d_out + BND;

    cudaFuncSetAttribute(gemm_T_fused,    cudaFuncAttributeMaxDynamicSharedMemorySize, GT_SMEM);
    cudaFuncSetAttribute(gemm_K2C_kernel, cudaFuncAttributeMaxDynamicSharedMemorySize, GK_SMEM);
    cudaFuncSetAttribute(attn_kernel,     cudaFuncAttributeMaxDynamicSharedMemorySize, SMEM_ATTN);

    detect_mask_kernel<<<1, 256>>>((const unsigned int*)mask);
    decode_compact_kernel<<<BB, 256>>>(mask);
    prep_w_kernel<<<dim3(128, 2), 512>>>(Wq1, Wk1, Wq2, Wk2);

    gemm_T_fused<<<296, 256, GT_SMEM>>>(mirror, satellite, sat_out);
    gemm_K2C_kernel<<<296, 256, GK_SMEM>>>();
    attn_kernel<<<dim3(NN / 128, BB), 512, SMEM_ATTN>>>(mir_out);
}

// round 11
// speedup vs baseline: 1.3698x; 1.0356x over previous
#include <cuda_runtime.h>
#include <cuda_fp16.h>
#include <cstdint>

// Problem constants
#define BB 512
#define NN 256
#define DD 128
#define BND ((size_t)BB * NN * DD)

static __device__ __half g_W1h[DD * DD], g_W1l[DD * DD];
static __device__ __half g_W2h[DD * DD], g_W2l[DD * DD];
static __device__ __half g_Mh[BND], g_Ml[BND];       // mirror split
static __device__ __half g_Sh[BND], g_Sl[BND];       // sat_out split
static __device__ __half g_Kh[BND], g_Kl[BND];       // K2C split (COMPACT rows)
static __device__ int g_idx[BB * NN];                // compact pos -> j
static __device__ int g_nv[BB];                      // valid count per batch
static __device__ int g_mwidth1;

#define SCALE 0.08838834764831845f  // 1/sqrt(128)

// ============================ PTX helpers ==================================
__device__ __forceinline__ uint32_t smem_u32(const void* p) {
    uint32_t a;
    asm("{ .reg .u64 t; cvta.to.shared.u64 t, %1; cvt.u32.u64 %0, t; }" : "=r"(a) : "l"(p));
    return a;
}

#define LDSM_X4(r, a) \
    asm volatile("ldmatrix.sync.aligned.m8n8.x4.shared.b16 {%0,%1,%2,%3}, [%4];" \
        : "=r"((r)[0]), "=r"((r)[1]), "=r"((r)[2]), "=r"((r)[3]) : "r"(a))
#define LDSM_X4T(r, a) \
    asm volatile("ldmatrix.sync.aligned.m8n8.x4.trans.shared.b16 {%0,%1,%2,%3}, [%4];" \
        : "=r"((r)[0]), "=r"((r)[1]), "=r"((r)[2]), "=r"((r)[3]) : "r"(a))

__device__ __forceinline__ void mma_fp16(float* c, const uint32_t* a, uint32_t b0, uint32_t b1) {
    asm volatile(
        "mma.sync.aligned.m16n8k16.row.col.f32.f16.f16.f32 "
        "{%0,%1,%2,%3}, {%4,%5,%6,%7}, {%8,%9}, {%0,%1,%2,%3};"
        : "+f"(c[0]), "+f"(c[1]), "+f"(c[2]), "+f"(c[3])
        : "r"(a[0]), "r"(a[1]), "r"(a[2]), "r"(a[3]), "r"(b0), "r"(b1));
}

__device__ __forceinline__ void split_pack(float x, float y, uint32_t& h, uint32_t& l) {
    __half hx = __float2half(x);
    __half hy = __float2half(y);
    __half lx = __float2half(x - __half2float(hx));
    __half ly = __float2half(y - __half2float(hy));
    __half2 hh; hh.x = hx; hh.y = hy;
    __half2 ll; ll.x = lx; ll.y = ly;
    h = *(uint32_t*)&hh;
    l = *(uint32_t*)&ll;
}

// ======================= mask canonicalization + compaction ================
__global__ void detect_mask_kernel(const unsigned int* __restrict__ m) {
    __shared__ int red[256];
    int tid = threadIdx.x;
    int p = 0;
    for (int i = tid; i < (BB * NN) / 4; i += 256) {
        unsigned int w = m[i];
        if (w != 0u && w != 1u && w != 0x3F800000u) p = 1;
    }
    red[tid] = p;
    __syncthreads();
    for (int s = 128; s > 0; s >>= 1) {
        if (tid < s) red[tid] |= red[tid + s];
        __syncthreads();
    }
    if (tid == 0) g_mwidth1 = red[0];
}

__global__ void decode_compact_kernel(const void* __restrict__ m) {
    int b = blockIdx.x;
    int tid = threadIdx.x;
    int w = tid >> 5, l = tid & 31;
    __shared__ int wcnt[8], woff[8];
    int i = b * NN + tid;
    int valid;
    if (g_mwidth1) valid = (((const unsigned char*)m)[i] != 0);
    else           valid = (((const unsigned int*)m)[i] != 0u);
    unsigned bal = __ballot_sync(0xffffffffu, valid);
    int pre = __popc(bal & ((1u << l) - 1u));
    if (l == 31) wcnt[w] = __popc(bal);
    g_idx[i] = 0;   // prefill pads with a safe (valid) index
    __syncthreads();
    if (tid == 0) {
        int s = 0;
        for (int k = 0; k < 8; k++) { woff[k] = s; s += wcnt[k]; }
        g_nv[b] = s;
    }
    __syncthreads();
    if (valid) g_idx[b * NN + woff[w] + pre] = tid;
}

// ======================= weight contraction (scaled + split) ===============
__global__ void prep_w_kernel(const float* __restrict__ Wq1, const float* __restrict__ Wk1,
                              const float* __restrict__ Wq2, const float* __restrict__ Wk2) {
    int a = blockIdx.x;
    int c = threadIdx.x & 127, kc = threadIdx.x >> 7;
    __shared__ float red[512];
    const float* X = (blockIdx.y == 0) ? Wq1 : Wq2;
    const float* Y = (blockIdx.y == 0) ? Wk1 : Wk2;
    float acc = 0.f;
#pragma unroll 8
    for (int k = kc * 32; k < kc * 32 + 32; k++)
        acc = fmaf(X[k * DD + c], Y[k * DD + a], acc);
    red[kc * 128 + c] = acc;
    __syncthreads();
    if (kc == 0) {
        float v = (red[c] + red[128 + c]) + (red[256 + c] + red[384 + c]);
        v *= SCALE;
        __half h = __float2half(v);
        __half lo = __float2half(v - __half2float(h));
        int idx = a * DD + c;
        if (blockIdx.y == 0) { g_W1h[idx] = h; g_W1l[idx] = lo; }
        else                 { g_W2h[idx] = h; g_W2l[idx] = lo; }
    }
}

// ======================= fused: M split + T GEMM + gate + sat_out ==========
// Persistent: 296 CTAs (2/SM) stage W1 ONCE, then stride over 2048 64-row
// tiles.  T in registers; alpha = rowdot(S,T); emits sat_out fp32 + split,
// and M split as a side product.
#define GT_A    0
#define GT_WH   17408
#define GT_WL   52224
#define GT_SMEM 87040

__global__ __launch_bounds__(256, 2)
void gemm_T_fused(const float* __restrict__ M, const float* __restrict__ S,
                  float* __restrict__ SO) {
    extern __shared__ char smem[];
    __shared__ float s_red[128];
    uint32_t sbase = smem_u32(smem);
    int tid = threadIdx.x;
    int w = tid >> 5, l = tid & 31;

    // stage W1 split ONCE
    for (int idx = tid; idx < 2048; idx += 256) {
        int row = idx >> 4, c8 = idx & 15;
        *(uint4*)(smem + GT_WH + row * 272 + c8 * 16) =
            *(const uint4*)(g_W1h + row * DD + c8 * 8);
        *(uint4*)(smem + GT_WL + row * 272 + c8 * 16) =
            *(const uint4*)(g_W1l + row * DD + c8 * 8);
    }

    int mw = w & 3, nwp = w >> 2;
    int r0 = mw * 16, c0 = nwp * 64;
    int g = l >> 2, t = l & 3;
    uint32_t halfOff = (uint32_t)((l >> 4) << 3);

    for (int item = blockIdx.x; item < 2048; item += gridDim.x) {
        size_t n0 = (size_t)item * 64;

        // convert M rows: fp32 -> split fp16 (global) + Mh smem tile
        for (int idx = tid; idx < 4096; idx += 256) {
            int row = idx >> 6, c2 = idx & 63;
            float2 v = ((const float2*)(M + (n0 + row) * DD))[c2];
            uint32_t h, lo;
            split_pack(v.x, v.y, h, lo);
            ((uint32_t*)(g_Mh + (n0 + row) * DD))[c2] = h;
            ((uint32_t*)(g_Ml + (n0 + row) * DD))[c2] = lo;
            *(uint32_t*)(smem + GT_A + row * 272 + c2 * 4) = h;
        }
        __syncthreads();

        float acc[8][4];
#pragma unroll
        for (int j = 0; j < 8; j++)
#pragma unroll
            for (int q = 0; q < 4; q++) acc[j][q] = 0.f;

#pragma unroll 1
        for (int ks = 0; ks < 8; ks++) {
            int k0 = 16 * ks;
            uint32_t aH[4];
            LDSM_X4(aH, sbase + GT_A + (r0 + (l & 15)) * 272 + (k0 + halfOff) * 2);
#pragma unroll
            for (int np = 0; np < 4; np++) {
                uint32_t baddr = sbase + GT_WH + (uint32_t)(k0 + (l & 15)) * 272 +
                                 (uint32_t)(c0 + 16 * np + halfOff) * 2;
                uint32_t bH[4], bL[4];
                LDSM_X4T(bH, baddr);
                LDSM_X4T(bL, baddr + (GT_WL - GT_WH));
                mma_fp16(acc[2 * np],     aH, bH[0], bH[1]);
                mma_fp16(acc[2 * np],     aH, bL[0], bL[1]);
                mma_fp16(acc[2 * np + 1], aH, bH[2], bH[3]);
                mma_fp16(acc[2 * np + 1], aH, bL[2], bL[3]);
            }
        }

        // --- epilogue: alpha = rowdot(S, T), then sat_out + split ---
        int rowA = r0 + g, rowB = rowA + 8;
        float p0 = 0.f, p1 = 0.f;
        {
            size_t rA = n0 + rowA, rB = n0 + rowB;
#pragma unroll
            for (int nt = 0; nt < 8; nt++) {
                int col = c0 + nt * 8 + 2 * t;
                float2 sa = *(const float2*)(S + rA * DD + col);
                float2 sb = *(const float2*)(S + rB * DD + col);
                p0 += sa.x * acc[nt][0] + sa.y * acc[nt][1];
                p1 += sb.x * acc[nt][2] + sb.y * acc[nt][3];
            }
        }
        p0 += __shfl_xor_sync(0xffffffffu, p0, 1);
        p0 += __shfl_xor_sync(0xffffffffu, p0, 2);
        p1 += __shfl_xor_sync(0xffffffffu, p1, 1);
        p1 += __shfl_xor_sync(0xffffffffu, p1, 2);
        if (t == 0) {
            s_red[nwp * 64 + rowA] = p0;
            s_red[nwp * 64 + rowB] = p1;
        }
        __syncthreads();

        float alA = s_red[rowA] + s_red[64 + rowA];
        float alB = s_red[rowB] + s_red[64 + rowB];
        size_t rA = n0 + rowA, rB = n0 + rowB;
#pragma unroll
        for (int nt = 0; nt < 8; nt++) {
            int col = c0 + nt * 8 + 2 * t;
            float2 sa = *(const float2*)(S + rA * DD + col);
            float2 ma = *(const float2*)(M + rA * DD + col);
            float2 oa;
            oa.x = fmaf(alA, ma.x - sa.x, sa.x);
            oa.y = fmaf(alA, ma.y - sa.y, sa.y);
            *(float2*)(SO + rA * DD + col) = oa;
            uint32_t h, lo;
            split_pack(oa.x, oa.y, h, lo);
            *(uint32_t*)(g_Sh + rA * DD + col) = h;
            *(uint32_t*)(g_Sl + rA * DD + col) = lo;

            float2 sb = *(const float2*)(S + rB * DD + col);
            float2 mb = *(const float2*)(M + rB * DD + col);
            float2 ob;
            ob.x = fmaf(alB, mb.x - sb.x, sb.x);
            ob.y = fmaf(alB, mb.y - sb.y, sb.y);
            *(float2*)(SO + rB * DD + col) = ob;
            split_pack(ob.x, ob.y, h, lo);
            *(uint32_t*)(g_Sh + rB * DD + col) = h;
            *(uint32_t*)(g_Sl + rB * DD + col) = lo;
        }
        __syncthreads();   // iter-n reads done before iter-n+1 staging
    }
}

// ======================= K2C GEMM (3-term, gathered, compact out) ==========
// Persistent: 296 CTAs stage W2 ONCE, then stride over (b, 64-row-quadrant)
// work items with uniform early skip of all-padding tiles.
#define GK_AH   0
#define GK_AL   17408
#define GK_WH   34816
#define GK_WL   69632
#define GK_SMEM 104448

__global__ __launch_bounds__(256, 2)
void gemm_K2C_kernel() {
    extern __shared__ char smem[];
    uint32_t sbase = smem_u32(smem);
    int tid = threadIdx.x;
    int w = tid >> 5, l = tid & 31;

    // stage W2 split ONCE
    for (int idx = tid; idx < 2048; idx += 256) {
        int row = idx >> 4, c8 = idx & 15;
        *(uint4*)(smem + GK_WH + row * 272 + c8 * 16) = *(const uint4*)(g_W2h + row * DD + c8 * 8);
        *(uint4*)(smem + GK_WL + row * 272 + c8 * 16) = *(const uint4*)(g_W2l + row * DD + c8 * 8);
    }
    __syncthreads();

    int mw = w & 3, nwp = w >> 2;
    int r0 = mw * 16, c0 = nwp * 64;
    int g = l >> 2, t = l & 3;
    uint32_t halfOff = (uint32_t)((l >> 4) << 3);

    for (int item = blockIdx.x; item < BB * 4; item += gridDim.x) {
        int b = item >> 2;
        int pos0 = (item & 3) * 64;
        if (pos0 >= g_nv[b]) continue;   // uniform across block

        for (int idx = tid; idx < 1024; idx += 256) {
            int row = idx >> 4, c8 = idx & 15;
            int j = g_idx[b * NN + pos0 + row];
            size_t srow = ((size_t)b * NN + j) * DD;
            *(uint4*)(smem + GK_AH + row * 272 + c8 * 16) = *(const uint4*)(g_Sh + srow + c8 * 8);
            *(uint4*)(smem + GK_AL + row * 272 + c8 * 16) = *(const uint4*)(g_Sl + srow + c8 * 8);
        }
        __syncthreads();

        float acc[8][4];
#pragma unroll
        for (int j = 0; j < 8; j++)
#pragma unroll
            for (int q = 0; q < 4; q++) acc[j][q] = 0.f;

#pragma unroll 1
        for (int ks = 0; ks < 8; ks++) {
            int k0 = 16 * ks;
            uint32_t aH[4], aL[4];
            uint32_t aaddr = sbase + GK_AH + (r0 + (l & 15)) * 272 + (k0 + halfOff) * 2;
            LDSM_X4(aH, aaddr);
            LDSM_X4(aL, aaddr + (GK_AL - GK_AH));
#pragma unroll
            for (int np = 0; np < 4; np++) {
                uint32_t baddr = sbase + GK_WH + (uint32_t)(k0 + (l & 15)) * 272 +
                                 (uint32_t)(c0 + 16 * np + halfOff) * 2;
                uint32_t bH[4], bL[4];
                LDSM_X4T(bH, baddr);
                LDSM_X4T(bL, baddr + (GK_WL - GK_WH));
                mma_fp16(acc[2 * np],     aH, bH[0], bH[1]);
                mma_fp16(acc[2 * np],     aH, bL[0], bL[1]);
                mma_fp16(acc[2 * np],     aL, bH[0], bH[1]);
                mma_fp16(acc[2 * np + 1], aH, bH[2], bH[3]);
                mma_fp16(acc[2 * np + 1], aH, bL[2], bL[3]);
                mma_fp16(acc[2 * np + 1], aL, bH[2], bH[3]);
            }
        }

#pragma unroll
        for (int nt = 0; nt < 8; nt++) {
            size_t rowA = (size_t)b * NN + pos0 + r0 + g;
            size_t rowB = rowA + 8;
            int col = c0 + nt * 8 + 2 * t;
            uint32_t h, lo;
            split_pack(acc[nt][0], acc[nt][1], h, lo);
            *(uint32_t*)(g_Kh + rowA * DD + col) = h;
            *(uint32_t*)(g_Kl + rowA * DD + col) = lo;
            split_pack(acc[nt][2], acc[nt][3], h, lo);
            *(uint32_t*)(g_Kh + rowB * DD + col) = h;
            *(uint32_t*)(g_Kl + rowB * DD + col) = lo;
        }
        __syncthreads();   // MMA reads done before next iter staging
    }
}

// ======================= fused attention (compacted keys) ==================
// CTA = (batch b, 128 i-rows).  512 threads = 16 warps: 8 m-warps x 2 n-warps.
// smem: Q 128 rows h/l (34816 each), K 256 rows h/l (69632 each).
// P (528-stride, 128 rows = 67584) overlays Q; V (hi only) overlays K.
#define SM_QH  0
#define SM_QL  34816
#define SM_KH  69632
#define SM_KL  139264
#define SM_PH  0
#define SM_VH  69632
#define SMEM_ATTN 208896

#define BETA_CHUNK(ACC, CBASE, NSTEPS) do {                                         \
    _Pragma("unroll")                                                               \
    for (int ks = 0; ks < 8; ks++) {                                                \
        int k0 = 16 * ks;                                                           \
        uint32_t aH[4], aL[4];                                                      \
        uint32_t aaddr = sbase + SM_QH + aRow * 272 + (k0 + halfOff) * 2;           \
        LDSM_X4(aH, aaddr);                                                         \
        LDSM_X4(aL, aaddr + (SM_QL - SM_QH));                                       \
        _Pragma("unroll")                                                           \
        for (int np = 0; np < 4; np++) {                                            \
            if (np >= (NSTEPS)) break;                                              \
            uint32_t baddr = sbase + SM_KH +                                        \
                (uint32_t)((CBASE) + nw * 64 + 16 * np + bRowBase) * 272 +          \
                (k0 + bColHalf) * 2;                                                \
            uint32_t bH[4], bL[4];                                                  \
            LDSM_X4(bH, baddr);                                                     \
            LDSM_X4(bL, baddr + (SM_KL - SM_KH));                                   \
            mma_fp16(ACC[2 * np],     aH, bH[0], bH[1]);                            \
            mma_fp16(ACC[2 * np],     aH, bL[0], bL[1]);                            \
            mma_fp16(ACC[2 * np],     aL, bH[0], bH[1]);                            \
            mma_fp16(ACC[2 * np + 1], aH, bH[2], bH[3]);                            \
            mma_fp16(ACC[2 * np + 1], aH, bL[2], bL[3]);                            \
            mma_fp16(ACC[2 * np + 1], aL, bH[2], bH[3]);                            \
        }                                                                           \
    }                                                                               \
} while (0)

__global__ __launch_bounds__(512, 1)
void attn_kernel(float* __restrict__ O) {
    extern __shared__ char smem[];
    __shared__ float s_bias[256];
    __shared__ float s_red[512];
    __shared__ int s_idx[256];
    uint32_t sbase = smem_u32(smem);

    int tid = threadIdx.x;
    int w = tid >> 5, l = tid & 31;
    int g = l >> 2, t = l & 3;
    int mw = w & 7, nw = w >> 3;
    int b = blockIdx.y;
    int i0 = blockIdx.x * 128;
    size_t boff = (size_t)b * NN * DD;

    int nv = g_nv[b];
    int kpadN = (nv + 15) & ~15;

    if (tid < 256) {
        s_idx[tid] = g_idx[b * NN + tid];
        s_bias[tid] = (tid < nv) ? 0.f : -1e30f;
    }

    // stage Q (128 rows of M split)
    for (int idx = tid; idx < 128 * 16; idx += 512) {
        int row = idx >> 4, c8 = idx & 15;
        size_t src = boff + (size_t)(i0 + row) * DD + c8 * 8;
        *(uint4*)(smem + SM_QH + row * 272 + c8 * 16) = *(const uint4*)(g_Mh + src);
        *(uint4*)(smem + SM_QL + row * 272 + c8 * 16) = *(const uint4*)(g_Ml + src);
    }
    // stage K compact rows [0, kpadN) (zero pads)
    {
        uint4 z = make_uint4(0, 0, 0, 0);
        for (int idx = tid; idx < kpadN * 16; idx += 512) {
            int row = idx >> 4, c8 = idx & 15;
            uint4 vh = z, vl = z;
            if (row < nv) {
                size_t src = boff + (size_t)row * DD + c8 * 8;
                vh = *(const uint4*)(g_Kh + src);
                vl = *(const uint4*)(g_Kl + src);
            }
            *(uint4*)(smem + SM_KH + row * 272 + c8 * 16) = vh;
            *(uint4*)(smem + SM_KL + row * 272 + c8 * 16) = vl;
        }
    }
    __syncthreads();

    // --- beta GEMM over valid 16-col tiles only ---
    uint32_t aRow = (uint32_t)(16 * mw + (l & 15));
    uint32_t halfOff = (uint32_t)((l >> 4) << 3);
    uint32_t bRowBase = (uint32_t)(((l >> 4) << 3) + (l & 7));
    uint32_t bColHalf = (uint32_t)(((l >> 3) & 1) << 3);

    int base0 = nw * 64, base1 = 128 + nw * 64;
    int ns0 = min(4, max(0, (kpadN - base0) >> 4));
    int ns1 = min(4, max(0, (kpadN - base1) >> 4));

    float acc0[8][4], acc1[8][4];
#pragma unroll
    for (int j = 0; j < 8; j++)
#pragma unroll
        for (int q = 0; q < 4; q++) { acc0[j][q] = 0.f; acc1[j][q] = 0.f; }

    if (ns0 > 0) BETA_CHUNK(acc0, 0, ns0);
    if (ns1 > 0) BETA_CHUNK(acc1, 128, ns1);

    // --- masked softmax (rows rowA, rowB in 0..127) ---
    int rowA = 16 * mw + g, rowB = rowA + 8;
    float mx0 = -3.0e38f, mx1 = -3.0e38f;
#pragma unroll
    for (int j = 0; j < 8; j++) {
        float2 bv = *(const float2*)&s_bias[nw * 64 + j * 8 + 2 * t];
        acc0[j][0] += bv.x; acc0[j][1] += bv.y;
        acc0[j][2] += bv.x; acc0[j][3] += bv.y;
        mx0 = fmaxf(mx0, fmaxf(acc0[j][0], acc0[j][1]));
        mx1 = fmaxf(mx1, fmaxf(acc0[j][2], acc0[j][3]));
    }
    if (kpadN > 128) {
#pragma unroll
        for (int j = 0; j < 8; j++) {
            float2 bv = *(const float2*)&s_bias[128 + nw * 64 + j * 8 + 2 * t];
            acc1[j][0] += bv.x; acc1[j][1] += bv.y;
            acc1[j][2] += bv.x; acc1[j][3] += bv.y;
            mx0 = fmaxf(mx0, fmaxf(acc1[j][0], acc1[j][1]));
            mx1 = fmaxf(mx1, fmaxf(acc1[j][2], acc1[j][3]));
        }
    }
    mx0 = fmaxf(mx0, __shfl_xor_sync(0xffffffffu, mx0, 1));
    mx0 = fmaxf(mx0, __shfl_xor_sync(0xffffffffu, mx0, 2));
    mx1 = fmaxf(mx1, __shfl_xor_sync(0xffffffffu, mx1, 1));
    mx1 = fmaxf(mx1, __shfl_xor_sync(0xffffffffu, mx1, 2));
    if (t == 0) {
        s_red[nw * 128 + rowA] = mx0;
        s_red[nw * 128 + rowB] = mx1;
    }
    __syncthreads();
    float M0 = fmaxf(s_red[rowA], s_red[128 + rowA]);
    float M1 = fmaxf(s_red[rowB], s_red[128 + rowB]);
    float s0 = 0.f, s1 = 0.f;
#pragma unroll
    for (int j = 0; j < 8; j++) {
        acc0[j][0] = __expf(acc0[j][0] - M0); s0 += acc0[j][0];
        acc0[j][1] = __expf(acc0[j][1] - M0); s0 += acc0[j][1];
        acc0[j][2] = __expf(acc0[j][2] - M1); s1 += acc0[j][2];
        acc0[j][3] = __expf(acc0[j][3] - M1); s1 += acc0[j][3];
    }
    if (kpadN > 128) {
#pragma unroll
        for (int j = 0; j < 8; j++) {
            acc1[j][0] = __expf(acc1[j][0] - M0); s0 += acc1[j][0];
            acc1[j][1] = __expf(acc1[j][1] - M0); s0 += acc1[j][1];
            acc1[j][2] = __expf(acc1[j][2] - M1); s1 += acc1[j][2];
            acc1[j][3] = __expf(acc1[j][3] - M1); s1 += acc1[j][3];
        }
    }
    s0 += __shfl_xor_sync(0xffffffffu, s0, 1);
    s0 += __shfl_xor_sync(0xffffffffu, s0, 2);
    s1 += __shfl_xor_sync(0xffffffffu, s1, 1);
    s1 += __shfl_xor_sync(0xffffffffu, s1, 2);
    __syncthreads();
    if (t == 0) {
        s_red[256 + nw * 128 + rowA] = s0;
        s_red[256 + nw * 128 + rowB] = s1;
    }
    __syncthreads();
    float inv0 = __fdividef(1.f, s_red[256 + rowA] + s_red[256 + 128 + rowA]);
    float inv1 = __fdividef(1.f, s_red[256 + rowB] + s_red[256 + 128 + rowB]);

    // --- write P (fp16 hi only) over retired Q region ---
    {
        char* ph = smem + SM_PH;
#pragma unroll
        for (int j = 0; j < 8; j++) {
            int col = nw * 64 + j * 8 + 2 * t;
            __half2 a; a.x = __float2half(acc0[j][0] * inv0); a.y = __float2half(acc0[j][1] * inv0);
            *(uint32_t*)(ph + rowA * 528 + col * 2) = *(uint32_t*)&a;
            __half2 c; c.x = __float2half(acc0[j][2] * inv1); c.y = __float2half(acc0[j][3] * inv1);
            *(uint32_t*)(ph + rowB * 528 + col * 2) = *(uint32_t*)&c;
        }
        if (kpadN > 128) {
#pragma unroll
            for (int j = 0; j < 8; j++) {
                int col = 128 + nw * 64 + j * 8 + 2 * t;
                __half2 a; a.x = __float2half(acc1[j][0] * inv0); a.y = __float2half(acc1[j][1] * inv0);
                *(uint32_t*)(ph + rowA * 528 + col * 2) = *(uint32_t*)&a;
                __half2 c; c.x = __float2half(acc1[j][2] * inv1); c.y = __float2half(acc1[j][3] * inv1);
                *(uint32_t*)(ph + rowB * 528 + col * 2) = *(uint32_t*)&c;
            }
        }
    }
    // --- stage V gathered (hi only, overlays retired K) ---
    {
        uint4 z = make_uint4(0, 0, 0, 0);
        for (int idx = tid; idx < kpadN * 16; idx += 512) {
            int row = idx >> 4, c8 = idx & 15;
            uint4 vh = z;
            if (row < nv) {
                size_t src = boff + (size_t)s_idx[row] * DD + c8 * 8;
                vh = *(const uint4*)(g_Mh + src);
            }
            *(uint4*)(smem + SM_VH + row * 272 + c8 * 16) = vh;
        }
    }
    __syncthreads();

    // --- PV GEMM: 1-term (P hi * V hi), k up to kpadN ---
    int d0 = 64 * nw;
    float o[8][4];
#pragma unroll
    for (int i = 0; i < 8; i++)
#pragma unroll
        for (int j = 0; j < 4; j++) o[i][j] = 0.f;

    int ksteps = kpadN >> 4;
#pragma unroll 1
    for (int ks = 0; ks < ksteps; ks++) {
        int k0 = 16 * ks;
        uint32_t aH[4];
        LDSM_X4(aH, sbase + SM_PH + aRow * 528 + (k0 + halfOff) * 2);
#pragma unroll
        for (int np = 0; np < 4; np++) {
            uint32_t baddr = sbase + SM_VH + (uint32_t)(k0 + (l & 15)) * 272 +
                             (uint32_t)(d0 + 16 * np + halfOff) * 2;
            uint32_t bH[4];
            LDSM_X4T(bH, baddr);
            mma_fp16(o[2 * np],     aH, bH[0], bH[1]);
            mma_fp16(o[2 * np + 1], aH, bH[2], bH[3]);
        }
    }

    float* Ob = O + ((size_t)b * NN + i0) * DD;
#pragma unroll
    for (int nt = 0; nt < 8; nt++) {
        int col = d0 + 8 * nt + 2 * t;
        *(float2*)&Ob[(size_t)rowA * DD + col] = make_float2(o[nt][0], o[nt][1]);
        *(float2*)&Ob[(size_t)rowB * DD + col] = make_float2(o[nt][2], o[nt][3]);
    }
}

// ---------------------------------------------------------------------------
extern "C" void kernel_launch(void* const* d_in, const int* in_sizes, int n_in,
                              void* d_out, int out_size) {
    (void)in_sizes; (void)n_in; (void)out_size;
    const float* mirror    = (const float*)d_in[0];
    const float* satellite = (const float*)d_in[1];
    const void*  mask      = d_in[2];
    const float* Wq1 = (const float*)d_in[3];
    const float* Wk1 = (const float*)d_in[4];
    const float* Wq2 = (const float*)d_in[5];
    const float* Wk2 = (const float*)d_in[6];
    float* sat_out = (float*)d_out;
    float* mir_out = (float*)d_out + BND;

    cudaFuncSetAttribute(gemm_T_fused,    cudaFuncAttributeMaxDynamicSharedMemorySize, GT_SMEM);
    cudaFuncSetAttribute(gemm_K2C_kernel, cudaFuncAttributeMaxDynamicSharedMemorySize, GK_SMEM);
    cudaFuncSetAttribute(attn_kernel,     cudaFuncAttributeMaxDynamicSharedMemorySize, SMEM_ATTN);

    detect_mask_kernel<<<1, 256>>>((const unsigned int*)mask);
    decode_compact_kernel<<<BB, 256>>>(mask);
    prep_w_kernel<<<dim3(128, 2), 512>>>(Wq1, Wk1, Wq2, Wk2);

    gemm_T_fused<<<296, 256, GT_SMEM>>>(mirror, satellite, sat_out);
    gemm_K2C_kernel<<<296, 256, GK_SMEM>>>();
    attn_kernel<<<dim3(NN / 128, BB), 512, SMEM_ATTN>>>(mir_out);
}

// round 12
// speedup vs baseline: 1.4750x; 1.0768x over previous
#include <cuda_runtime.h>
#include <cuda_fp16.h>
#include <cstdint>

// Problem constants
#define BB 512
#define NN 256
#define DD 128
#define BND ((size_t)BB * NN * DD)

static __device__ __half g_W1h[DD * DD];
static __device__ __half g_W2h[DD * DD], g_W2l[DD * DD];
static __device__ __half g_Mh[BND], g_Ml[BND];       // mirror split
static __device__ __half g_Sh[BND];                  // sat_out hi
static __device__ __half g_Kh[BND], g_Kl[BND];       // K2C split (COMPACT rows)
static __device__ int g_idx[BB * NN];                // compact pos -> j
static __device__ int g_nv[BB];                      // valid count per batch
static __device__ int g_mwidth1;

#define SCALE 0.08838834764831845f  // 1/sqrt(128)

// ============================ PTX helpers ==================================
__device__ __forceinline__ uint32_t smem_u32(const void* p) {
    uint32_t a;
    asm("{ .reg .u64 t; cvta.to.shared.u64 t, %1; cvt.u32.u64 %0, t; }" : "=r"(a) : "l"(p));
    return a;
}

#define LDSM_X4(r, a) \
    asm volatile("ldmatrix.sync.aligned.m8n8.x4.shared.b16 {%0,%1,%2,%3}, [%4];" \
        : "=r"((r)[0]), "=r"((r)[1]), "=r"((r)[2]), "=r"((r)[3]) : "r"(a))
#define LDSM_X4T(r, a) \
    asm volatile("ldmatrix.sync.aligned.m8n8.x4.trans.shared.b16 {%0,%1,%2,%3}, [%4];" \
        : "=r"((r)[0]), "=r"((r)[1]), "=r"((r)[2]), "=r"((r)[3]) : "r"(a))

__device__ __forceinline__ void mma_fp16(float* c, const uint32_t* a, uint32_t b0, uint32_t b1) {
    asm volatile(
        "mma.sync.aligned.m16n8k16.row.col.f32.f16.f16.f32 "
        "{%0,%1,%2,%3}, {%4,%5,%6,%7}, {%8,%9}, {%0,%1,%2,%3};"
        : "+f"(c[0]), "+f"(c[1]), "+f"(c[2]), "+f"(c[3])
        : "r"(a[0]), "r"(a[1]), "r"(a[2]), "r"(a[3]), "r"(b0), "r"(b1));
}

__device__ __forceinline__ void split_pack(float x, float y, uint32_t& h, uint32_t& l) {
    __half hx = __float2half(x);
    __half hy = __float2half(y);
    __half lx = __float2half(x - __half2float(hx));
    __half ly = __float2half(y - __half2float(hy));
    __half2 hh; hh.x = hx; hh.y = hy;
    __half2 ll; ll.x = lx; ll.y = ly;
    h = *(uint32_t*)&hh;
    l = *(uint32_t*)&ll;
}

__device__ __forceinline__ uint32_t pack_hi(float x, float y) {
    __half2 hh; hh.x = __float2half(x); hh.y = __float2half(y);
    return *(uint32_t*)&hh;
}

// ======================= mask canonicalization + compaction ================
__global__ void detect_mask_kernel(const unsigned int* __restrict__ m) {
    __shared__ int red[256];
    int tid = threadIdx.x;
    int p = 0;
    for (int i = tid; i < (BB * NN) / 4; i += 256) {
        unsigned int w = m[i];
        if (w != 0u && w != 1u && w != 0x3F800000u) p = 1;
    }
    red[tid] = p;
    __syncthreads();
    for (int s = 128; s > 0; s >>= 1) {
        if (tid < s) red[tid] |= red[tid + s];
        __syncthreads();
    }
    if (tid == 0) g_mwidth1 = red[0];
}

__global__ void decode_compact_kernel(const void* __restrict__ m) {
    int b = blockIdx.x;
    int tid = threadIdx.x;
    int w = tid >> 5, l = tid & 31;
    __shared__ int wcnt[8], woff[8];
    int i = b * NN + tid;
    int valid;
    if (g_mwidth1) valid = (((const unsigned char*)m)[i] != 0);
    else           valid = (((const unsigned int*)m)[i] != 0u);
    unsigned bal = __ballot_sync(0xffffffffu, valid);
    int pre = __popc(bal & ((1u << l) - 1u));
    if (l == 31) wcnt[w] = __popc(bal);
    g_idx[i] = 0;   // prefill pads with a safe (valid) index
    __syncthreads();
    if (tid == 0) {
        int s = 0;
        for (int k = 0; k < 8; k++) { woff[k] = s; s += wcnt[k]; }
        g_nv[b] = s;
    }
    __syncthreads();
    if (valid) g_idx[b * NN + woff[w] + pre] = tid;
}

// ======================= weight contraction (scaled + split) ===============
__global__ void prep_w_kernel(const float* __restrict__ Wq1, const float* __restrict__ Wk1,
                              const float* __restrict__ Wq2, const float* __restrict__ Wk2) {
    int a = blockIdx.x;
    int c = threadIdx.x & 127, kc = threadIdx.x >> 7;
    __shared__ float red[512];
    const float* X = (blockIdx.y == 0) ? Wq1 : Wq2;
    const float* Y = (blockIdx.y == 0) ? Wk1 : Wk2;
    float acc = 0.f;
#pragma unroll 8
    for (int k = kc * 32; k < kc * 32 + 32; k++)
        acc = fmaf(X[k * DD + c], Y[k * DD + a], acc);
    red[kc * 128 + c] = acc;
    __syncthreads();
    if (kc == 0) {
        float v = (red[c] + red[128 + c]) + (red[256 + c] + red[384 + c]);
        v *= SCALE;
        __half h = __float2half(v);
        __half lo = __float2half(v - __half2float(h));
        int idx = a * DD + c;
        if (blockIdx.y == 0) { g_W1h[idx] = h; }
        else                 { g_W2h[idx] = h; g_W2l[idx] = lo; }
    }
}

// ======================= fused: M split + T GEMM + gate + sat_out ==========
// Persistent: 296 CTAs (2/SM) stage W1h ONCE, then stride over 2048 64-row
// tiles.  T = Mh @ W1h (1-term); alpha = rowdot(S,T); emits sat_out fp32 +
// hi split (g_Sh), and M split (hi+lo, needed by attn) as a side product.
#define GT_A    0
#define GT_WH   17408
#define GT_SMEM 52224

__global__ __launch_bounds__(256, 2)
void gemm_T_fused(const float* __restrict__ M, const float* __restrict__ S,
                  float* __restrict__ SO) {
    extern __shared__ char smem[];
    __shared__ float s_red[128];
    uint32_t sbase = smem_u32(smem);
    int tid = threadIdx.x;
    int w = tid >> 5, l = tid & 31;

    // stage W1h ONCE
    for (int idx = tid; idx < 2048; idx += 256) {
        int row = idx >> 4, c8 = idx & 15;
        *(uint4*)(smem + GT_WH + row * 272 + c8 * 16) =
            *(const uint4*)(g_W1h + row * DD + c8 * 8);
    }

    int mw = w & 3, nwp = w >> 2;
    int r0 = mw * 16, c0 = nwp * 64;
    int g = l >> 2, t = l & 3;
    uint32_t halfOff = (uint32_t)((l >> 4) << 3);

    for (int item = blockIdx.x; item < 2048; item += gridDim.x) {
        size_t n0 = (size_t)item * 64;

        // convert M rows: fp32 -> split fp16 (global) + Mh smem tile
        for (int idx = tid; idx < 4096; idx += 256) {
            int row = idx >> 6, c2 = idx & 63;
            float2 v = ((const float2*)(M + (n0 + row) * DD))[c2];
            uint32_t h, lo;
            split_pack(v.x, v.y, h, lo);
            ((uint32_t*)(g_Mh + (n0 + row) * DD))[c2] = h;
            ((uint32_t*)(g_Ml + (n0 + row) * DD))[c2] = lo;
            *(uint32_t*)(smem + GT_A + row * 272 + c2 * 4) = h;
        }
        __syncthreads();

        float acc[8][4];
#pragma unroll
        for (int j = 0; j < 8; j++)
#pragma unroll
            for (int q = 0; q < 4; q++) acc[j][q] = 0.f;

#pragma unroll 1
        for (int ks = 0; ks < 8; ks++) {
            int k0 = 16 * ks;
            uint32_t aH[4];
            LDSM_X4(aH, sbase + GT_A + (r0 + (l & 15)) * 272 + (k0 + halfOff) * 2);
#pragma unroll
            for (int np = 0; np < 4; np++) {
                uint32_t baddr = sbase + GT_WH + (uint32_t)(k0 + (l & 15)) * 272 +
                                 (uint32_t)(c0 + 16 * np + halfOff) * 2;
                uint32_t bH[4];
                LDSM_X4T(bH, baddr);
                mma_fp16(acc[2 * np],     aH, bH[0], bH[1]);
                mma_fp16(acc[2 * np + 1], aH, bH[2], bH[3]);
            }
        }

        // --- epilogue: alpha = rowdot(S, T), then sat_out + hi split ---
        int rowA = r0 + g, rowB = rowA + 8;
        float p0 = 0.f, p1 = 0.f;
        {
            size_t rA = n0 + rowA, rB = n0 + rowB;
#pragma unroll
            for (int nt = 0; nt < 8; nt++) {
                int col = c0 + nt * 8 + 2 * t;
                float2 sa = *(const float2*)(S + rA * DD + col);
                float2 sb = *(const float2*)(S + rB * DD + col);
                p0 += sa.x * acc[nt][0] + sa.y * acc[nt][1];
                p1 += sb.x * acc[nt][2] + sb.y * acc[nt][3];
            }
        }
        p0 += __shfl_xor_sync(0xffffffffu, p0, 1);
        p0 += __shfl_xor_sync(0xffffffffu, p0, 2);
        p1 += __shfl_xor_sync(0xffffffffu, p1, 1);
        p1 += __shfl_xor_sync(0xffffffffu, p1, 2);
        if (t == 0) {
            s_red[nwp * 64 + rowA] = p0;
            s_red[nwp * 64 + rowB] = p1;
        }
        __syncthreads();

        float alA = s_red[rowA] + s_red[64 + rowA];
        float alB = s_red[rowB] + s_red[64 + rowB];
        size_t rA = n0 + rowA, rB = n0 + rowB;
#pragma unroll
        for (int nt = 0; nt < 8; nt++) {
            int col = c0 + nt * 8 + 2 * t;
            float2 sa = *(const float2*)(S + rA * DD + col);
            float2 ma = *(const float2*)(M + rA * DD + col);
            float2 oa;
            oa.x = fmaf(alA, ma.x - sa.x, sa.x);
            oa.y = fmaf(alA, ma.y - sa.y, sa.y);
            *(float2*)(SO + rA * DD + col) = oa;
            *(uint32_t*)(g_Sh + rA * DD + col) = pack_hi(oa.x, oa.y);

            float2 sb = *(const float2*)(S + rB * DD + col);
            float2 mb = *(const float2*)(M + rB * DD + col);
            float2 ob;
            ob.x = fmaf(alB, mb.x - sb.x, sb.x);
            ob.y = fmaf(alB, mb.y - sb.y, sb.y);
            *(float2*)(SO + rB * DD + col) = ob;
            *(uint32_t*)(g_Sh + rB * DD + col) = pack_hi(ob.x, ob.y);
        }
        __syncthreads();   // iter-n reads done before iter-n+1 staging
    }
}

// ======================= K2C GEMM (2-term, gathered, compact out) ==========
// K2C = Sh @ (W2h + W2l).  Persistent: 296 CTAs stage W2 ONCE, then stride
// over (b, 64-row-quadrant) items with uniform early skip of padding tiles.
#define GK_A    0
#define GK_WH   17408
#define GK_WL   52224
#define GK_SMEM 87040

__global__ __launch_bounds__(256, 2)
void gemm_K2C_kernel() {
    extern __shared__ char smem[];
    uint32_t sbase = smem_u32(smem);
    int tid = threadIdx.x;
    int w = tid >> 5, l = tid & 31;

    // stage W2 split ONCE
    for (int idx = tid; idx < 2048; idx += 256) {
        int row = idx >> 4, c8 = idx & 15;
        *(uint4*)(smem + GK_WH + row * 272 + c8 * 16) = *(const uint4*)(g_W2h + row * DD + c8 * 8);
        *(uint4*)(smem + GK_WL + row * 272 + c8 * 16) = *(const uint4*)(g_W2l + row * DD + c8 * 8);
    }
    __syncthreads();

    int mw = w & 3, nwp = w >> 2;
    int r0 = mw * 16, c0 = nwp * 64;
    int g = l >> 2, t = l & 3;
    uint32_t halfOff = (uint32_t)((l >> 4) << 3);

    for (int item = blockIdx.x; item < BB * 4; item += gridDim.x) {
        int b = item >> 2;
        int pos0 = (item & 3) * 64;
        if (pos0 >= g_nv[b]) continue;   // uniform across block

        for (int idx = tid; idx < 1024; idx += 256) {
            int row = idx >> 4, c8 = idx & 15;
            int j = g_idx[b * NN + pos0 + row];
            size_t srow = ((size_t)b * NN + j) * DD;
            *(uint4*)(smem + GK_A + row * 272 + c8 * 16) = *(const uint4*)(g_Sh + srow + c8 * 8);
        }
        __syncthreads();

        float acc[8][4];
#pragma unroll
        for (int j = 0; j < 8; j++)
#pragma unroll
            for (int q = 0; q < 4; q++) acc[j][q] = 0.f;

#pragma unroll 1
        for (int ks = 0; ks < 8; ks++) {
            int k0 = 16 * ks;
            uint32_t aH[4];
            LDSM_X4(aH, sbase + GK_A + (r0 + (l & 15)) * 272 + (k0 + halfOff) * 2);
#pragma unroll
            for (int np = 0; np < 4; np++) {
                uint32_t baddr = sbase + GK_WH + (uint32_t)(k0 + (l & 15)) * 272 +
                                 (uint32_t)(c0 + 16 * np + halfOff) * 2;
                uint32_t bH[4], bL[4];
                LDSM_X4T(bH, baddr);
                LDSM_X4T(bL, baddr + (GK_WL - GK_WH));
                mma_fp16(acc[2 * np],     aH, bH[0], bH[1]);
                mma_fp16(acc[2 * np],     aH, bL[0], bL[1]);
                mma_fp16(acc[2 * np + 1], aH, bH[2], bH[3]);
                mma_fp16(acc[2 * np + 1], aH, bL[2], bL[3]);
            }
        }

#pragma unroll
        for (int nt = 0; nt < 8; nt++) {
            size_t rowA = (size_t)b * NN + pos0 + r0 + g;
            size_t rowB = rowA + 8;
            int col = c0 + nt * 8 + 2 * t;
            uint32_t h, lo;
            split_pack(acc[nt][0], acc[nt][1], h, lo);
            *(uint32_t*)(g_Kh + rowA * DD + col) = h;
            *(uint32_t*)(g_Kl + rowA * DD + col) = lo;
            split_pack(acc[nt][2], acc[nt][3], h, lo);
            *(uint32_t*)(g_Kh + rowB * DD + col) = h;
            *(uint32_t*)(g_Kl + rowB * DD + col) = lo;
        }
        __syncthreads();   // MMA reads done before next iter staging
    }
}

// ======================= fused attention (compacted keys) ==================
// CTA = (batch b, 128 i-rows).  512 threads = 16 warps: 8 m-warps x 2 n-warps.
#define SM_QH  0
#define SM_QL  34816
#define SM_KH  69632
#define SM_KL  139264
#define SM_PH  0
#define SM_VH  69632
#define SMEM_ATTN 208896

#define BETA_CHUNK(ACC, CBASE, NSTEPS) do {                                         \
    _Pragma("unroll")                                                               \
    for (int ks = 0; ks < 8; ks++) {                                                \
        int k0 = 16 * ks;                                                           \
        uint32_t aH[4], aL[4];                                                      \
        uint32_t aaddr = sbase + SM_QH + aRow * 272 + (k0 + halfOff) * 2;           \
        LDSM_X4(aH, aaddr);                                                         \
        LDSM_X4(aL, aaddr + (SM_QL - SM_QH));                                       \
        _Pragma("unroll")                                                           \
        for (int np = 0; np < 4; np++) {                                            \
            if (np >= (NSTEPS)) break;                                              \
            uint32_t baddr = sbase + SM_KH +                                        \
                (uint32_t)((CBASE) + nw * 64 + 16 * np + bRowBase) * 272 +          \
                (k0 + bColHalf) * 2;                                                \
            uint32_t bH[4], bL[4];                                                  \
            LDSM_X4(bH, baddr);                                                     \
            LDSM_X4(bL, baddr + (SM_KL - SM_KH));                                   \
            mma_fp16(ACC[2 * np],     aH, bH[0], bH[1]);                            \
            mma_fp16(ACC[2 * np],     aH, bL[0], bL[1]);                            \
            mma_fp16(ACC[2 * np],     aL, bH[0], bH[1]);                            \
            mma_fp16(ACC[2 * np + 1], aH, bH[2], bH[3]);                            \
            mma_fp16(ACC[2 * np + 1], aH, bL[2], bL[3]);                            \
            mma_fp16(ACC[2 * np + 1], aL, bH[2], bH[3]);                            \
        }                                                                           \
    }                                                                               \
} while (0)

__global__ __launch_bounds__(512, 1)
void attn_kernel(float* __restrict__ O) {
    extern __shared__ char smem[];
    __shared__ float s_bias[256];
    __shared__ float s_red[512];
    __shared__ int s_idx[256];
    uint32_t sbase = smem_u32(smem);

    int tid = threadIdx.x;
    int w = tid >> 5, l = tid & 31;
    int g = l >> 2, t = l & 3;
    int mw = w & 7, nw = w >> 3;
    int b = blockIdx.y;
    int i0 = blockIdx.x * 128;
    size_t boff = (size_t)b * NN * DD;

    int nv = g_nv[b];
    int kpadN = (nv + 15) & ~15;

    if (tid < 256) {
        s_idx[tid] = g_idx[b * NN + tid];
        s_bias[tid] = (tid < nv) ? 0.f : -1e30f;
    }

    // stage Q (128 rows of M split)
    for (int idx = tid; idx < 128 * 16; idx += 512) {
        int row = idx >> 4, c8 = idx & 15;
        size_t src = boff + (size_t)(i0 + row) * DD + c8 * 8;
        *(uint4*)(smem + SM_QH + row * 272 + c8 * 16) = *(const uint4*)(g_Mh + src);
        *(uint4*)(smem + SM_QL + row * 272 + c8 * 16) = *(const uint4*)(g_Ml + src);
    }
    // stage K compact rows [0, kpadN) (zero pads)
    {
        uint4 z = make_uint4(0, 0, 0, 0);
        for (int idx = tid; idx < kpadN * 16; idx += 512) {
            int row = idx >> 4, c8 = idx & 15;
            uint4 vh = z, vl = z;
            if (row < nv) {
                size_t src = boff + (size_t)row * DD + c8 * 8;
                vh = *(const uint4*)(g_Kh + src);
                vl = *(const uint4*)(g_Kl + src);
            }
            *(uint4*)(smem + SM_KH + row * 272 + c8 * 16) = vh;
            *(uint4*)(smem + SM_KL + row * 272 + c8 * 16) = vl;
        }
    }
    __syncthreads();

    // --- beta GEMM over valid 16-col tiles only ---
    uint32_t aRow = (uint32_t)(16 * mw + (l & 15));
    uint32_t halfOff = (uint32_t)((l >> 4) << 3);
    uint32_t bRowBase = (uint32_t)(((l >> 4) << 3) + (l & 7));
    uint32_t bColHalf = (uint32_t)(((l >> 3) & 1) << 3);

    int base0 = nw * 64, base1 = 128 + nw * 64;
    int ns0 = min(4, max(0, (kpadN - base0) >> 4));
    int ns1 = min(4, max(0, (kpadN - base1) >> 4));

    float acc0[8][4], acc1[8][4];
#pragma unroll
    for (int j = 0; j < 8; j++)
#pragma unroll
        for (int q = 0; q < 4; q++) { acc0[j][q] = 0.f; acc1[j][q] = 0.f; }

    if (ns0 > 0) BETA_CHUNK(acc0, 0, ns0);
    if (ns1 > 0) BETA_CHUNK(acc1, 128, ns1);

    // --- masked softmax (rows rowA, rowB in 0..127) ---
    int rowA = 16 * mw + g, rowB = rowA + 8;
    float mx0 = -3.0e38f, mx1 = -3.0e38f;
#pragma unroll
    for (int j = 0; j < 8; j++) {
        float2 bv = *(const float2*)&s_bias[nw * 64 + j * 8 + 2 * t];
        acc0[j][0] += bv.x; acc0[j][1] += bv.y;
        acc0[j][2] += bv.x; acc0[j][3] += bv.y;
        mx0 = fmaxf(mx0, fmaxf(acc0[j][0], acc0[j][1]));
        mx1 = fmaxf(mx1, fmaxf(acc0[j][2], acc0[j][3]));
    }
    if (kpadN > 128) {
#pragma unroll
        for (int j = 0; j < 8; j++) {
            float2 bv = *(const float2*)&s_bias[128 + nw * 64 + j * 8 + 2 * t];
            acc1[j][0] += bv.x; acc1[j][1] += bv.y;
            acc1[j][2] += bv.x; acc1[j][3] += bv.y;
            mx0 = fmaxf(mx0, fmaxf(acc1[j][0], acc1[j][1]));
            mx1 = fmaxf(mx1, fmaxf(acc1[j][2], acc1[j][3]));
        }
    }
    mx0 = fmaxf(mx0, __shfl_xor_sync(0xffffffffu, mx0, 1));
    mx0 = fmaxf(mx0, __shfl_xor_sync(0xffffffffu, mx0, 2));
    mx1 = fmaxf(mx1, __shfl_xor_sync(0xffffffffu, mx1, 1));
    mx1 = fmaxf(mx1, __shfl_xor_sync(0xffffffffu, mx1, 2));
    if (t == 0) {
        s_red[nw * 128 + rowA] = mx0;
        s_red[nw * 128 + rowB] = mx1;
    }
    __syncthreads();
    float M0 = fmaxf(s_red[rowA], s_red[128 + rowA]);
    float M1 = fmaxf(s_red[rowB], s_red[128 + rowB]);
    float s0 = 0.f, s1 = 0.f;
#pragma unroll
    for (int j = 0; j < 8; j++) {
        acc0[j][0] = __expf(acc0[j][0] - M0); s0 += acc0[j][0];
        acc0[j][1] = __expf(acc0[j][1] - M0); s0 += acc0[j][1];
        acc0[j][2] = __expf(acc0[j][2] - M1); s1 += acc0[j][2];
        acc0[j][3] = __expf(acc0[j][3] - M1); s1 += acc0[j][3];
    }
    if (kpadN > 128) {
#pragma unroll
        for (int j = 0; j < 8; j++) {
            acc1[j][0] = __expf(acc1[j][0] - M0); s0 += acc1[j][0];
            acc1[j][1] = __expf(acc1[j][1] - M0); s0 += acc1[j][1];
            acc1[j][2] = __expf(acc1[j][2] - M1); s1 += acc1[j][2];
            acc1[j][3] = __expf(acc1[j][3] - M1); s1 += acc1[j][3];
        }
    }
    s0 += __shfl_xor_sync(0xffffffffu, s0, 1);
    s0 += __shfl_xor_sync(0xffffffffu, s0, 2);
    s1 += __shfl_xor_sync(0xffffffffu, s1, 1);
    s1 += __shfl_xor_sync(0xffffffffu, s1, 2);
    __syncthreads();
    if (t == 0) {
        s_red[256 + nw * 128 + rowA] = s0;
        s_red[256 + nw * 128 + rowB] = s1;
    }
    __syncthreads();
    float inv0 = __fdividef(1.f, s_red[256 + rowA] + s_red[256 + 128 + rowA]);
    float inv1 = __fdividef(1.f, s_red[256 + rowB] + s_red[256 + 128 + rowB]);

    // --- write P (fp16 hi only) over retired Q region ---
    {
        char* ph = smem + SM_PH;
#pragma unroll
        for (int j = 0; j < 8; j++) {
            int col = nw * 64 + j * 8 + 2 * t;
            *(uint32_t*)(ph + rowA * 528 + col * 2) = pack_hi(acc0[j][0] * inv0, acc0[j][1] * inv0);
            *(uint32_t*)(ph + rowB * 528 + col * 2) = pack_hi(acc0[j][2] * inv1, acc0[j][3] * inv1);
        }
        if (kpadN > 128) {
#pragma unroll
            for (int j = 0; j < 8; j++) {
                int col = 128 + nw * 64 + j * 8 + 2 * t;
                *(uint32_t*)(ph + rowA * 528 + col * 2) = pack_hi(acc1[j][0] * inv0, acc1[j][1] * inv0);
                *(uint32_t*)(ph + rowB * 528 + col * 2) = pack_hi(acc1[j][2] * inv1, acc1[j][3] * inv1);
            }
        }
    }
    // --- stage V gathered (hi only, overlays retired K) ---
    {
        uint4 z = make_uint4(0, 0, 0, 0);
        for (int idx = tid; idx < kpadN * 16; idx += 512) {
            int row = idx >> 4, c8 = idx & 15;
            uint4 vh = z;
            if (row < nv) {
                size_t src = boff + (size_t)s_idx[row] * DD + c8 * 8;
                vh = *(const uint4*)(g_Mh + src);
            }
            *(uint4*)(smem + SM_VH + row * 272 + c8 * 16) = vh;
        }
    }
    __syncthreads();

    // --- PV GEMM: 1-term (P hi * V hi), k up to kpadN ---
    int d0 = 64 * nw;
    float o[8][4];
#pragma unroll
    for (int i = 0; i < 8; i++)
#pragma unroll
        for (int j = 0; j < 4; j++) o[i][j] = 0.f;

    int ksteps = kpadN >> 4;
#pragma unroll 1
    for (int ks = 0; ks < ksteps; ks++) {
        int k0 = 16 * ks;
        uint32_t aH[4];
        LDSM_X4(aH, sbase + SM_PH + aRow * 528 + (k0 + halfOff) * 2);
#pragma unroll
        for (int np = 0; np < 4; np++) {
            uint32_t baddr = sbase + SM_VH + (uint32_t)(k0 + (l & 15)) * 272 +
                             (uint32_t)(d0 + 16 * np + halfOff) * 2;
            uint32_t bH[4];
            LDSM_X4T(bH, baddr);
            mma_fp16(o[2 * np],     aH, bH[0], bH[1]);
            mma_fp16(o[2 * np + 1], aH, bH[2], bH[3]);
        }
    }

    float* Ob = O + ((size_t)b * NN + i0) * DD;
#pragma unroll
    for (int nt = 0; nt < 8; nt++) {
        int col = d0 + 8 * nt + 2 * t;
        *(float2*)&Ob[(size_t)rowA * DD + col] = make_float2(o[nt][0], o[nt][1]);
        *(float2*)&Ob[(size_t)rowB * DD + col] = make_float2(o[nt][2], o[nt][3]);
    }
}

// ---------------------------------------------------------------------------
extern "C" void kernel_launch(void* const* d_in, const int* in_sizes, int n_in,
                              void* d_out, int out_size) {
    (void)in_sizes; (void)n_in; (void)out_size;
    const float* mirror    = (const float*)d_in[0];
    const float* satellite = (const float*)d_in[1];
    const void*  mask      = d_in[2];
    const float* Wq1 = (const float*)d_in[3];
    const float* Wk1 = (const float*)d_in[4];
    const float* Wq2 = (const float*)d_in[5];
    const float* Wk2 = (const float*)d_in[6];
    float* sat_out = (float*)d_out;
    float* mir_out = (float*)d_out + BND;

    cudaFuncSetAttribute(gemm_T_fused,    cudaFuncAttributeMaxDynamicSharedMemorySize, GT_SMEM);
    cudaFuncSetAttribute(gemm_K2C_kernel, cudaFuncAttributeMaxDynamicSharedMemorySize, GK_SMEM);
    cudaFuncSetAttribute(attn_kernel,     cudaFuncAttributeMaxDynamicSharedMemorySize, SMEM_ATTN);

    detect_mask_kernel<<<1, 256>>>((const unsigned int*)mask);
    decode_compact_kernel<<<BB, 256>>>(mask);
    prep_w_kernel<<<dim3(128, 2), 512>>>(Wq1, Wk1, Wq2, Wk2);

    gemm_T_fused<<<296, 256, GT_SMEM>>>(mirror, satellite, sat_out);
    gemm_K2C_kernel<<<296, 256, GK_SMEM>>>();
    attn_kernel<<<dim3(NN / 128, BB), 512, SMEM_ATTN>>>(mir_out);
}

// round 13
// speedup vs baseline: 1.5725x; 1.0660x over previous
#include <cuda_runtime.h>
#include <cuda_fp16.h>
#include <cstdint>

// Problem constants
#define BB 512
#define NN 256
#define DD 128
#define BND ((size_t)BB * NN * DD)

static __device__ __half g_W1h[DD * DD];
static __device__ __half g_W2h[DD * DD], g_W2l[DD * DD];
static __device__ __half g_Mh[BND];                  // mirror hi
static __device__ __half g_Sh[BND];                  // sat_out hi
static __device__ __half g_Kh[BND], g_Kl[BND];       // K2C split (COMPACT rows)
static __device__ int g_idx[BB * NN];                // compact pos -> j
static __device__ int g_nv[BB];                      // valid count per batch
static __device__ int g_mwidth1;

#define SCALE 0.08838834764831845f  // 1/sqrt(128)

// ============================ PTX helpers ==================================
__device__ __forceinline__ uint32_t smem_u32(const void* p) {
    uint32_t a;
    asm("{ .reg .u64 t; cvta.to.shared.u64 t, %1; cvt.u32.u64 %0, t; }" : "=r"(a) : "l"(p));
    return a;
}

#define LDSM_X4(r, a) \
    asm volatile("ldmatrix.sync.aligned.m8n8.x4.shared.b16 {%0,%1,%2,%3}, [%4];" \
        : "=r"((r)[0]), "=r"((r)[1]), "=r"((r)[2]), "=r"((r)[3]) : "r"(a))
#define LDSM_X4T(r, a) \
    asm volatile("ldmatrix.sync.aligned.m8n8.x4.trans.shared.b16 {%0,%1,%2,%3}, [%4];" \
        : "=r"((r)[0]), "=r"((r)[1]), "=r"((r)[2]), "=r"((r)[3]) : "r"(a))

__device__ __forceinline__ void mma_fp16(float* c, const uint32_t* a, uint32_t b0, uint32_t b1) {
    asm volatile(
        "mma.sync.aligned.m16n8k16.row.col.f32.f16.f16.f32 "
        "{%0,%1,%2,%3}, {%4,%5,%6,%7}, {%8,%9}, {%0,%1,%2,%3};"
        : "+f"(c[0]), "+f"(c[1]), "+f"(c[2]), "+f"(c[3])
        : "r"(a[0]), "r"(a[1]), "r"(a[2]), "r"(a[3]), "r"(b0), "r"(b1));
}

__device__ __forceinline__ void split_pack(float x, float y, uint32_t& h, uint32_t& l) {
    __half hx = __float2half(x);
    __half hy = __float2half(y);
    __half lx = __float2half(x - __half2float(hx));
    __half ly = __float2half(y - __half2float(hy));
    __half2 hh; hh.x = hx; hh.y = hy;
    __half2 ll; ll.x = lx; ll.y = ly;
    h = *(uint32_t*)&hh;
    l = *(uint32_t*)&ll;
}

__device__ __forceinline__ uint32_t pack_hi(float x, float y) {
    __half2 hh; hh.x = __float2half(x); hh.y = __float2half(y);
    return *(uint32_t*)&hh;
}

// ======================= mask canonicalization + compaction ================
__global__ void detect_mask_kernel(const unsigned int* __restrict__ m) {
    __shared__ int red[256];
    int tid = threadIdx.x;
    int p = 0;
    for (int i = tid; i < (BB * NN) / 4; i += 256) {
        unsigned int w = m[i];
        if (w != 0u && w != 1u && w != 0x3F800000u) p = 1;
    }
    red[tid] = p;
    __syncthreads();
    for (int s = 128; s > 0; s >>= 1) {
        if (tid < s) red[tid] |= red[tid + s];
        __syncthreads();
    }
    if (tid == 0) g_mwidth1 = red[0];
}

__global__ void decode_compact_kernel(const void* __restrict__ m) {
    int b = blockIdx.x;
    int tid = threadIdx.x;
    int w = tid >> 5, l = tid & 31;
    __shared__ int wcnt[8], woff[8];
    int i = b * NN + tid;
    int valid;
    if (g_mwidth1) valid = (((const unsigned char*)m)[i] != 0);
    else           valid = (((const unsigned int*)m)[i] != 0u);
    unsigned bal = __ballot_sync(0xffffffffu, valid);
    int pre = __popc(bal & ((1u << l) - 1u));
    if (l == 31) wcnt[w] = __popc(bal);
    g_idx[i] = 0;   // prefill pads with a safe (valid) index
    __syncthreads();
    if (tid == 0) {
        int s = 0;
        for (int k = 0; k < 8; k++) { woff[k] = s; s += wcnt[k]; }
        g_nv[b] = s;
    }
    __syncthreads();
    if (valid) g_idx[b * NN + woff[w] + pre] = tid;
}

// ======================= weight contraction (scaled + split) ===============
__global__ void prep_w_kernel(const float* __restrict__ Wq1, const float* __restrict__ Wk1,
                              const float* __restrict__ Wq2, const float* __restrict__ Wk2) {
    int a = blockIdx.x;
    int c = threadIdx.x & 127, kc = threadIdx.x >> 7;
    __shared__ float red[512];
    const float* X = (blockIdx.y == 0) ? Wq1 : Wq2;
    const float* Y = (blockIdx.y == 0) ? Wk1 : Wk2;
    float acc = 0.f;
#pragma unroll 8
    for (int k = kc * 32; k < kc * 32 + 32; k++)
        acc = fmaf(X[k * DD + c], Y[k * DD + a], acc);
    red[kc * 128 + c] = acc;
    __syncthreads();
    if (kc == 0) {
        float v = (red[c] + red[128 + c]) + (red[256 + c] + red[384 + c]);
        v *= SCALE;
        __half h = __float2half(v);
        __half lo = __float2half(v - __half2float(h));
        int idx = a * DD + c;
        if (blockIdx.y == 0) { g_W1h[idx] = h; }
        else                 { g_W2h[idx] = h; g_W2l[idx] = lo; }
    }
}

// ======================= fused: M convert + T GEMM + gate + sat_out ========
// Persistent: 296 CTAs (2/SM) stage W1h ONCE, then stride over 2048 64-row
// tiles.  T = Mh @ W1h (1-term); alpha = rowdot(S,T); emits sat_out fp32 +
// hi split (g_Sh), and M hi (g_Mh, needed by attn) as a side product.
#define GT_A    0
#define GT_WH   17408
#define GT_SMEM 52224

__global__ __launch_bounds__(256, 2)
void gemm_T_fused(const float* __restrict__ M, const float* __restrict__ S,
                  float* __restrict__ SO) {
    extern __shared__ char smem[];
    __shared__ float s_red[128];
    uint32_t sbase = smem_u32(smem);
    int tid = threadIdx.x;
    int w = tid >> 5, l = tid & 31;

    // stage W1h ONCE
    for (int idx = tid; idx < 2048; idx += 256) {
        int row = idx >> 4, c8 = idx & 15;
        *(uint4*)(smem + GT_WH + row * 272 + c8 * 16) =
            *(const uint4*)(g_W1h + row * DD + c8 * 8);
    }

    int mw = w & 3, nwp = w >> 2;
    int r0 = mw * 16, c0 = nwp * 64;
    int g = l >> 2, t = l & 3;
    uint32_t halfOff = (uint32_t)((l >> 4) << 3);

    for (int item = blockIdx.x; item < 2048; item += gridDim.x) {
        size_t n0 = (size_t)item * 64;

        // convert M rows: fp32 -> fp16 hi (global) + Mh smem tile
        for (int idx = tid; idx < 4096; idx += 256) {
            int row = idx >> 6, c2 = idx & 63;
            float2 v = ((const float2*)(M + (n0 + row) * DD))[c2];
            uint32_t h = pack_hi(v.x, v.y);
            ((uint32_t*)(g_Mh + (n0 + row) * DD))[c2] = h;
            *(uint32_t*)(smem + GT_A + row * 272 + c2 * 4) = h;
        }
        __syncthreads();

        float acc[8][4];
#pragma unroll
        for (int j = 0; j < 8; j++)
#pragma unroll
            for (int q = 0; q < 4; q++) acc[j][q] = 0.f;

#pragma unroll 1
        for (int ks = 0; ks < 8; ks++) {
            int k0 = 16 * ks;
            uint32_t aH[4];
            LDSM_X4(aH, sbase + GT_A + (r0 + (l & 15)) * 272 + (k0 + halfOff) * 2);
#pragma unroll
            for (int np = 0; np < 4; np++) {
                uint32_t baddr = sbase + GT_WH + (uint32_t)(k0 + (l & 15)) * 272 +
                                 (uint32_t)(c0 + 16 * np + halfOff) * 2;
                uint32_t bH[4];
                LDSM_X4T(bH, baddr);
                mma_fp16(acc[2 * np],     aH, bH[0], bH[1]);
                mma_fp16(acc[2 * np + 1], aH, bH[2], bH[3]);
            }
        }

        // --- epilogue: alpha = rowdot(S, T), then sat_out + hi split ---
        int rowA = r0 + g, rowB = rowA + 8;
        float p0 = 0.f, p1 = 0.f;
        {
            size_t rA = n0 + rowA, rB = n0 + rowB;
#pragma unroll
            for (int nt = 0; nt < 8; nt++) {
                int col = c0 + nt * 8 + 2 * t;
                float2 sa = *(const float2*)(S + rA * DD + col);
                float2 sb = *(const float2*)(S + rB * DD + col);
                p0 += sa.x * acc[nt][0] + sa.y * acc[nt][1];
                p1 += sb.x * acc[nt][2] + sb.y * acc[nt][3];
            }
        }
        p0 += __shfl_xor_sync(0xffffffffu, p0, 1);
        p0 += __shfl_xor_sync(0xffffffffu, p0, 2);
        p1 += __shfl_xor_sync(0xffffffffu, p1, 1);
        p1 += __shfl_xor_sync(0xffffffffu, p1, 2);
        if (t == 0) {
            s_red[nwp * 64 + rowA] = p0;
            s_red[nwp * 64 + rowB] = p1;
        }
        __syncthreads();

        float alA = s_red[rowA] + s_red[64 + rowA];
        float alB = s_red[rowB] + s_red[64 + rowB];
        size_t rA = n0 + rowA, rB = n0 + rowB;
#pragma unroll
        for (int nt = 0; nt < 8; nt++) {
            int col = c0 + nt * 8 + 2 * t;
            float2 sa = *(const float2*)(S + rA * DD + col);
            float2 ma = *(const float2*)(M + rA * DD + col);
            float2 oa;
            oa.x = fmaf(alA, ma.x - sa.x, sa.x);
            oa.y = fmaf(alA, ma.y - sa.y, sa.y);
            *(float2*)(SO + rA * DD + col) = oa;
            *(uint32_t*)(g_Sh + rA * DD + col) = pack_hi(oa.x, oa.y);

            float2 sb = *(const float2*)(S + rB * DD + col);
            float2 mb = *(const float2*)(M + rB * DD + col);
            float2 ob;
            ob.x = fmaf(alB, mb.x - sb.x, sb.x);
            ob.y = fmaf(alB, mb.y - sb.y, sb.y);
            *(float2*)(SO + rB * DD + col) = ob;
            *(uint32_t*)(g_Sh + rB * DD + col) = pack_hi(ob.x, ob.y);
        }
        __syncthreads();   // iter-n reads done before iter-n+1 staging
    }
}

// ======================= K2C GEMM (2-term, gathered, compact out) ==========
// K2C = Sh @ (W2h + W2l).  Persistent: 296 CTAs stage W2 ONCE, then stride
// over (b, 64-row-quadrant) items with uniform early skip of padding tiles.
#define GK_A    0
#define GK_WH   17408
#define GK_WL   52224
#define GK_SMEM 87040

__global__ __launch_bounds__(256, 2)
void gemm_K2C_kernel() {
    extern __shared__ char smem[];
    uint32_t sbase = smem_u32(smem);
    int tid = threadIdx.x;
    int w = tid >> 5, l = tid & 31;

    // stage W2 split ONCE
    for (int idx = tid; idx < 2048; idx += 256) {
        int row = idx >> 4, c8 = idx & 15;
        *(uint4*)(smem + GK_WH + row * 272 + c8 * 16) = *(const uint4*)(g_W2h + row * DD + c8 * 8);
        *(uint4*)(smem + GK_WL + row * 272 + c8 * 16) = *(const uint4*)(g_W2l + row * DD + c8 * 8);
    }
    __syncthreads();

    int mw = w & 3, nwp = w >> 2;
    int r0 = mw * 16, c0 = nwp * 64;
    int g = l >> 2, t = l & 3;
    uint32_t halfOff = (uint32_t)((l >> 4) << 3);

    for (int item = blockIdx.x; item < BB * 4; item += gridDim.x) {
        int b = item >> 2;
        int pos0 = (item & 3) * 64;
        if (pos0 >= g_nv[b]) continue;   // uniform across block

        for (int idx = tid; idx < 1024; idx += 256) {
            int row = idx >> 4, c8 = idx & 15;
            int j = g_idx[b * NN + pos0 + row];
            size_t srow = ((size_t)b * NN + j) * DD;
            *(uint4*)(smem + GK_A + row * 272 + c8 * 16) = *(const uint4*)(g_Sh + srow + c8 * 8);
        }
        __syncthreads();

        float acc[8][4];
#pragma unroll
        for (int j = 0; j < 8; j++)
#pragma unroll
            for (int q = 0; q < 4; q++) acc[j][q] = 0.f;

#pragma unroll 1
        for (int ks = 0; ks < 8; ks++) {
            int k0 = 16 * ks;
            uint32_t aH[4];
            LDSM_X4(aH, sbase + GK_A + (r0 + (l & 15)) * 272 + (k0 + halfOff) * 2);
#pragma unroll
            for (int np = 0; np < 4; np++) {
                uint32_t baddr = sbase + GK_WH + (uint32_t)(k0 + (l & 15)) * 272 +
                                 (uint32_t)(c0 + 16 * np + halfOff) * 2;
                uint32_t bH[4], bL[4];
                LDSM_X4T(bH, baddr);
                LDSM_X4T(bL, baddr + (GK_WL - GK_WH));
                mma_fp16(acc[2 * np],     aH, bH[0], bH[1]);
                mma_fp16(acc[2 * np],     aH, bL[0], bL[1]);
                mma_fp16(acc[2 * np + 1], aH, bH[2], bH[3]);
                mma_fp16(acc[2 * np + 1], aH, bL[2], bL[3]);
            }
        }

#pragma unroll
        for (int nt = 0; nt < 8; nt++) {
            size_t rowA = (size_t)b * NN + pos0 + r0 + g;
            size_t rowB = rowA + 8;
            int col = c0 + nt * 8 + 2 * t;
            uint32_t h, lo;
            split_pack(acc[nt][0], acc[nt][1], h, lo);
            *(uint32_t*)(g_Kh + rowA * DD + col) = h;
            *(uint32_t*)(g_Kl + rowA * DD + col) = lo;
            split_pack(acc[nt][2], acc[nt][3], h, lo);
            *(uint32_t*)(g_Kh + rowB * DD + col) = h;
            *(uint32_t*)(g_Kl + rowB * DD + col) = lo;
        }
        __syncthreads();   // MMA reads done before next iter staging
    }
}

// ======================= fused attention (compacted keys) ==================
// CTA = (batch b, 128 i-rows).  512 threads = 16 warps: 8 m-warps x 2 n-warps.
// beta phase: Q hi [0,34816), K hi [34816,104448), K lo [104448,174080).
// PV phase:   P (528-stride) [0,67584) over dead Q + K-head,
//             V hi [69632,139264) over dead K tail.
#define SM_QH  0
#define SM_KH  34816
#define SM_KL  104448
#define SM_PH  0
#define SM_VH  69632
#define SMEM_ATTN 174080

#define BETA_CHUNK(ACC, CBASE, NSTEPS) do {                                         \
    _Pragma("unroll")                                                               \
    for (int ks = 0; ks < 8; ks++) {                                                \
        int k0 = 16 * ks;                                                           \
        uint32_t aH[4];                                                             \
        LDSM_X4(aH, sbase + SM_QH + aRow * 272 + (k0 + halfOff) * 2);               \
        _Pragma("unroll")                                                           \
        for (int np = 0; np < 4; np++) {                                            \
            if (np >= (NSTEPS)) break;                                              \
            uint32_t baddr = sbase + SM_KH +                                        \
                (uint32_t)((CBASE) + nw * 64 + 16 * np + bRowBase) * 272 +          \
                (k0 + bColHalf) * 2;                                                \
            uint32_t bH[4], bL[4];                                                  \
            LDSM_X4(bH, baddr);                                                     \
            LDSM_X4(bL, baddr + (SM_KL - SM_KH));                                   \
            mma_fp16(ACC[2 * np],     aH, bH[0], bH[1]);                            \
            mma_fp16(ACC[2 * np],     aH, bL[0], bL[1]);                            \
            mma_fp16(ACC[2 * np + 1], aH, bH[2], bH[3]);                            \
            mma_fp16(ACC[2 * np + 1], aH, bL[2], bL[3]);                            \
        }                                                                           \
    }                                                                               \
} while (0)

__global__ __launch_bounds__(512, 1)
void attn_kernel(float* __restrict__ O) {
    extern __shared__ char smem[];
    __shared__ float s_bias[256];
    __shared__ float s_red[512];
    __shared__ int s_idx[256];
    uint32_t sbase = smem_u32(smem);

    int tid = threadIdx.x;
    int w = tid >> 5, l = tid & 31;
    int g = l >> 2, t = l & 3;
    int mw = w & 7, nw = w >> 3;
    int b = blockIdx.y;
    int i0 = blockIdx.x * 128;
    size_t boff = (size_t)b * NN * DD;

    int nv = g_nv[b];
    int kpadN = (nv + 15) & ~15;

    if (tid < 256) {
        s_idx[tid] = g_idx[b * NN + tid];
        s_bias[tid] = (tid < nv) ? 0.f : -1e30f;
    }

    // stage Q hi (128 rows of M)
    for (int idx = tid; idx < 128 * 16; idx += 512) {
        int row = idx >> 4, c8 = idx & 15;
        size_t src = boff + (size_t)(i0 + row) * DD + c8 * 8;
        *(uint4*)(smem + SM_QH + row * 272 + c8 * 16) = *(const uint4*)(g_Mh + src);
    }
    // stage K compact rows [0, kpadN) (zero pads)
    {
        uint4 z = make_uint4(0, 0, 0, 0);
        for (int idx = tid; idx < kpadN * 16; idx += 512) {
            int row = idx >> 4, c8 = idx & 15;
            uint4 vh = z, vl = z;
            if (row < nv) {
                size_t src = boff + (size_t)row * DD + c8 * 8;
                vh = *(const uint4*)(g_Kh + src);
                vl = *(const uint4*)(g_Kl + src);
            }
            *(uint4*)(smem + SM_KH + row * 272 + c8 * 16) = vh;
            *(uint4*)(smem + SM_KL + row * 272 + c8 * 16) = vl;
        }
    }
    __syncthreads();

    // --- beta GEMM over valid 16-col tiles only (2-term: Qh*(Kh+Kl)) ---
    uint32_t aRow = (uint32_t)(16 * mw + (l & 15));
    uint32_t halfOff = (uint32_t)((l >> 4) << 3);
    uint32_t bRowBase = (uint32_t)(((l >> 4) << 3) + (l & 7));
    uint32_t bColHalf = (uint32_t)(((l >> 3) & 1) << 3);

    int base0 = nw * 64, base1 = 128 + nw * 64;
    int ns0 = min(4, max(0, (kpadN - base0) >> 4));
    int ns1 = min(4, max(0, (kpadN - base1) >> 4));

    float acc0[8][4], acc1[8][4];
#pragma unroll
    for (int j = 0; j < 8; j++)
#pragma unroll
        for (int q = 0; q < 4; q++) { acc0[j][q] = 0.f; acc1[j][q] = 0.f; }

    if (ns0 > 0) BETA_CHUNK(acc0, 0, ns0);
    if (ns1 > 0) BETA_CHUNK(acc1, 128, ns1);

    // --- masked softmax (rows rowA, rowB in 0..127) ---
    int rowA = 16 * mw + g, rowB = rowA + 8;
    float mx0 = -3.0e38f, mx1 = -3.0e38f;
#pragma unroll
    for (int j = 0; j < 8; j++) {
        float2 bv = *(const float2*)&s_bias[nw * 64 + j * 8 + 2 * t];
        acc0[j][0] += bv.x; acc0[j][1] += bv.y;
        acc0[j][2] += bv.x; acc0[j][3] += bv.y;
        mx0 = fmaxf(mx0, fmaxf(acc0[j][0], acc0[j][1]));
        mx1 = fmaxf(mx1, fmaxf(acc0[j][2], acc0[j][3]));
    }
    if (kpadN > 128) {
#pragma unroll
        for (int j = 0; j < 8; j++) {
            float2 bv = *(const float2*)&s_bias[128 + nw * 64 + j * 8 + 2 * t];
            acc1[j][0] += bv.x; acc1[j][1] += bv.y;
            acc1[j][2] += bv.x; acc1[j][3] += bv.y;
            mx0 = fmaxf(mx0, fmaxf(acc1[j][0], acc1[j][1]));
            mx1 = fmaxf(mx1, fmaxf(acc1[j][2], acc1[j][3]));
        }
    }
    mx0 = fmaxf(mx0, __shfl_xor_sync(0xffffffffu, mx0, 1));
    mx0 = fmaxf(mx0, __shfl_xor_sync(0xffffffffu, mx0, 2));
    mx1 = fmaxf(mx1, __shfl_xor_sync(0xffffffffu, mx1, 1));
    mx1 = fmaxf(mx1, __shfl_xor_sync(0xffffffffu, mx1, 2));
    if (t == 0) {
        s_red[nw * 128 + rowA] = mx0;
        s_red[nw * 128 + rowB] = mx1;
    }
    __syncthreads();
    float M0 = fmaxf(s_red[rowA], s_red[128 + rowA]);
    float M1 = fmaxf(s_red[rowB], s_red[128 + rowB]);
    float s0 = 0.f, s1 = 0.f;
#pragma unroll
    for (int j = 0; j < 8; j++) {
        acc0[j][0] = __expf(acc0[j][0] - M0); s0 += acc0[j][0];
        acc0[j][1] = __expf(acc0[j][1] - M0); s0 += acc0[j][1];
        acc0[j][2] = __expf(acc0[j][2] - M1); s1 += acc0[j][2];
        acc0[j][3] = __expf(acc0[j][3] - M1); s1 += acc0[j][3];
    }
    if (kpadN > 128) {
#pragma unroll
        for (int j = 0; j < 8; j++) {
            acc1[j][0] = __expf(acc1[j][0] - M0); s0 += acc1[j][0];
            acc1[j][1] = __expf(acc1[j][1] - M0); s0 += acc1[j][1];
            acc1[j][2] = __expf(acc1[j][2] - M1); s1 += acc1[j][2];
            acc1[j][3] = __expf(acc1[j][3] - M1); s1 += acc1[j][3];
        }
    }
    s0 += __shfl_xor_sync(0xffffffffu, s0, 1);
    s0 += __shfl_xor_sync(0xffffffffu, s0, 2);
    s1 += __shfl_xor_sync(0xffffffffu, s1, 1);
    s1 += __shfl_xor_sync(0xffffffffu, s1, 2);
    __syncthreads();
    if (t == 0) {
        s_red[256 + nw * 128 + rowA] = s0;
        s_red[256 + nw * 128 + rowB] = s1;
    }
    __syncthreads();
    float inv0 = __fdividef(1.f, s_red[256 + rowA] + s_red[256 + 128 + rowA]);
    float inv1 = __fdividef(1.f, s_red[256 + rowB] + s_red[256 + 128 + rowB]);

    // --- write P (fp16 hi only) over dead Q + K-head region ---
    {
        char* ph = smem + SM_PH;
#pragma unroll
        for (int j = 0; j < 8; j++) {
            int col = nw * 64 + j * 8 + 2 * t;
            *(uint32_t*)(ph + rowA * 528 + col * 2) = pack_hi(acc0[j][0] * inv0, acc0[j][1] * inv0);
            *(uint32_t*)(ph + rowB * 528 + col * 2) = pack_hi(acc0[j][2] * inv1, acc0[j][3] * inv1);
        }
        if (kpadN > 128) {
#pragma unroll
            for (int j = 0; j < 8; j++) {
                int col = 128 + nw * 64 + j * 8 + 2 * t;
                *(uint32_t*)(ph + rowA * 528 + col * 2) = pack_hi(acc1[j][0] * inv0, acc1[j][1] * inv0);
                *(uint32_t*)(ph + rowB * 528 + col * 2) = pack_hi(acc1[j][2] * inv1, acc1[j][3] * inv1);
            }
        }
    }
    // --- stage V gathered (hi only, over dead K tail) ---
    {
        uint4 z = make_uint4(0, 0, 0, 0);
        for (int idx = tid; idx < kpadN * 16; idx += 512) {
            int row = idx >> 4, c8 = idx & 15;
            uint4 vh = z;
            if (row < nv) {
                size_t src = boff + (size_t)s_idx[row] * DD + c8 * 8;
                vh = *(const uint4*)(g_Mh + src);
            }
            *(uint4*)(smem + SM_VH + row * 272 + c8 * 16) = vh;
        }
    }
    __syncthreads();

    // --- PV GEMM: 1-term (P hi * V hi), k up to kpadN ---
    int d0 = 64 * nw;
    float o[8][4];
#pragma unroll
    for (int i = 0; i < 8; i++)
#pragma unroll
        for (int j = 0; j < 4; j++) o[i][j] = 0.f;

    int ksteps = kpadN >> 4;
#pragma unroll 1
    for (int ks = 0; ks < ksteps; ks++) {
        int k0 = 16 * ks;
        uint32_t aH[4];
        LDSM_X4(aH, sbase + SM_PH + aRow * 528 + (k0 + halfOff) * 2);
#pragma unroll
        for (int np = 0; np < 4; np++) {
            uint32_t baddr = sbase + SM_VH + (uint32_t)(k0 + (l & 15)) * 272 +
                             (uint32_t)(d0 + 16 * np + halfOff) * 2;
            uint32_t bH[4];
            LDSM_X4T(bH, baddr);
            mma_fp16(o[2 * np],     aH, bH[0], bH[1]);
            mma_fp16(o[2 * np + 1], aH, bH[2], bH[3]);
        }
    }

    float* Ob = O + ((size_t)b * NN + i0) * DD;
#pragma unroll
    for (int nt = 0; nt < 8; nt++) {
        int col = d0 + 8 * nt + 2 * t;
        *(float2*)&Ob[(size_t)rowA * DD + col] = make_float2(o[nt][0], o[nt][1]);
        *(float2*)&Ob[(size_t)rowB * DD + col] = make_float2(o[nt][2], o[nt][3]);
    }
}

// ---------------------------------------------------------------------------
extern "C" void kernel_launch(void* const* d_in, const int* in_sizes, int n_in,
                              void* d_out, int out_size) {
    (void)in_sizes; (void)n_in; (void)out_size;
    const float* mirror    = (const float*)d_in[0];
    const float* satellite = (const float*)d_in[1];
    const void*  mask      = d_in[2];
    const float* Wq1 = (const float*)d_in[3];
    const float* Wk1 = (const float*)d_in[4];
    const float* Wq2 = (const float*)d_in[5];
    const float* Wk2 = (const float*)d_in[6];
    float* sat_out = (float*)d_out;
    float* mir_out = (float*)d_out + BND;

    cudaFuncSetAttribute(gemm_T_fused,    cudaFuncAttributeMaxDynamicSharedMemorySize, GT_SMEM);
    cudaFuncSetAttribute(gemm_K2C_kernel, cudaFuncAttributeMaxDynamicSharedMemorySize, GK_SMEM);
    cudaFuncSetAttribute(attn_kernel,     cudaFuncAttributeMaxDynamicSharedMemorySize, SMEM_ATTN);

    detect_mask_kernel<<<1, 256>>>((const unsigned int*)mask);
    decode_compact_kernel<<<BB, 256>>>(mask);
    prep_w_kernel<<<dim3(128, 2), 512>>>(Wq1, Wk1, Wq2, Wk2);

    gemm_T_fused<<<296, 256, GT_SMEM>>>(mirror, satellite, sat_out);
    gemm_K2C_kernel<<<296, 256, GK_SMEM>>>();
    attn_kernel<<<dim3(NN / 128, BB), 512, SMEM_ATTN>>>(mir_out);
}

// round 14
// speedup vs baseline: 1.5910x; 1.0118x over previous
#include <cuda_runtime.h>
#include <cuda_fp16.h>
#include <cstdint>

// Problem constants
#define BB 512
#define NN 256
#define DD 128
#define BND ((size_t)BB * NN * DD)

static __device__ __half g_W1h[DD * DD];
static __device__ __half g_W2h[DD * DD], g_W2l[DD * DD];
static __device__ __half g_Mh[BND];                  // mirror hi
static __device__ __half g_Sh[BND];                  // sat_out hi
static __device__ __half g_Kh[BND], g_Kl[BND];       // K2C split (COMPACT rows)
static __device__ int g_idx[BB * NN];                // compact pos -> j
static __device__ int g_nv[BB];                      // valid count per batch
static __device__ int g_mwidth1;

#define SCALE 0.08838834764831845f  // 1/sqrt(128)

// ============================ PTX helpers ==================================
__device__ __forceinline__ uint32_t smem_u32(const void* p) {
    uint32_t a;
    asm("{ .reg .u64 t; cvta.to.shared.u64 t, %1; cvt.u32.u64 %0, t; }" : "=r"(a) : "l"(p));
    return a;
}

#define LDSM_X4(r, a) \
    asm volatile("ldmatrix.sync.aligned.m8n8.x4.shared.b16 {%0,%1,%2,%3}, [%4];" \
        : "=r"((r)[0]), "=r"((r)[1]), "=r"((r)[2]), "=r"((r)[3]) : "r"(a))
#define LDSM_X4T(r, a) \
    asm volatile("ldmatrix.sync.aligned.m8n8.x4.trans.shared.b16 {%0,%1,%2,%3}, [%4];" \
        : "=r"((r)[0]), "=r"((r)[1]), "=r"((r)[2]), "=r"((r)[3]) : "r"(a))

__device__ __forceinline__ void mma_fp16(float* c, const uint32_t* a, uint32_t b0, uint32_t b1) {
    asm volatile(
        "mma.sync.aligned.m16n8k16.row.col.f32.f16.f16.f32 "
        "{%0,%1,%2,%3}, {%4,%5,%6,%7}, {%8,%9}, {%0,%1,%2,%3};"
        : "+f"(c[0]), "+f"(c[1]), "+f"(c[2]), "+f"(c[3])
        : "r"(a[0]), "r"(a[1]), "r"(a[2]), "r"(a[3]), "r"(b0), "r"(b1));
}

__device__ __forceinline__ void split_pack(float x, float y, uint32_t& h, uint32_t& l) {
    __half hx = __float2half(x);
    __half hy = __float2half(y);
    __half lx = __float2half(x - __half2float(hx));
    __half ly = __float2half(y - __half2float(hy));
    __half2 hh; hh.x = hx; hh.y = hy;
    __half2 ll; ll.x = lx; ll.y = ly;
    h = *(uint32_t*)&hh;
    l = *(uint32_t*)&ll;
}

__device__ __forceinline__ uint32_t pack_hi(float x, float y) {
    __half2 hh; hh.x = __float2half(x); hh.y = __float2half(y);
    return *(uint32_t*)&hh;
}

// ======================= mask canonicalization + compaction ================
__global__ void detect_mask_kernel(const unsigned int* __restrict__ m) {
    __shared__ int red[256];
    int tid = threadIdx.x;
    int p = 0;
    for (int i = tid; i < (BB * NN) / 4; i += 256) {
        unsigned int w = m[i];
        if (w != 0u && w != 1u && w != 0x3F800000u) p = 1;
    }
    red[tid] = p;
    __syncthreads();
    for (int s = 128; s > 0; s >>= 1) {
        if (tid < s) red[tid] |= red[tid + s];
        __syncthreads();
    }
    if (tid == 0) g_mwidth1 = red[0];
}

__global__ void decode_compact_kernel(const void* __restrict__ m) {
    int b = blockIdx.x;
    int tid = threadIdx.x;
    int w = tid >> 5, l = tid & 31;
    __shared__ int wcnt[8], woff[8];
    int i = b * NN + tid;
    int valid;
    if (g_mwidth1) valid = (((const unsigned char*)m)[i] != 0);
    else           valid = (((const unsigned int*)m)[i] != 0u);
    unsigned bal = __ballot_sync(0xffffffffu, valid);
    int pre = __popc(bal & ((1u << l) - 1u));
    if (l == 31) wcnt[w] = __popc(bal);
    g_idx[i] = 0;   // prefill pads with a safe (valid) index
    __syncthreads();
    if (tid == 0) {
        int s = 0;
        for (int k = 0; k < 8; k++) { woff[k] = s; s += wcnt[k]; }
        g_nv[b] = s;
    }
    __syncthreads();
    if (valid) g_idx[b * NN + woff[w] + pre] = tid;
}

// ======================= weight contraction (scaled + split) ===============
__global__ void prep_w_kernel(const float* __restrict__ Wq1, const float* __restrict__ Wk1,
                              const float* __restrict__ Wq2, const float* __restrict__ Wk2) {
    int a = blockIdx.x;
    int c = threadIdx.x & 127, kc = threadIdx.x >> 7;
    __shared__ float red[512];
    const float* X = (blockIdx.y == 0) ? Wq1 : Wq2;
    const float* Y = (blockIdx.y == 0) ? Wk1 : Wk2;
    float acc = 0.f;
#pragma unroll 8
    for (int k = kc * 32; k < kc * 32 + 32; k++)
        acc = fmaf(X[k * DD + c], Y[k * DD + a], acc);
    red[kc * 128 + c] = acc;
    __syncthreads();
    if (kc == 0) {
        float v = (red[c] + red[128 + c]) + (red[256 + c] + red[384 + c]);
        v *= SCALE;
        __half h = __float2half(v);
        __half lo = __float2half(v - __half2float(h));
        int idx = a * DD + c;
        if (blockIdx.y == 0) { g_W1h[idx] = h; }
        else                 { g_W2h[idx] = h; g_W2l[idx] = lo; }
    }
}

// ======================= fused: M convert + T GEMM + gate + sat_out ========
// Persistent: 296 CTAs (2/SM) stage W1h ONCE, then stride over 2048 64-row
// tiles.  Staging also caches S (fp32) in smem; the epilogue does ZERO global
// loads (S from smem, M from the fp16 Mh tile).
#define GT_A    0          // Mh tile: 64 x 272 B
#define GT_WH   17408      // W1h: 128 x 272 B
#define GT_S    52224      // S fp32: 64 x 132 floats (528 B rows)
#define GT_SMEM 86016

__global__ __launch_bounds__(256, 2)
void gemm_T_fused(const float* __restrict__ M, const float* __restrict__ S,
                  float* __restrict__ SO) {
    extern __shared__ char smem[];
    __shared__ float s_red[128];
    uint32_t sbase = smem_u32(smem);
    float* sS = (float*)(smem + GT_S);
    int tid = threadIdx.x;
    int w = tid >> 5, l = tid & 31;

    // stage W1h ONCE
    for (int idx = tid; idx < 2048; idx += 256) {
        int row = idx >> 4, c8 = idx & 15;
        *(uint4*)(smem + GT_WH + row * 272 + c8 * 16) =
            *(const uint4*)(g_W1h + row * DD + c8 * 8);
    }

    int mw = w & 3, nwp = w >> 2;
    int r0 = mw * 16, c0 = nwp * 64;
    int g = l >> 2, t = l & 3;
    uint32_t halfOff = (uint32_t)((l >> 4) << 3);

    for (int item = blockIdx.x; item < 2048; item += gridDim.x) {
        size_t n0 = (size_t)item * 64;

        // staging: M fp32 -> fp16 hi (global + smem); S fp32 -> smem
        for (int idx = tid; idx < 4096; idx += 256) {
            int row = idx >> 6, c2 = idx & 63;
            float2 v = ((const float2*)(M + (n0 + row) * DD))[c2];
            uint32_t h = pack_hi(v.x, v.y);
            ((uint32_t*)(g_Mh + (n0 + row) * DD))[c2] = h;
            *(uint32_t*)(smem + GT_A + row * 272 + c2 * 4) = h;
            float2 sv = ((const float2*)(S + (n0 + row) * DD))[c2];
            *(float2*)&sS[row * 132 + c2 * 2] = sv;
        }
        __syncthreads();

        float acc[8][4];
#pragma unroll
        for (int j = 0; j < 8; j++)
#pragma unroll
            for (int q = 0; q < 4; q++) acc[j][q] = 0.f;

#pragma unroll 1
        for (int ks = 0; ks < 8; ks++) {
            int k0 = 16 * ks;
            uint32_t aH[4];
            LDSM_X4(aH, sbase + GT_A + (r0 + (l & 15)) * 272 + (k0 + halfOff) * 2);
#pragma unroll
            for (int np = 0; np < 4; np++) {
                uint32_t baddr = sbase + GT_WH + (uint32_t)(k0 + (l & 15)) * 272 +
                                 (uint32_t)(c0 + 16 * np + halfOff) * 2;
                uint32_t bH[4];
                LDSM_X4T(bH, baddr);
                mma_fp16(acc[2 * np],     aH, bH[0], bH[1]);
                mma_fp16(acc[2 * np + 1], aH, bH[2], bH[3]);
            }
        }

        // --- epilogue: alpha = rowdot(S, T) [smem], sat_out + hi split ---
        int rowA = r0 + g, rowB = rowA + 8;
        float p0 = 0.f, p1 = 0.f;
#pragma unroll
        for (int nt = 0; nt < 8; nt++) {
            int col = c0 + nt * 8 + 2 * t;
            float2 sa = *(const float2*)&sS[rowA * 132 + col];
            float2 sb = *(const float2*)&sS[rowB * 132 + col];
            p0 += sa.x * acc[nt][0] + sa.y * acc[nt][1];
            p1 += sb.x * acc[nt][2] + sb.y * acc[nt][3];
        }
        p0 += __shfl_xor_sync(0xffffffffu, p0, 1);
        p0 += __shfl_xor_sync(0xffffffffu, p0, 2);
        p1 += __shfl_xor_sync(0xffffffffu, p1, 1);
        p1 += __shfl_xor_sync(0xffffffffu, p1, 2);
        if (t == 0) {
            s_red[nwp * 64 + rowA] = p0;
            s_red[nwp * 64 + rowB] = p1;
        }
        __syncthreads();

        float alA = s_red[rowA] + s_red[64 + rowA];
        float alB = s_red[rowB] + s_red[64 + rowB];
        size_t rA = n0 + rowA, rB = n0 + rowB;
#pragma unroll
        for (int nt = 0; nt < 8; nt++) {
            int col = c0 + nt * 8 + 2 * t;
            float2 sa = *(const float2*)&sS[rowA * 132 + col];
            __half2 mh = *(const __half2*)(smem + GT_A + rowA * 272 + col * 2);
            float2 ma = __half22float2(mh);
            float2 oa;
            oa.x = fmaf(alA, ma.x - sa.x, sa.x);
            oa.y = fmaf(alA, ma.y - sa.y, sa.y);
            *(float2*)(SO + rA * DD + col) = oa;
            *(uint32_t*)(g_Sh + rA * DD + col) = pack_hi(oa.x, oa.y);

            float2 sb = *(const float2*)&sS[rowB * 132 + col];
            __half2 mhb = *(const __half2*)(smem + GT_A + rowB * 272 + col * 2);
            float2 mb = __half22float2(mhb);
            float2 ob;
            ob.x = fmaf(alB, mb.x - sb.x, sb.x);
            ob.y = fmaf(alB, mb.y - sb.y, sb.y);
            *(float2*)(SO + rB * DD + col) = ob;
            *(uint32_t*)(g_Sh + rB * DD + col) = pack_hi(ob.x, ob.y);
        }
        __syncthreads();   // iter-n reads done before iter-n+1 staging
    }
}

// ======================= K2C GEMM (2-term, gathered, compact out) ==========
// K2C = Sh @ (W2h + W2l).  Persistent: 296 CTAs stage W2 ONCE, then stride
// over (b, 64-row-quadrant) items with uniform early skip of padding tiles.
#define GK_A    0
#define GK_WH   17408
#define GK_WL   52224
#define GK_SMEM 87040

__global__ __launch_bounds__(256, 2)
void gemm_K2C_kernel() {
    extern __shared__ char smem[];
    uint32_t sbase = smem_u32(smem);
    int tid = threadIdx.x;
    int w = tid >> 5, l = tid & 31;

    // stage W2 split ONCE
    for (int idx = tid; idx < 2048; idx += 256) {
        int row = idx >> 4, c8 = idx & 15;
        *(uint4*)(smem + GK_WH + row * 272 + c8 * 16) = *(const uint4*)(g_W2h + row * DD + c8 * 8);
        *(uint4*)(smem + GK_WL + row * 272 + c8 * 16) = *(const uint4*)(g_W2l + row * DD + c8 * 8);
    }
    __syncthreads();

    int mw = w & 3, nwp = w >> 2;
    int r0 = mw * 16, c0 = nwp * 64;
    int g = l >> 2, t = l & 3;
    uint32_t halfOff = (uint32_t)((l >> 4) << 3);

    for (int item = blockIdx.x; item < BB * 4; item += gridDim.x) {
        int b = item >> 2;
        int pos0 = (item & 3) * 64;
        if (pos0 >= g_nv[b]) continue;   // uniform across block

        for (int idx = tid; idx < 1024; idx += 256) {
            int row = idx >> 4, c8 = idx & 15;
            int j = g_idx[b * NN + pos0 + row];
            size_t srow = ((size_t)b * NN + j) * DD;
            *(uint4*)(smem + GK_A + row * 272 + c8 * 16) = *(const uint4*)(g_Sh + srow + c8 * 8);
        }
        __syncthreads();

        float acc[8][4];
#pragma unroll
        for (int j = 0; j < 8; j++)
#pragma unroll
            for (int q = 0; q < 4; q++) acc[j][q] = 0.f;

#pragma unroll 1
        for (int ks = 0; ks < 8; ks++) {
            int k0 = 16 * ks;
            uint32_t aH[4];
            LDSM_X4(aH, sbase + GK_A + (r0 + (l & 15)) * 272 + (k0 + halfOff) * 2);
#pragma unroll
            for (int np = 0; np < 4; np++) {
                uint32_t baddr = sbase + GK_WH + (uint32_t)(k0 + (l & 15)) * 272 +
                                 (uint32_t)(c0 + 16 * np + halfOff) * 2;
                uint32_t bH[4], bL[4];
                LDSM_X4T(bH, baddr);
                LDSM_X4T(bL, baddr + (GK_WL - GK_WH));
                mma_fp16(acc[2 * np],     aH, bH[0], bH[1]);
                mma_fp16(acc[2 * np],     aH, bL[0], bL[1]);
                mma_fp16(acc[2 * np + 1], aH, bH[2], bH[3]);
                mma_fp16(acc[2 * np + 1], aH, bL[2], bL[3]);
            }
        }

#pragma unroll
        for (int nt = 0; nt < 8; nt++) {
            size_t rowA = (size_t)b * NN + pos0 + r0 + g;
            size_t rowB = rowA + 8;
            int col = c0 + nt * 8 + 2 * t;
            uint32_t h, lo;
            split_pack(acc[nt][0], acc[nt][1], h, lo);
            *(uint32_t*)(g_Kh + rowA * DD + col) = h;
            *(uint32_t*)(g_Kl + rowA * DD + col) = lo;
            split_pack(acc[nt][2], acc[nt][3], h, lo);
            *(uint32_t*)(g_Kh + rowB * DD + col) = h;
            *(uint32_t*)(g_Kl + rowB * DD + col) = lo;
        }
        __syncthreads();   // MMA reads done before next iter staging
    }
}

// ======================= fused attention (compacted keys) ==================
// CTA = (batch b, 128 i-rows).  512 threads = 16 warps: 8 m-warps x 2 n-warps.
// beta phase: Q hi [0,34816), K hi [34816,104448), K lo [104448,174080).
// PV phase:   P (528-stride) [0,67584) over dead Q + K-head,
//             V hi [69632,139264) over dead K tail.
#define SM_QH  0
#define SM_KH  34816
#define SM_KL  104448
#define SM_PH  0
#define SM_VH  69632
#define SMEM_ATTN 174080

#define BETA_CHUNK(ACC, CBASE, NSTEPS) do {                                         \
    _Pragma("unroll")                                                               \
    for (int ks = 0; ks < 8; ks++) {                                                \
        int k0 = 16 * ks;                                                           \
        uint32_t aH[4];                                                             \
        LDSM_X4(aH, sbase + SM_QH + aRow * 272 + (k0 + halfOff) * 2);               \
        _Pragma("unroll")                                                           \
        for (int np = 0; np < 4; np++) {                                            \
            if (np >= (NSTEPS)) break;                                              \
            uint32_t baddr = sbase + SM_KH +                                        \
                (uint32_t)((CBASE) + nw * 64 + 16 * np + bRowBase) * 272 +          \
                (k0 + bColHalf) * 2;                                                \
            uint32_t bH[4], bL[4];                                                  \
            LDSM_X4(bH, baddr);                                                     \
            LDSM_X4(bL, baddr + (SM_KL - SM_KH));                                   \
            mma_fp16(ACC[2 * np],     aH, bH[0], bH[1]);                            \
            mma_fp16(ACC[2 * np],     aH, bL[0], bL[1]);                            \
            mma_fp16(ACC[2 * np + 1], aH, bH[2], bH[3]);                            \
            mma_fp16(ACC[2 * np + 1], aH, bL[2], bL[3]);                            \
        }                                                                           \
    }                                                                               \
} while (0)

__global__ __launch_bounds__(512, 1)
void attn_kernel(float* __restrict__ O) {
    extern __shared__ char smem[];
    __shared__ float s_bias[256];
    __shared__ float s_red[512];
    __shared__ int s_idx[256];
    uint32_t sbase = smem_u32(smem);

    int tid = threadIdx.x;
    int w = tid >> 5, l = tid & 31;
    int g = l >> 2, t = l & 3;
    int mw = w & 7, nw = w >> 3;
    int b = blockIdx.y;
    int i0 = blockIdx.x * 128;
    size_t boff = (size_t)b * NN * DD;

    int nv = g_nv[b];
    int kpadN = (nv + 15) & ~15;

    if (tid < 256) {
        s_idx[tid] = g_idx[b * NN + tid];
        s_bias[tid] = (tid < nv) ? 0.f : -1e30f;
    }

    // stage Q hi (128 rows of M)
    for (int idx = tid; idx < 128 * 16; idx += 512) {
        int row = idx >> 4, c8 = idx & 15;
        size_t src = boff + (size_t)(i0 + row) * DD + c8 * 8;
        *(uint4*)(smem + SM_QH + row * 272 + c8 * 16) = *(const uint4*)(g_Mh + src);
    }
    // stage K compact rows [0, kpadN) (zero pads)
    {
        uint4 z = make_uint4(0, 0, 0, 0);
        for (int idx = tid; idx < kpadN * 16; idx += 512) {
            int row = idx >> 4, c8 = idx & 15;
            uint4 vh = z, vl = z;
            if (row < nv) {
                size_t src = boff + (size_t)row * DD + c8 * 8;
                vh = *(const uint4*)(g_Kh + src);
                vl = *(const uint4*)(g_Kl + src);
            }
            *(uint4*)(smem + SM_KH + row * 272 + c8 * 16) = vh;
            *(uint4*)(smem + SM_KL + row * 272 + c8 * 16) = vl;
        }
    }
    __syncthreads();

    // --- beta GEMM over valid 16-col tiles only (2-term: Qh*(Kh+Kl)) ---
    uint32_t aRow = (uint32_t)(16 * mw + (l & 15));
    uint32_t halfOff = (uint32_t)((l >> 4) << 3);
    uint32_t bRowBase = (uint32_t)(((l >> 4) << 3) + (l & 7));
    uint32_t bColHalf = (uint32_t)(((l >> 3) & 1) << 3);

    int base0 = nw * 64, base1 = 128 + nw * 64;
    int ns0 = min(4, max(0, (kpadN - base0) >> 4));
    int ns1 = min(4, max(0, (kpadN - base1) >> 4));

    float acc0[8][4], acc1[8][4];
#pragma unroll
    for (int j = 0; j < 8; j++)
#pragma unroll
        for (int q = 0; q < 4; q++) { acc0[j][q] = 0.f; acc1[j][q] = 0.f; }

    if (ns0 > 0) BETA_CHUNK(acc0, 0, ns0);
    if (ns1 > 0) BETA_CHUNK(acc1, 128, ns1);

    // --- masked softmax (rows rowA, rowB in 0..127) ---
    int rowA = 16 * mw + g, rowB = rowA + 8;
    float mx0 = -3.0e38f, mx1 = -3.0e38f;
#pragma unroll
    for (int j = 0; j < 8; j++) {
        float2 bv = *(const float2*)&s_bias[nw * 64 + j * 8 + 2 * t];
        acc0[j][0] += bv.x; acc0[j][1] += bv.y;
        acc0[j][2] += bv.x; acc0[j][3] += bv.y;
        mx0 = fmaxf(mx0, fmaxf(acc0[j][0], acc0[j][1]));
        mx1 = fmaxf(mx1, fmaxf(acc0[j][2], acc0[j][3]));
    }
    if (kpadN > 128) {
#pragma unroll
        for (int j = 0; j < 8; j++) {
            float2 bv = *(const float2*)&s_bias[128 + nw * 64 + j * 8 + 2 * t];
            acc1[j][0] += bv.x; acc1[j][1] += bv.y;
            acc1[j][2] += bv.x; acc1[j][3] += bv.y;
            mx0 = fmaxf(mx0, fmaxf(acc1[j][0], acc1[j][1]));
            mx1 = fmaxf(mx1, fmaxf(acc1[j][2], acc1[j][3]));
        }
    }
    mx0 = fmaxf(mx0, __shfl_xor_sync(0xffffffffu, mx0, 1));
    mx0 = fmaxf(mx0, __shfl_xor_sync(0xffffffffu, mx0, 2));
    mx1 = fmaxf(mx1, __shfl_xor_sync(0xffffffffu, mx1, 1));
    mx1 = fmaxf(mx1, __shfl_xor_sync(0xffffffffu, mx1, 2));
    if (t == 0) {
        s_red[nw * 128 + rowA] = mx0;
        s_red[nw * 128 + rowB] = mx1;
    }
    __syncthreads();
    float M0 = fmaxf(s_red[rowA], s_red[128 + rowA]);
    float M1 = fmaxf(s_red[rowB], s_red[128 + rowB]);
    float s0 = 0.f, s1 = 0.f;
#pragma unroll
    for (int j = 0; j < 8; j++) {
        acc0[j][0] = __expf(acc0[j][0] - M0); s0 += acc0[j][0];
        acc0[j][1] = __expf(acc0[j][1] - M0); s0 += acc0[j][1];
        acc0[j][2] = __expf(acc0[j][2] - M1); s1 += acc0[j][2];
        acc0[j][3] = __expf(acc0[j][3] - M1); s1 += acc0[j][3];
    }
    if (kpadN > 128) {
#pragma unroll
        for (int j = 0; j < 8; j++) {
            acc1[j][0] = __expf(acc1[j][0] - M0); s0 += acc1[j][0];
            acc1[j][1] = __expf(acc1[j][1] - M0); s0 += acc1[j][1];
            acc1[j][2] = __expf(acc1[j][2] - M1); s1 += acc1[j][2];
            acc1[j][3] = __expf(acc1[j][3] - M1); s1 += acc1[j][3];
        }
    }
    s0 += __shfl_xor_sync(0xffffffffu, s0, 1);
    s0 += __shfl_xor_sync(0xffffffffu, s0, 2);
    s1 += __shfl_xor_sync(0xffffffffu, s1, 1);
    s1 += __shfl_xor_sync(0xffffffffu, s1, 2);
    __syncthreads();
    if (t == 0) {
        s_red[256 + nw * 128 + rowA] = s0;
        s_red[256 + nw * 128 + rowB] = s1;
    }
    __syncthreads();
    float inv0 = __fdividef(1.f, s_red[256 + rowA] + s_red[256 + 128 + rowA]);
    float inv1 = __fdividef(1.f, s_red[256 + rowB] + s_red[256 + 128 + rowB]);

    // --- write P (fp16 hi only) over dead Q + K-head region ---
    {
        char* ph = smem + SM_PH;
#pragma unroll
        for (int j = 0; j < 8; j++) {
            int col = nw * 64 + j * 8 + 2 * t;
            *(uint32_t*)(ph + rowA * 528 + col * 2) = pack_hi(acc0[j][0] * inv0, acc0[j][1] * inv0);
            *(uint32_t*)(ph + rowB * 528 + col * 2) = pack_hi(acc0[j][2] * inv1, acc0[j][3] * inv1);
        }
        if (kpadN > 128) {
#pragma unroll
            for (int j = 0; j < 8; j++) {
                int col = 128 + nw * 64 + j * 8 + 2 * t;
                *(uint32_t*)(ph + rowA * 528 + col * 2) = pack_hi(acc1[j][0] * inv0, acc1[j][1] * inv0);
                *(uint32_t*)(ph + rowB * 528 + col * 2) = pack_hi(acc1[j][2] * inv1, acc1[j][3] * inv1);
            }
        }
    }
    // --- stage V gathered (hi only, over dead K tail) ---
    {
        uint4 z = make_uint4(0, 0, 0, 0);
        for (int idx = tid; idx < kpadN * 16; idx += 512) {
            int row = idx >> 4, c8 = idx & 15;
            uint4 vh = z;
            if (row < nv) {
                size_t src = boff + (size_t)s_idx[row] * DD + c8 * 8;
                vh = *(const uint4*)(g_Mh + src);
            }
            *(uint4*)(smem + SM_VH + row * 272 + c8 * 16) = vh;
        }
    }
    __syncthreads();

    // --- PV GEMM: 1-term (P hi * V hi), k up to kpadN ---
    int d0 = 64 * nw;
    float o[8][4];
#pragma unroll
    for (int i = 0; i < 8; i++)
#pragma unroll
        for (int j = 0; j < 4; j++) o[i][j] = 0.f;

    int ksteps = kpadN >> 4;
#pragma unroll 1
    for (int ks = 0; ks < ksteps; ks++) {
        int k0 = 16 * ks;
        uint32_t aH[4];
        LDSM_X4(aH, sbase + SM_PH + aRow * 528 + (k0 + halfOff) * 2);
#pragma unroll
        for (int np = 0; np < 4; np++) {
            uint32_t baddr = sbase + SM_VH + (uint32_t)(k0 + (l & 15)) * 272 +
                             (uint32_t)(d0 + 16 * np + halfOff) * 2;
            uint32_t bH[4];
            LDSM_X4T(bH, baddr);
            mma_fp16(o[2 * np],     aH, bH[0], bH[1]);
            mma_fp16(o[2 * np + 1], aH, bH[2], bH[3]);
        }
    }

    float* Ob = O + ((size_t)b * NN + i0) * DD;
#pragma unroll
    for (int nt = 0; nt < 8; nt++) {
        int col = d0 + 8 * nt + 2 * t;
        *(float2*)&Ob[(size_t)rowA * DD + col] = make_float2(o[nt][0], o[nt][1]);
        *(float2*)&Ob[(size_t)rowB * DD + col] = make_float2(o[nt][2], o[nt][3]);
    }
}

// ---------------------------------------------------------------------------
extern "C" void kernel_launch(void* const* d_in, const int* in_sizes, int n_in,
                              void* d_out, int out_size) {
    (void)in_sizes; (void)n_in; (void)out_size;
    const float* mirror    = (const float*)d_in[0];
    const float* satellite = (const float*)d_in[1];
    const void*  mask      = d_in[2];
    const float* Wq1 = (const float*)d_in[3];
    const float* Wk1 = (const float*)d_in[4];
    const float* Wq2 = (const float*)d_in[5];
    const float* Wk2 = (const float*)d_in[6];
    float* sat_out = (float*)d_out;
    float* mir_out = (float*)d_out + BND;

    cudaFuncSetAttribute(gemm_T_fused,    cudaFuncAttributeMaxDynamicSharedMemorySize, GT_SMEM);
    cudaFuncSetAttribute(gemm_K2C_kernel, cudaFuncAttributeMaxDynamicSharedMemorySize, GK_SMEM);
    cudaFuncSetAttribute(attn_kernel,     cudaFuncAttributeMaxDynamicSharedMemorySize, SMEM_ATTN);

    detect_mask_kernel<<<1, 256>>>((const unsigned int*)mask);
    decode_compact_kernel<<<BB, 256>>>(mask);
    prep_w_kernel<<<dim3(128, 2), 512>>>(Wq1, Wk1, Wq2, Wk2);

    gemm_T_fused<<<296, 256, GT_SMEM>>>(mirror, satellite, sat_out);
    gemm_K2C_kernel<<<296, 256, GK_SMEM>>>();
    attn_kernel<<<dim3(NN / 128, BB), 512, SMEM_ATTN>>>(mir_out);
}

// round 15
// speedup vs baseline: 1.6684x; 1.0486x over previous
#include <cuda_runtime.h>
#include <cuda_fp16.h>
#include <cstdint>

// Problem constants
#define BB 512
#define NN 256
#define DD 128
#define BND ((size_t)BB * NN * DD)

static __device__ __half g_W1h[DD * DD];
static __device__ __half g_W2h[DD * DD], g_W2l[DD * DD];
static __device__ __half g_Mh[BND];                  // mirror hi
static __device__ __half g_Sh[BND];                  // sat_out hi
static __device__ __half g_Kh[BND], g_Kl[BND];       // K2C split (COMPACT rows)
static __device__ int g_idx[BB * NN];                // compact pos -> j
static __device__ int g_nv[BB];                      // valid count per batch
static __device__ int g_mwidth1;

#define SCALE 0.08838834764831845f  // 1/sqrt(128)

// ============================ PTX helpers ==================================
__device__ __forceinline__ uint32_t smem_u32(const void* p) {
    uint32_t a;
    asm("{ .reg .u64 t; cvta.to.shared.u64 t, %1; cvt.u32.u64 %0, t; }" : "=r"(a) : "l"(p));
    return a;
}

#define LDSM_X4(r, a) \
    asm volatile("ldmatrix.sync.aligned.m8n8.x4.shared.b16 {%0,%1,%2,%3}, [%4];" \
        : "=r"((r)[0]), "=r"((r)[1]), "=r"((r)[2]), "=r"((r)[3]) : "r"(a))
#define LDSM_X4T(r, a) \
    asm volatile("ldmatrix.sync.aligned.m8n8.x4.trans.shared.b16 {%0,%1,%2,%3}, [%4];" \
        : "=r"((r)[0]), "=r"((r)[1]), "=r"((r)[2]), "=r"((r)[3]) : "r"(a))

#define CP_ASYNC16(dst, src) \
    asm volatile("cp.async.cg.shared.global [%0], [%1], 16;" :: "r"(dst), "l"(src) : "memory")
#define CP_COMMIT() asm volatile("cp.async.commit_group;" ::: "memory")
#define CP_WAIT0()  asm volatile("cp.async.wait_group 0;" ::: "memory")

__device__ __forceinline__ void mma_fp16(float* c, const uint32_t* a, uint32_t b0, uint32_t b1) {
    asm volatile(
        "mma.sync.aligned.m16n8k16.row.col.f32.f16.f16.f32 "
        "{%0,%1,%2,%3}, {%4,%5,%6,%7}, {%8,%9}, {%0,%1,%2,%3};"
        : "+f"(c[0]), "+f"(c[1]), "+f"(c[2]), "+f"(c[3])
        : "r"(a[0]), "r"(a[1]), "r"(a[2]), "r"(a[3]), "r"(b0), "r"(b1));
}

__device__ __forceinline__ void split_pack(float x, float y, uint32_t& h, uint32_t& l) {
    __half hx = __float2half(x);
    __half hy = __float2half(y);
    __half lx = __float2half(x - __half2float(hx));
    __half ly = __float2half(y - __half2float(hy));
    __half2 hh; hh.x = hx; hh.y = hy;
    __half2 ll; ll.x = lx; ll.y = ly;
    h = *(uint32_t*)&hh;
    l = *(uint32_t*)&ll;
}

__device__ __forceinline__ uint32_t pack_hi(float x, float y) {
    __half2 hh; hh.x = __float2half(x); hh.y = __float2half(y);
    return *(uint32_t*)&hh;
}

// ======================= mask canonicalization + compaction ================
__global__ void detect_mask_kernel(const unsigned int* __restrict__ m) {
    __shared__ int red[256];
    int tid = threadIdx.x;
    int p = 0;
    for (int i = tid; i < (BB * NN) / 4; i += 256) {
        unsigned int w = m[i];
        if (w != 0u && w != 1u && w != 0x3F800000u) p = 1;
    }
    red[tid] = p;
    __syncthreads();
    for (int s = 128; s > 0; s >>= 1) {
        if (tid < s) red[tid] |= red[tid + s];
        __syncthreads();
    }
    if (tid == 0) g_mwidth1 = red[0];
}

__global__ void decode_compact_kernel(const void* __restrict__ m) {
    int b = blockIdx.x;
    int tid = threadIdx.x;
    int w = tid >> 5, l = tid & 31;
    __shared__ int wcnt[8], woff[8];
    int i = b * NN + tid;
    int valid;
    if (g_mwidth1) valid = (((const unsigned char*)m)[i] != 0);
    else           valid = (((const unsigned int*)m)[i] != 0u);
    unsigned bal = __ballot_sync(0xffffffffu, valid);
    int pre = __popc(bal & ((1u << l) - 1u));
    if (l == 31) wcnt[w] = __popc(bal);
    g_idx[i] = 0;   // prefill pads with a safe (valid) index
    __syncthreads();
    if (tid == 0) {
        int s = 0;
        for (int k = 0; k < 8; k++) { woff[k] = s; s += wcnt[k]; }
        g_nv[b] = s;
    }
    __syncthreads();
    if (valid) g_idx[b * NN + woff[w] + pre] = tid;
}

// ======================= weight contraction (scaled + split) ===============
__global__ void prep_w_kernel(const float* __restrict__ Wq1, const float* __restrict__ Wk1,
                              const float* __restrict__ Wq2, const float* __restrict__ Wk2) {
    int a = blockIdx.x;
    int c = threadIdx.x & 127, kc = threadIdx.x >> 7;
    __shared__ float red[512];
    const float* X = (blockIdx.y == 0) ? Wq1 : Wq2;
    const float* Y = (blockIdx.y == 0) ? Wk1 : Wk2;
    float acc = 0.f;
#pragma unroll 8
    for (int k = kc * 32; k < kc * 32 + 32; k++)
        acc = fmaf(X[k * DD + c], Y[k * DD + a], acc);
    red[kc * 128 + c] = acc;
    __syncthreads();
    if (kc == 0) {
        float v = (red[c] + red[128 + c]) + (red[256 + c] + red[384 + c]);
        v *= SCALE;
        __half h = __float2half(v);
        __half lo = __float2half(v - __half2float(h));
        int idx = a * DD + c;
        if (blockIdx.y == 0) { g_W1h[idx] = h; }
        else                 { g_W2h[idx] = h; g_W2l[idx] = lo; }
    }
}

// ======================= fused: M convert + T GEMM + gate + sat_out ========
// Persistent: 296 CTAs (2/SM) stage W1h ONCE, then stride over 2048 64-row
// tiles.  S staged via cp.async (overlaps M convert); epilogue does zero
// global loads.
#define GT_A    0          // Mh tile: 64 x 272 B
#define GT_WH   17408      // W1h: 128 x 272 B
#define GT_S    52224      // S fp32: 64 x 132 floats (528 B rows)
#define GT_SMEM 86016

__global__ __launch_bounds__(256, 2)
void gemm_T_fused(const float* __restrict__ M, const float* __restrict__ S,
                  float* __restrict__ SO) {
    extern __shared__ char smem[];
    __shared__ float s_red[128];
    uint32_t sbase = smem_u32(smem);
    float* sS = (float*)(smem + GT_S);
    int tid = threadIdx.x;
    int w = tid >> 5, l = tid & 31;

    // stage W1h ONCE
    for (int idx = tid; idx < 2048; idx += 256) {
        int row = idx >> 4, c8 = idx & 15;
        *(uint4*)(smem + GT_WH + row * 272 + c8 * 16) =
            *(const uint4*)(g_W1h + row * DD + c8 * 8);
    }

    int mw = w & 3, nwp = w >> 2;
    int r0 = mw * 16, c0 = nwp * 64;
    int g = l >> 2, t = l & 3;
    uint32_t halfOff = (uint32_t)((l >> 4) << 3);

    for (int item = blockIdx.x; item < 2048; item += gridDim.x) {
        size_t n0 = (size_t)item * 64;

        // S -> smem via cp.async (64 rows x 32 16B-chunks = 2048 chunks)
        for (int idx = tid; idx < 2048; idx += 256) {
            int row = idx >> 5, c4 = idx & 31;
            CP_ASYNC16(sbase + GT_S + row * 528 + c4 * 16,
                       S + (n0 + row) * DD + c4 * 4);
        }
        CP_COMMIT();

        // M fp32 -> fp16 hi (global + smem tile), overlapping the S DMA
        for (int idx = tid; idx < 4096; idx += 256) {
            int row = idx >> 6, c2 = idx & 63;
            float2 v = ((const float2*)(M + (n0 + row) * DD))[c2];
            uint32_t h = pack_hi(v.x, v.y);
            ((uint32_t*)(g_Mh + (n0 + row) * DD))[c2] = h;
            *(uint32_t*)(smem + GT_A + row * 272 + c2 * 4) = h;
        }
        CP_WAIT0();
        __syncthreads();

        float acc[8][4];
#pragma unroll
        for (int j = 0; j < 8; j++)
#pragma unroll
            for (int q = 0; q < 4; q++) acc[j][q] = 0.f;

#pragma unroll 1
        for (int ks = 0; ks < 8; ks++) {
            int k0 = 16 * ks;
            uint32_t aH[4];
            LDSM_X4(aH, sbase + GT_A + (r0 + (l & 15)) * 272 + (k0 + halfOff) * 2);
#pragma unroll
            for (int np = 0; np < 4; np++) {
                uint32_t baddr = sbase + GT_WH + (uint32_t)(k0 + (l & 15)) * 272 +
                                 (uint32_t)(c0 + 16 * np + halfOff) * 2;
                uint32_t bH[4];
                LDSM_X4T(bH, baddr);
                mma_fp16(acc[2 * np],     aH, bH[0], bH[1]);
                mma_fp16(acc[2 * np + 1], aH, bH[2], bH[3]);
            }
        }

        // --- epilogue: alpha = rowdot(S, T) [smem], sat_out + hi split ---
        int rowA = r0 + g, rowB = rowA + 8;
        float p0 = 0.f, p1 = 0.f;
#pragma unroll
        for (int nt = 0; nt < 8; nt++) {
            int col = c0 + nt * 8 + 2 * t;
            float2 sa = *(const float2*)&sS[rowA * 132 + col];
            float2 sb = *(const float2*)&sS[rowB * 132 + col];
            p0 += sa.x * acc[nt][0] + sa.y * acc[nt][1];
            p1 += sb.x * acc[nt][2] + sb.y * acc[nt][3];
        }
        p0 += __shfl_xor_sync(0xffffffffu, p0, 1);
        p0 += __shfl_xor_sync(0xffffffffu, p0, 2);
        p1 += __shfl_xor_sync(0xffffffffu, p1, 1);
        p1 += __shfl_xor_sync(0xffffffffu, p1, 2);
        if (t == 0) {
            s_red[nwp * 64 + rowA] = p0;
            s_red[nwp * 64 + rowB] = p1;
        }
        __syncthreads();

        float alA = s_red[rowA] + s_red[64 + rowA];
        float alB = s_red[rowB] + s_red[64 + rowB];
        size_t rA = n0 + rowA, rB = n0 + rowB;
#pragma unroll
        for (int nt = 0; nt < 8; nt++) {
            int col = c0 + nt * 8 + 2 * t;
            float2 sa = *(const float2*)&sS[rowA * 132 + col];
            __half2 mh = *(const __half2*)(smem + GT_A + rowA * 272 + col * 2);
            float2 ma = __half22float2(mh);
            float2 oa;
            oa.x = fmaf(alA, ma.x - sa.x, sa.x);
            oa.y = fmaf(alA, ma.y - sa.y, sa.y);
            *(float2*)(SO + rA * DD + col) = oa;
            *(uint32_t*)(g_Sh + rA * DD + col) = pack_hi(oa.x, oa.y);

            float2 sb = *(const float2*)&sS[rowB * 132 + col];
            __half2 mhb = *(const __half2*)(smem + GT_A + rowB * 272 + col * 2);
            float2 mb = __half22float2(mhb);
            float2 ob;
            ob.x = fmaf(alB, mb.x - sb.x, sb.x);
            ob.y = fmaf(alB, mb.y - sb.y, sb.y);
            *(float2*)(SO + rB * DD + col) = ob;
            *(uint32_t*)(g_Sh + rB * DD + col) = pack_hi(ob.x, ob.y);
        }
        __syncthreads();   // iter-n reads done before iter-n+1 staging
    }
}

// ======================= K2C GEMM (2-term, gathered, compact out) ==========
#define GK_A    0
#define GK_WH   17408
#define GK_WL   52224
#define GK_SMEM 87040

__global__ __launch_bounds__(256, 2)
void gemm_K2C_kernel() {
    extern __shared__ char smem[];
    uint32_t sbase = smem_u32(smem);
    int tid = threadIdx.x;
    int w = tid >> 5, l = tid & 31;

    // stage W2 split ONCE
    for (int idx = tid; idx < 2048; idx += 256) {
        int row = idx >> 4, c8 = idx & 15;
        *(uint4*)(smem + GK_WH + row * 272 + c8 * 16) = *(const uint4*)(g_W2h + row * DD + c8 * 8);
        *(uint4*)(smem + GK_WL + row * 272 + c8 * 16) = *(const uint4*)(g_W2l + row * DD + c8 * 8);
    }
    __syncthreads();

    int mw = w & 3, nwp = w >> 2;
    int r0 = mw * 16, c0 = nwp * 64;
    int g = l >> 2, t = l & 3;
    uint32_t halfOff = (uint32_t)((l >> 4) << 3);

    for (int item = blockIdx.x; item < BB * 4; item += gridDim.x) {
        int b = item >> 2;
        int pos0 = (item & 3) * 64;
        if (pos0 >= g_nv[b]) continue;   // uniform across block

        // gather Sh rows via cp.async
        for (int idx = tid; idx < 1024; idx += 256) {
            int row = idx >> 4, c8 = idx & 15;
            int j = g_idx[b * NN + pos0 + row];
            CP_ASYNC16(sbase + GK_A + row * 272 + c8 * 16,
                       g_Sh + ((size_t)b * NN + j) * DD + c8 * 8);
        }
        CP_COMMIT();
        CP_WAIT0();
        __syncthreads();

        float acc[8][4];
#pragma unroll
        for (int j = 0; j < 8; j++)
#pragma unroll
            for (int q = 0; q < 4; q++) acc[j][q] = 0.f;

#pragma unroll 1
        for (int ks = 0; ks < 8; ks++) {
            int k0 = 16 * ks;
            uint32_t aH[4];
            LDSM_X4(aH, sbase + GK_A + (r0 + (l & 15)) * 272 + (k0 + halfOff) * 2);
#pragma unroll
            for (int np = 0; np < 4; np++) {
                uint32_t baddr = sbase + GK_WH + (uint32_t)(k0 + (l & 15)) * 272 +
                                 (uint32_t)(c0 + 16 * np + halfOff) * 2;
                uint32_t bH[4], bL[4];
                LDSM_X4T(bH, baddr);
                LDSM_X4T(bL, baddr + (GK_WL - GK_WH));
                mma_fp16(acc[2 * np],     aH, bH[0], bH[1]);
                mma_fp16(acc[2 * np],     aH, bL[0], bL[1]);
                mma_fp16(acc[2 * np + 1], aH, bH[2], bH[3]);
                mma_fp16(acc[2 * np + 1], aH, bL[2], bL[3]);
            }
        }

#pragma unroll
        for (int nt = 0; nt < 8; nt++) {
            size_t rowA = (size_t)b * NN + pos0 + r0 + g;
            size_t rowB = rowA + 8;
            int col = c0 + nt * 8 + 2 * t;
            uint32_t h, lo;
            split_pack(acc[nt][0], acc[nt][1], h, lo);
            *(uint32_t*)(g_Kh + rowA * DD + col) = h;
            *(uint32_t*)(g_Kl + rowA * DD + col) = lo;
            split_pack(acc[nt][2], acc[nt][3], h, lo);
            *(uint32_t*)(g_Kh + rowB * DD + col) = h;
            *(uint32_t*)(g_Kl + rowB * DD + col) = lo;
        }
        __syncthreads();   // MMA reads done before next iter staging
    }
}

// ======================= fused attention (compacted keys) ==================
// CTA = (batch b, 128 i-rows).  512 threads = 16 warps: 8 m-warps x 2 n-warps.
// beta phase: Q hi [0,34816), K hi [34816,104448), K lo [104448,174080).
// PV phase:   P (528-stride) [0,67584) over dead Q + K-head,
//             V hi [69632,139264) over dead K (prefetched via cp.async
//             during softmax — K fully retired by the first post-beta sync).
#define SM_QH  0
#define SM_KH  34816
#define SM_KL  104448
#define SM_PH  0
#define SM_VH  69632
#define SMEM_ATTN 174080

#define BETA_CHUNK(ACC, CBASE, NSTEPS) do {                                         \
    _Pragma("unroll")                                                               \
    for (int ks = 0; ks < 8; ks++) {                                                \
        int k0 = 16 * ks;                                                           \
        uint32_t aH[4];                                                             \
        LDSM_X4(aH, sbase + SM_QH + aRow * 272 + (k0 + halfOff) * 2);               \
        _Pragma("unroll")                                                           \
        for (int np = 0; np < 4; np++) {                                            \
            if (np >= (NSTEPS)) break;                                              \
            uint32_t baddr = sbase + SM_KH +                                        \
                (uint32_t)((CBASE) + nw * 64 + 16 * np + bRowBase) * 272 +          \
                (k0 + bColHalf) * 2;                                                \
            uint32_t bH[4], bL[4];                                                  \
            LDSM_X4(bH, baddr);                                                     \
            LDSM_X4(bL, baddr + (SM_KL - SM_KH));                                   \
            mma_fp16(ACC[2 * np],     aH, bH[0], bH[1]);                            \
            mma_fp16(ACC[2 * np],     aH, bL[0], bL[1]);                            \
            mma_fp16(ACC[2 * np + 1], aH, bH[2], bH[3]);                            \
            mma_fp16(ACC[2 * np + 1], aH, bL[2], bL[3]);                            \
        }                                                                           \
    }                                                                               \
} while (0)

__global__ __launch_bounds__(512, 1)
void attn_kernel(float* __restrict__ O) {
    extern __shared__ char smem[];
    __shared__ float s_bias[256];
    __shared__ float s_red[512];
    __shared__ int s_idx[256];
    uint32_t sbase = smem_u32(smem);

    int tid = threadIdx.x;
    int w = tid >> 5, l = tid & 31;
    int g = l >> 2, t = l & 3;
    int mw = w & 7, nw = w >> 3;
    int b = blockIdx.y;
    int i0 = blockIdx.x * 128;
    size_t boff = (size_t)b * NN * DD;

    int nv = g_nv[b];
    int kpadN = (nv + 15) & ~15;

    if (tid < 256) {
        s_idx[tid] = g_idx[b * NN + tid];
        s_bias[tid] = (tid < nv) ? 0.f : -1e30f;
    }

    // stage Q hi (128 rows of M)
    for (int idx = tid; idx < 128 * 16; idx += 512) {
        int row = idx >> 4, c8 = idx & 15;
        size_t src = boff + (size_t)(i0 + row) * DD + c8 * 8;
        *(uint4*)(smem + SM_QH + row * 272 + c8 * 16) = *(const uint4*)(g_Mh + src);
    }
    // stage K compact rows [0, kpadN) (zero pads)
    {
        uint4 z = make_uint4(0, 0, 0, 0);
        for (int idx = tid; idx < kpadN * 16; idx += 512) {
            int row = idx >> 4, c8 = idx & 15;
            uint4 vh = z, vl = z;
            if (row < nv) {
                size_t src = boff + (size_t)row * DD + c8 * 8;
                vh = *(const uint4*)(g_Kh + src);
                vl = *(const uint4*)(g_Kl + src);
            }
            *(uint4*)(smem + SM_KH + row * 272 + c8 * 16) = vh;
            *(uint4*)(smem + SM_KL + row * 272 + c8 * 16) = vl;
        }
    }
    __syncthreads();

    // --- beta GEMM over valid 16-col tiles only (2-term: Qh*(Kh+Kl)) ---
    uint32_t aRow = (uint32_t)(16 * mw + (l & 15));
    uint32_t halfOff = (uint32_t)((l >> 4) << 3);
    uint32_t bRowBase = (uint32_t)(((l >> 4) << 3) + (l & 7));
    uint32_t bColHalf = (uint32_t)(((l >> 3) & 1) << 3);

    int base0 = nw * 64, base1 = 128 + nw * 64;
    int ns0 = min(4, max(0, (kpadN - base0) >> 4));
    int ns1 = min(4, max(0, (kpadN - base1) >> 4));

    float acc0[8][4], acc1[8][4];
#pragma unroll
    for (int j = 0; j < 8; j++)
#pragma unroll
        for (int q = 0; q < 4; q++) { acc0[j][q] = 0.f; acc1[j][q] = 0.f; }

    if (ns0 > 0) BETA_CHUNK(acc0, 0, ns0);
    if (ns1 > 0) BETA_CHUNK(acc1, 128, ns1);

    // --- masked softmax (rows rowA, rowB in 0..127) ---
    int rowA = 16 * mw + g, rowB = rowA + 8;
    float mx0 = -3.0e38f, mx1 = -3.0e38f;
#pragma unroll
    for (int j = 0; j < 8; j++) {
        float2 bv = *(const float2*)&s_bias[nw * 64 + j * 8 + 2 * t];
        acc0[j][0] += bv.x; acc0[j][1] += bv.y;
        acc0[j][2] += bv.x; acc0[j][3] += bv.y;
        mx0 = fmaxf(mx0, fmaxf(acc0[j][0], acc0[j][1]));
        mx1 = fmaxf(mx1, fmaxf(acc0[j][2], acc0[j][3]));
    }
    if (kpadN > 128) {
#pragma unroll
        for (int j = 0; j < 8; j++) {
            float2 bv = *(const float2*)&s_bias[128 + nw * 64 + j * 8 + 2 * t];
            acc1[j][0] += bv.x; acc1[j][1] += bv.y;
            acc1[j][2] += bv.x; acc1[j][3] += bv.y;
            mx0 = fmaxf(mx0, fmaxf(acc1[j][0], acc1[j][1]));
            mx1 = fmaxf(mx1, fmaxf(acc1[j][2], acc1[j][3]));
        }
    }
    mx0 = fmaxf(mx0, __shfl_xor_sync(0xffffffffu, mx0, 1));
    mx0 = fmaxf(mx0, __shfl_xor_sync(0xffffffffu, mx0, 2));
    mx1 = fmaxf(mx1, __shfl_xor_sync(0xffffffffu, mx1, 1));
    mx1 = fmaxf(mx1, __shfl_xor_sync(0xffffffffu, mx1, 2));
    if (t == 0) {
        s_red[nw * 128 + rowA] = mx0;
        s_red[nw * 128 + rowB] = mx1;
    }
    __syncthreads();   // <-- every thread past beta: K region retired

    // --- prefetch V (gathered, hi only) into dead K region via cp.async ---
    {
        uint4 z = make_uint4(0, 0, 0, 0);
        for (int idx = tid; idx < kpadN * 16; idx += 512) {
            int row = idx >> 4, c8 = idx & 15;
            if (row < nv) {
                CP_ASYNC16(sbase + SM_VH + row * 272 + c8 * 16,
                           g_Mh + boff + (size_t)s_idx[row] * DD + c8 * 8);
            } else {
                *(uint4*)(smem + SM_VH + row * 272 + c8 * 16) = z;
            }
        }
        CP_COMMIT();
    }

    // --- softmax continues while V streams in ---
    float M0 = fmaxf(s_red[rowA], s_red[128 + rowA]);
    float M1 = fmaxf(s_red[rowB], s_red[128 + rowB]);
    float s0 = 0.f, s1 = 0.f;
#pragma unroll
    for (int j = 0; j < 8; j++) {
        acc0[j][0] = __expf(acc0[j][0] - M0); s0 += acc0[j][0];
        acc0[j][1] = __expf(acc0[j][1] - M0); s0 += acc0[j][1];
        acc0[j][2] = __expf(acc0[j][2] - M1); s1 += acc0[j][2];
        acc0[j][3] = __expf(acc0[j][3] - M1); s1 += acc0[j][3];
    }
    if (kpadN > 128) {
#pragma unroll
        for (int j = 0; j < 8; j++) {
            acc1[j][0] = __expf(acc1[j][0] - M0); s0 += acc1[j][0];
            acc1[j][1] = __expf(acc1[j][1] - M0); s0 += acc1[j][1];
            acc1[j][2] = __expf(acc1[j][2] - M1); s1 += acc1[j][2];
            acc1[j][3] = __expf(acc1[j][3] - M1); s1 += acc1[j][3];
        }
    }
    s0 += __shfl_xor_sync(0xffffffffu, s0, 1);
    s0 += __shfl_xor_sync(0xffffffffu, s0, 2);
    s1 += __shfl_xor_sync(0xffffffffu, s1, 1);
    s1 += __shfl_xor_sync(0xffffffffu, s1, 2);
    __syncthreads();
    if (t == 0) {
        s_red[256 + nw * 128 + rowA] = s0;
        s_red[256 + nw * 128 + rowB] = s1;
    }
    __syncthreads();
    float inv0 = __fdividef(1.f, s_red[256 + rowA] + s_red[256 + 128 + rowA]);
    float inv1 = __fdividef(1.f, s_red[256 + rowB] + s_red[256 + 128 + rowB]);

    // --- write P (fp16 hi only) over dead Q + K-head region ---
    {
        char* ph = smem + SM_PH;
#pragma unroll
        for (int j = 0; j < 8; j++) {
            int col = nw * 64 + j * 8 + 2 * t;
            *(uint32_t*)(ph + rowA * 528 + col * 2) = pack_hi(acc0[j][0] * inv0, acc0[j][1] * inv0);
            *(uint32_t*)(ph + rowB * 528 + col * 2) = pack_hi(acc0[j][2] * inv1, acc0[j][3] * inv1);
        }
        if (kpadN > 128) {
#pragma unroll
            for (int j = 0; j < 8; j++) {
                int col = 128 + nw * 64 + j * 8 + 2 * t;
                *(uint32_t*)(ph + rowA * 528 + col * 2) = pack_hi(acc1[j][0] * inv0, acc1[j][1] * inv0);
                *(uint32_t*)(ph + rowB * 528 + col * 2) = pack_hi(acc1[j][2] * inv1, acc1[j][3] * inv1);
            }
        }
    }
    CP_WAIT0();      // V fully resident
    __syncthreads(); // P + V visible to all warps

    // --- PV GEMM: 1-term (P hi * V hi), k up to kpadN ---
    int d0 = 64 * nw;
    float o[8][4];
#pragma unroll
    for (int i = 0; i < 8; i++)
#pragma unroll
        for (int j = 0; j < 4; j++) o[i][j] = 0.f;

    int ksteps = kpadN >> 4;
#pragma unroll 1
    for (int ks = 0; ks < ksteps; ks++) {
        int k0 = 16 * ks;
        uint32_t aH[4];
        LDSM_X4(aH, sbase + SM_PH + aRow * 528 + (k0 + halfOff) * 2);
#pragma unroll
        for (int np = 0; np < 4; np++) {
            uint32_t baddr = sbase + SM_VH + (uint32_t)(k0 + (l & 15)) * 272 +
                             (uint32_t)(d0 + 16 * np + halfOff) * 2;
            uint32_t bH[4];
            LDSM_X4T(bH, baddr);
            mma_fp16(o[2 * np],     aH, bH[0], bH[1]);
            mma_fp16(o[2 * np + 1], aH, bH[2], bH[3]);
        }
    }

    float* Ob = O + ((size_t)b * NN + i0) * DD;
#pragma unroll
    for (int nt = 0; nt < 8; nt++) {
        int col = d0 + 8 * nt + 2 * t;
        *(float2*)&Ob[(size_t)rowA * DD + col] = make_float2(o[nt][0], o[nt][1]);
        *(float2*)&Ob[(size_t)rowB * DD + col] = make_float2(o[nt][2], o[nt][3]);
    }
}

// ---------------------------------------------------------------------------
extern "C" void kernel_launch(void* const* d_in, const int* in_sizes, int n_in,
                              void* d_out, int out_size) {
    (void)in_sizes; (void)n_in; (void)out_size;
    const float* mirror    = (const float*)d_in[0];
    const float* satellite = (const float*)d_in[1];
    const void*  mask      = d_in[2];
    const float* Wq1 = (const float*)d_in[3];
    const float* Wk1 = (const float*)d_in[4];
    const float* Wq2 = (const float*)d_in[5];
    const float* Wk2 = (const float*)d_in[6];
    float* sat_out = (float*)d_out;
    float* mir_out = (float*)d_out + BND;

    cudaFuncSetAttribute(gemm_T_fused,    cudaFuncAttributeMaxDynamicSharedMemorySize, GT_SMEM);
    cudaFuncSetAttribute(gemm_K2C_kernel, cudaFuncAttributeMaxDynamicSharedMemorySize, GK_SMEM);
    cudaFuncSetAttribute(attn_kernel,     cudaFuncAttributeMaxDynamicSharedMemorySize, SMEM_ATTN);

    detect_mask_kernel<<<1, 256>>>((const unsigned int*)mask);
    decode_compact_kernel<<<BB, 256>>>(mask);
    prep_w_kernel<<<dim3(128, 2), 512>>>(Wq1, Wk1, Wq2, Wk2);

    gemm_T_fused<<<296, 256, GT_SMEM>>>(mirror, satellite, sat_out);
    gemm_K2C_kernel<<<296, 256, GK_SMEM>>>();
    attn_kernel<<<dim3(NN / 128, BB), 512, SMEM_ATTN>>>(mir_out);
}

// round 16
// speedup vs baseline: 1.9500x; 1.1688x over previous
#include <cuda_runtime.h>
#include <cuda_fp16.h>
#include <cstdint>

// Problem constants
#define BB 512
#define NN 256
#define DD 128
#define BND ((size_t)BB * NN * DD)

static __device__ __half g_W1h[DD * DD];
static __device__ __half g_W2h[DD * DD], g_W2l[DD * DD];
static __device__ __half g_Mh[BND];                  // mirror hi
static __device__ __half g_Sh[BND];                  // sat_out hi
static __device__ __half g_Kh[BND], g_Kl[BND];       // K2C split (COMPACT rows)
static __device__ int g_idx[BB * NN];                // compact pos -> j
static __device__ int g_nv[BB];                      // valid count per batch

#define SCALE 0.08838834764831845f  // 1/sqrt(128)

// ============================ PTX helpers ==================================
__device__ __forceinline__ uint32_t smem_u32(const void* p) {
    uint32_t a;
    asm("{ .reg .u64 t; cvta.to.shared.u64 t, %1; cvt.u32.u64 %0, t; }" : "=r"(a) : "l"(p));
    return a;
}

#define LDSM_X4(r, a) \
    asm volatile("ldmatrix.sync.aligned.m8n8.x4.shared.b16 {%0,%1,%2,%3}, [%4];" \
        : "=r"((r)[0]), "=r"((r)[1]), "=r"((r)[2]), "=r"((r)[3]) : "r"(a))
#define LDSM_X4T(r, a) \
    asm volatile("ldmatrix.sync.aligned.m8n8.x4.trans.shared.b16 {%0,%1,%2,%3}, [%4];" \
        : "=r"((r)[0]), "=r"((r)[1]), "=r"((r)[2]), "=r"((r)[3]) : "r"(a))

#define CP_ASYNC16(dst, src) \
    asm volatile("cp.async.cg.shared.global [%0], [%1], 16;" :: "r"(dst), "l"(src) : "memory")
#define CP_COMMIT() asm volatile("cp.async.commit_group;" ::: "memory")
#define CP_WAIT0()  asm volatile("cp.async.wait_group 0;" ::: "memory")

__device__ __forceinline__ void mma_fp16(float* c, const uint32_t* a, uint32_t b0, uint32_t b1) {
    asm volatile(
        "mma.sync.aligned.m16n8k16.row.col.f32.f16.f16.f32 "
        "{%0,%1,%2,%3}, {%4,%5,%6,%7}, {%8,%9}, {%0,%1,%2,%3};"
        : "+f"(c[0]), "+f"(c[1]), "+f"(c[2]), "+f"(c[3])
        : "r"(a[0]), "r"(a[1]), "r"(a[2]), "r"(a[3]), "r"(b0), "r"(b1));
}

__device__ __forceinline__ void split_pack(float x, float y, uint32_t& h, uint32_t& l) {
    __half hx = __float2half(x);
    __half hy = __float2half(y);
    __half lx = __float2half(x - __half2float(hx));
    __half ly = __float2half(y - __half2float(hy));
    __half2 hh; hh.x = hx; hh.y = hy;
    __half2 ll; ll.x = lx; ll.y = ly;
    h = *(uint32_t*)&hh;
    l = *(uint32_t*)&ll;
}

__device__ __forceinline__ uint32_t pack_hi(float x, float y) {
    __half2 hh; hh.x = __float2half(x); hh.y = __float2half(y);
    return *(uint32_t*)&hh;
}

// ======================= mask decode + compaction (self-detecting) =========
// Each block decides the mask dtype from ITS OWN 64 words (bytes b*256..+256
// of the buffer — in-bounds under both layouts).  For a random 0/1 byte
// array, P(a word looks like a valid int32 0/1) = 1/8 -> P(all 64 do) ~ 0.
__global__ void decode_compact_kernel(const void* __restrict__ m) {
    int b = blockIdx.x;
    int tid = threadIdx.x;
    int w = tid >> 5, l = tid & 31;
    __shared__ int wcnt[8], woff[8], s_w1;
    if (tid == 0) s_w1 = 0;
    __syncthreads();
    if (tid < 64) {
        unsigned int wd = ((const unsigned int*)m)[b * 64 + tid];
        if (wd != 0u && wd != 1u && wd != 0x3F800000u) s_w1 = 1;
    }
    __syncthreads();
    int width1 = s_w1;

    int i = b * NN + tid;
    int valid;
    if (width1) valid = (((const unsigned char*)m)[i] != 0);
    else        valid = (((const unsigned int*)m)[i] != 0u);
    unsigned bal = __ballot_sync(0xffffffffu, valid);
    int pre = __popc(bal & ((1u << l) - 1u));
    if (l == 31) wcnt[w] = __popc(bal);
    g_idx[i] = 0;   // prefill pads with a safe (valid) index
    __syncthreads();
    if (tid == 0) {
        int s = 0;
        for (int k = 0; k < 8; k++) { woff[k] = s; s += wcnt[k]; }
        g_nv[b] = s;
    }
    __syncthreads();
    if (valid) g_idx[b * NN + woff[w] + pre] = tid;
}

// ======================= weight contraction (scaled + split) ===============
__global__ void prep_w_kernel(const float* __restrict__ Wq1, const float* __restrict__ Wk1,
                              const float* __restrict__ Wq2, const float* __restrict__ Wk2) {
    int a = blockIdx.x;
    int c = threadIdx.x & 127, kc = threadIdx.x >> 7;
    __shared__ float red[512];
    const float* X = (blockIdx.y == 0) ? Wq1 : Wq2;
    const float* Y = (blockIdx.y == 0) ? Wk1 : Wk2;
    float acc = 0.f;
#pragma unroll 8
    for (int k = kc * 32; k < kc * 32 + 32; k++)
        acc = fmaf(X[k * DD + c], Y[k * DD + a], acc);
    red[kc * 128 + c] = acc;
    __syncthreads();
    if (kc == 0) {
        float v = (red[c] + red[128 + c]) + (red[256 + c] + red[384 + c]);
        v *= SCALE;
        __half h = __float2half(v);
        __half lo = __float2half(v - __half2float(h));
        int idx = a * DD + c;
        if (blockIdx.y == 0) { g_W1h[idx] = h; }
        else                 { g_W2h[idx] = h; g_W2l[idx] = lo; }
    }
}

// ======================= fused: M convert + T GEMM + gate + sat_out ========
#define GT_A    0          // Mh tile: 64 x 272 B
#define GT_WH   17408      // W1h: 128 x 272 B
#define GT_S    52224      // S fp32: 64 x 132 floats (528 B rows)
#define GT_SMEM 86016

__global__ __launch_bounds__(256, 2)
void gemm_T_fused(const float* __restrict__ M, const float* __restrict__ S,
                  float* __restrict__ SO) {
    extern __shared__ char smem[];
    __shared__ float s_red[128];
    uint32_t sbase = smem_u32(smem);
    float* sS = (float*)(smem + GT_S);
    int tid = threadIdx.x;
    int w = tid >> 5, l = tid & 31;

    // stage W1h ONCE
    for (int idx = tid; idx < 2048; idx += 256) {
        int row = idx >> 4, c8 = idx & 15;
        *(uint4*)(smem + GT_WH + row * 272 + c8 * 16) =
            *(const uint4*)(g_W1h + row * DD + c8 * 8);
    }

    int mw = w & 3, nwp = w >> 2;
    int r0 = mw * 16, c0 = nwp * 64;
    int g = l >> 2, t = l & 3;
    uint32_t halfOff = (uint32_t)((l >> 4) << 3);

    for (int item = blockIdx.x; item < 2048; item += gridDim.x) {
        size_t n0 = (size_t)item * 64;

        // S -> smem via cp.async
        for (int idx = tid; idx < 2048; idx += 256) {
            int row = idx >> 5, c4 = idx & 31;
            CP_ASYNC16(sbase + GT_S + row * 528 + c4 * 16,
                       S + (n0 + row) * DD + c4 * 4);
        }
        CP_COMMIT();

        // M fp32 -> fp16 hi (global + smem tile), overlapping the S DMA
        for (int idx = tid; idx < 4096; idx += 256) {
            int row = idx >> 6, c2 = idx & 63;
            float2 v = ((const float2*)(M + (n0 + row) * DD))[c2];
            uint32_t h = pack_hi(v.x, v.y);
            ((uint32_t*)(g_Mh + (n0 + row) * DD))[c2] = h;
            *(uint32_t*)(smem + GT_A + row * 272 + c2 * 4) = h;
        }
        CP_WAIT0();
        __syncthreads();

        float acc[8][4];
#pragma unroll
        for (int j = 0; j < 8; j++)
#pragma unroll
            for (int q = 0; q < 4; q++) acc[j][q] = 0.f;

#pragma unroll 1
        for (int ks = 0; ks < 8; ks++) {
            int k0 = 16 * ks;
            uint32_t aH[4];
            LDSM_X4(aH, sbase + GT_A + (r0 + (l & 15)) * 272 + (k0 + halfOff) * 2);
#pragma unroll
            for (int np = 0; np < 4; np++) {
                uint32_t baddr = sbase + GT_WH + (uint32_t)(k0 + (l & 15)) * 272 +
                                 (uint32_t)(c0 + 16 * np + halfOff) * 2;
                uint32_t bH[4];
                LDSM_X4T(bH, baddr);
                mma_fp16(acc[2 * np],     aH, bH[0], bH[1]);
                mma_fp16(acc[2 * np + 1], aH, bH[2], bH[3]);
            }
        }

        // --- epilogue: alpha = rowdot(S, T) [smem], sat_out + hi split ---
        int rowA = r0 + g, rowB = rowA + 8;
        float p0 = 0.f, p1 = 0.f;
#pragma unroll
        for (int nt = 0; nt < 8; nt++) {
            int col = c0 + nt * 8 + 2 * t;
            float2 sa = *(const float2*)&sS[rowA * 132 + col];
            float2 sb = *(const float2*)&sS[rowB * 132 + col];
            p0 += sa.x * acc[nt][0] + sa.y * acc[nt][1];
            p1 += sb.x * acc[nt][2] + sb.y * acc[nt][3];
        }
        p0 += __shfl_xor_sync(0xffffffffu, p0, 1);
        p0 += __shfl_xor_sync(0xffffffffu, p0, 2);
        p1 += __shfl_xor_sync(0xffffffffu, p1, 1);
        p1 += __shfl_xor_sync(0xffffffffu, p1, 2);
        if (t == 0) {
            s_red[nwp * 64 + rowA] = p0;
            s_red[nwp * 64 + rowB] = p1;
        }
        __syncthreads();

        float alA = s_red[rowA] + s_red[64 + rowA];
        float alB = s_red[rowB] + s_red[64 + rowB];
        size_t rA = n0 + rowA, rB = n0 + rowB;
#pragma unroll
        for (int nt = 0; nt < 8; nt++) {
            int col = c0 + nt * 8 + 2 * t;
            float2 sa = *(const float2*)&sS[rowA * 132 + col];
            __half2 mh = *(const __half2*)(smem + GT_A + rowA * 272 + col * 2);
            float2 ma = __half22float2(mh);
            float2 oa;
            oa.x = fmaf(alA, ma.x - sa.x, sa.x);
            oa.y = fmaf(alA, ma.y - sa.y, sa.y);
            *(float2*)(SO + rA * DD + col) = oa;
            *(uint32_t*)(g_Sh + rA * DD + col) = pack_hi(oa.x, oa.y);

            float2 sb = *(const float2*)&sS[rowB * 132 + col];
            __half2 mhb = *(const __half2*)(smem + GT_A + rowB * 272 + col * 2);
            float2 mb = __half22float2(mhb);
            float2 ob;
            ob.x = fmaf(alB, mb.x - sb.x, sb.x);
            ob.y = fmaf(alB, mb.y - sb.y, sb.y);
            *(float2*)(SO + rB * DD + col) = ob;
            *(uint32_t*)(g_Sh + rB * DD + col) = pack_hi(ob.x, ob.y);
        }
        __syncthreads();   // iter-n reads done before iter-n+1 staging
    }
}

// ======================= K2C GEMM (2-term, double-buffered gather) =========
#define GK_A0   0
#define GK_A1   17408
#define GK_WH   34816
#define GK_WL   69632
#define GK_SMEM 104448

__global__ __launch_bounds__(256, 2)
void gemm_K2C_kernel() {
    extern __shared__ char smem[];
    uint32_t sbase = smem_u32(smem);
    int tid = threadIdx.x;
    int w = tid >> 5, l = tid & 31;

    // stage W2 split ONCE (first loop-top syncthreads publishes it)
    for (int idx = tid; idx < 2048; idx += 256) {
        int row = idx >> 4, c8 = idx & 15;
        *(uint4*)(smem + GK_WH + row * 272 + c8 * 16) = *(const uint4*)(g_W2h + row * DD + c8 * 8);
        *(uint4*)(smem + GK_WL + row * 272 + c8 * 16) = *(const uint4*)(g_W2l + row * DD + c8 * 8);
    }

    int mw = w & 3, nwp = w >> 2;
    int r0 = mw * 16, c0 = nwp * 64;
    int g = l >> 2, t = l & 3;
    uint32_t halfOff = (uint32_t)((l >> 4) << 3);

    const int TOT = BB * 4, G = gridDim.x;
    int item = blockIdx.x;
    while (item < TOT && ((item & 3) * 64 >= g_nv[item >> 2])) item += G;

    int buf = 0;
    if (item < TOT) {
        int b = item >> 2, pos0 = (item & 3) * 64;
        for (int idx = tid; idx < 1024; idx += 256) {
            int row = idx >> 4, c8 = idx & 15;
            int j = g_idx[b * NN + pos0 + row];
            CP_ASYNC16(sbase + GK_A0 + row * 272 + c8 * 16,
                       g_Sh + ((size_t)b * NN + j) * DD + c8 * 8);
        }
        CP_COMMIT();
    }

    while (item < TOT) {
        int next = item + G;
        while (next < TOT && ((next & 3) * 64 >= g_nv[next >> 2])) next += G;

        CP_WAIT0();
        __syncthreads();   // A[buf] visible; prior MMA readers of A[buf^1] done

        if (next < TOT) {
            int nb = next >> 2, npos0 = (next & 3) * 64;
            uint32_t dst = sbase + ((buf ^ 1) ? GK_A1 : GK_A0);
            for (int idx = tid; idx < 1024; idx += 256) {
                int row = idx >> 4, c8 = idx & 15;
                int j = g_idx[nb * NN + npos0 + row];
                CP_ASYNC16(dst + row * 272 + c8 * 16,
                           g_Sh + ((size_t)nb * NN + j) * DD + c8 * 8);
            }
            CP_COMMIT();
        }

        int b = item >> 2, pos0 = (item & 3) * 64;
        uint32_t abase = sbase + (buf ? GK_A1 : GK_A0);

        float acc[8][4];
#pragma unroll
        for (int j = 0; j < 8; j++)
#pragma unroll
            for (int q = 0; q < 4; q++) acc[j][q] = 0.f;

#pragma unroll 1
        for (int ks = 0; ks < 8; ks++) {
            int k0 = 16 * ks;
            uint32_t aH[4];
            LDSM_X4(aH, abase + (r0 + (l & 15)) * 272 + (k0 + halfOff) * 2);
#pragma unroll
            for (int np = 0; np < 4; np++) {
                uint32_t baddr = sbase + GK_WH + (uint32_t)(k0 + (l & 15)) * 272 +
                                 (uint32_t)(c0 + 16 * np + halfOff) * 2;
                uint32_t bH[4], bL[4];
                LDSM_X4T(bH, baddr);
                LDSM_X4T(bL, baddr + (GK_WL - GK_WH));
                mma_fp16(acc[2 * np],     aH, bH[0], bH[1]);
                mma_fp16(acc[2 * np],     aH, bL[0], bL[1]);
                mma_fp16(acc[2 * np + 1], aH, bH[2], bH[3]);
                mma_fp16(acc[2 * np + 1], aH, bL[2], bL[3]);
            }
        }

#pragma unroll
        for (int nt = 0; nt < 8; nt++) {
            size_t rowA = (size_t)b * NN + pos0 + r0 + g;
            size_t rowB = rowA + 8;
            int col = c0 + nt * 8 + 2 * t;
            uint32_t h, lo;
            split_pack(acc[nt][0], acc[nt][1], h, lo);
            *(uint32_t*)(g_Kh + rowA * DD + col) = h;
            *(uint32_t*)(g_Kl + rowA * DD + col) = lo;
            split_pack(acc[nt][2], acc[nt][3], h, lo);
            *(uint32_t*)(g_Kh + rowB * DD + col) = h;
            *(uint32_t*)(g_Kl + rowB * DD + col) = lo;
        }
        item = next;
        buf ^= 1;
    }
}

// ======================= fused attention (compacted keys) ==================
// CTA = (batch b, 128 i-rows).  512 threads = 16 warps: 8 m-warps x 2 n-warps.
// beta phase: Q hi [0,34816), K hi [34816,104448), K lo [104448,174080).
// PV phase:   P (528-stride) [0,67584) over dead Q + K-head,
//             V hi [69632,139264) over dead K (cp.async during softmax).
#define SM_QH  0
#define SM_KH  34816
#define SM_KL  104448
#define SM_PH  0
#define SM_VH  69632
#define SMEM_ATTN 174080

#define BETA_CHUNK(ACC, CBASE, NSTEPS) do {                                         \
    _Pragma("unroll")                                                               \
    for (int ks = 0; ks < 8; ks++) {                                                \
        int k0 = 16 * ks;                                                           \
        uint32_t aH[4];                                                             \
        LDSM_X4(aH, sbase + SM_QH + aRow * 272 + (k0 + halfOff) * 2);               \
        _Pragma("unroll")                                                           \
        for (int np = 0; np < 4; np++) {                                            \
            if (np >= (NSTEPS)) break;                                              \
            uint32_t baddr = sbase + SM_KH +                                        \
                (uint32_t)((CBASE) + nw * 64 + 16 * np + bRowBase) * 272 +          \
                (k0 + bColHalf) * 2;                                                \
            uint32_t bH[4], bL[4];                                                  \
            LDSM_X4(bH, baddr);                                                     \
            LDSM_X4(bL, baddr + (SM_KL - SM_KH));                                   \
            mma_fp16(ACC[2 * np],     aH, bH[0], bH[1]);                            \
            mma_fp16(ACC[2 * np],     aH, bL[0], bL[1]);                            \
            mma_fp16(ACC[2 * np + 1], aH, bH[2], bH[3]);                            \
            mma_fp16(ACC[2 * np + 1], aH, bL[2], bL[3]);                            \
        }                                                                           \
    }                                                                               \
} while (0)

__global__ __launch_bounds__(512, 1)
void attn_kernel(float* __restrict__ O) {
    extern __shared__ char smem[];
    __shared__ float s_bias[256];
    __shared__ float s_red[512];
    __shared__ int s_idx[256];
    uint32_t sbase = smem_u32(smem);

    int tid = threadIdx.x;
    int w = tid >> 5, l = tid & 31;
    int g = l >> 2, t = l & 3;
    int mw = w & 7, nw = w >> 3;
    int b = blockIdx.y;
    int i0 = blockIdx.x * 128;
    size_t boff = (size_t)b * NN * DD;

    int nv = g_nv[b];
    int kpadN = (nv + 15) & ~15;

    if (tid < 256) {
        s_idx[tid] = g_idx[b * NN + tid];
        s_bias[tid] = (tid < nv) ? 0.f : -1e30f;
    }

    // stage Q hi (cp.async)
    for (int idx = tid; idx < 128 * 16; idx += 512) {
        int row = idx >> 4, c8 = idx & 15;
        CP_ASYNC16(sbase + SM_QH + row * 272 + c8 * 16,
                   g_Mh + boff + (size_t)(i0 + row) * DD + c8 * 8);
    }
    // stage K compact rows [0, kpadN) (cp.async; zero pads via plain stores)
    {
        uint4 z = make_uint4(0, 0, 0, 0);
        for (int idx = tid; idx < kpadN * 16; idx += 512) {
            int row = idx >> 4, c8 = idx & 15;
            if (row < nv) {
                size_t src = boff + (size_t)row * DD + c8 * 8;
                CP_ASYNC16(sbase + SM_KH + row * 272 + c8 * 16, g_Kh + src);
                CP_ASYNC16(sbase + SM_KL + row * 272 + c8 * 16, g_Kl + src);
            } else {
                *(uint4*)(smem + SM_KH + row * 272 + c8 * 16) = z;
                *(uint4*)(smem + SM_KL + row * 272 + c8 * 16) = z;
            }
        }
    }
    CP_COMMIT();
    CP_WAIT0();
    __syncthreads();

    // --- beta GEMM over valid 16-col tiles only (2-term: Qh*(Kh+Kl)) ---
    uint32_t aRow = (uint32_t)(16 * mw + (l & 15));
    uint32_t halfOff = (uint32_t)((l >> 4) << 3);
    uint32_t bRowBase = (uint32_t)(((l >> 4) << 3) + (l & 7));
    uint32_t bColHalf = (uint32_t)(((l >> 3) & 1) << 3);

    int base0 = nw * 64, base1 = 128 + nw * 64;
    int ns0 = min(4, max(0, (kpadN - base0) >> 4));
    int ns1 = min(4, max(0, (kpadN - base1) >> 4));

    float acc0[8][4], acc1[8][4];
#pragma unroll
    for (int j = 0; j < 8; j++)
#pragma unroll
        for (int q = 0; q < 4; q++) { acc0[j][q] = 0.f; acc1[j][q] = 0.f; }

    if (ns0 > 0) BETA_CHUNK(acc0, 0, ns0);
    if (ns1 > 0) BETA_CHUNK(acc1, 128, ns1);

    // --- masked softmax (rows rowA, rowB in 0..127) ---
    int rowA = 16 * mw + g, rowB = rowA + 8;
    float mx0 = -3.0e38f, mx1 = -3.0e38f;
#pragma unroll
    for (int j = 0; j < 8; j++) {
        float2 bv = *(const float2*)&s_bias[nw * 64 + j * 8 + 2 * t];
        acc0[j][0] += bv.x; acc0[j][1] += bv.y;
        acc0[j][2] += bv.x; acc0[j][3] += bv.y;
        mx0 = fmaxf(mx0, fmaxf(acc0[j][0], acc0[j][1]));
        mx1 = fmaxf(mx1, fmaxf(acc0[j][2], acc0[j][3]));
    }
    if (kpadN > 128) {
#pragma unroll
        for (int j = 0; j < 8; j++) {
            float2 bv = *(const float2*)&s_bias[128 + nw * 64 + j * 8 + 2 * t];
            acc1[j][0] += bv.x; acc1[j][1] += bv.y;
            acc1[j][2] += bv.x; acc1[j][3] += bv.y;
            mx0 = fmaxf(mx0, fmaxf(acc1[j][0], acc1[j][1]));
            mx1 = fmaxf(mx1, fmaxf(acc1[j][2], acc1[j][3]));
        }
    }
    mx0 = fmaxf(mx0, __shfl_xor_sync(0xffffffffu, mx0, 1));
    mx0 = fmaxf(mx0, __shfl_xor_sync(0xffffffffu, mx0, 2));
    mx1 = fmaxf(mx1, __shfl_xor_sync(0xffffffffu, mx1, 1));
    mx1 = fmaxf(mx1, __shfl_xor_sync(0xffffffffu, mx1, 2));
    if (t == 0) {
        s_red[nw * 128 + rowA] = mx0;
        s_red[nw * 128 + rowB] = mx1;
    }
    __syncthreads();   // <-- every thread past beta: K region retired

    // --- prefetch V (gathered, hi only) into dead K region via cp.async ---
    {
        uint4 z = make_uint4(0, 0, 0, 0);
        for (int idx = tid; idx < kpadN * 16; idx += 512) {
            int row = idx >> 4, c8 = idx & 15;
            if (row < nv) {
                CP_ASYNC16(sbase + SM_VH + row * 272 + c8 * 16,
                           g_Mh + boff + (size_t)s_idx[row] * DD + c8 * 8);
            } else {
                *(uint4*)(smem + SM_VH + row * 272 + c8 * 16) = z;
            }
        }
        CP_COMMIT();
    }

    // --- softmax continues while V streams in ---
    float M0 = fmaxf(s_red[rowA], s_red[128 + rowA]);
    float M1 = fmaxf(s_red[rowB], s_red[128 + rowB]);
    float s0 = 0.f, s1 = 0.f;
#pragma unroll
    for (int j = 0; j < 8; j++) {
        acc0[j][0] = __expf(acc0[j][0] - M0); s0 += acc0[j][0];
        acc0[j][1] = __expf(acc0[j][1] - M0); s0 += acc0[j][1];
        acc0[j][2] = __expf(acc0[j][2] - M1); s1 += acc0[j][2];
        acc0[j][3] = __expf(acc0[j][3] - M1); s1 += acc0[j][3];
    }
    if (kpadN > 128) {
#pragma unroll
        for (int j = 0; j < 8; j++) {
            acc1[j][0] = __expf(acc1[j][0] - M0); s0 += acc1[j][0];
            acc1[j][1] = __expf(acc1[j][1] - M0); s0 += acc1[j][1];
            acc1[j][2] = __expf(acc1[j][2] - M1); s1 += acc1[j][2];
            acc1[j][3] = __expf(acc1[j][3] - M1); s1 += acc1[j][3];
        }
    }
    s0 += __shfl_xor_sync(0xffffffffu, s0, 1);
    s0 += __shfl_xor_sync(0xffffffffu, s0, 2);
    s1 += __shfl_xor_sync(0xffffffffu, s1, 1);
    s1 += __shfl_xor_sync(0xffffffffu, s1, 2);
    __syncthreads();
    if (t == 0) {
        s_red[256 + nw * 128 + rowA] = s0;
        s_red[256 + nw * 128 + rowB] = s1;
    }
    __syncthreads();
    float inv0 = __fdividef(1.f, s_red[256 + rowA] + s_red[256 + 128 + rowA]);
    float inv1 = __fdividef(1.f, s_red[256 + rowB] + s_red[256 + 128 + rowB]);

    // --- write P (fp16 hi only) over dead Q + K-head region ---
    {
        char* ph = smem + SM_PH;
#pragma unroll
        for (int j = 0; j < 8; j++) {
            int col = nw * 64 + j * 8 + 2 * t;
            *(uint32_t*)(ph + rowA * 528 + col * 2) = pack_hi(acc0[j][0] * inv0, acc0[j][1] * inv0);
            *(uint32_t*)(ph + rowB * 528 + col * 2) = pack_hi(acc0[j][2] * inv1, acc0[j][3] * inv1);
        }
        if (kpadN > 128) {
#pragma unroll
            for (int j = 0; j < 8; j++) {
                int col = 128 + nw * 64 + j * 8 + 2 * t;
                *(uint32_t*)(ph + rowA * 528 + col * 2) = pack_hi(acc1[j][0] * inv0, acc1[j][1] * inv0);
                *(uint32_t*)(ph + rowB * 528 + col * 2) = pack_hi(acc1[j][2] * inv1, acc1[j][3] * inv1);
            }
        }
    }
    CP_WAIT0();      // V fully resident
    __syncthreads(); // P + V visible to all warps

    // --- PV GEMM: 1-term (P hi * V hi), k up to kpadN ---
    int d0 = 64 * nw;
    float o[8][4];
#pragma unroll
    for (int i = 0; i < 8; i++)
#pragma unroll
        for (int j = 0; j < 4; j++) o[i][j] = 0.f;

    int ksteps = kpadN >> 4;
#pragma unroll 1
    for (int ks = 0; ks < ksteps; ks++) {
        int k0 = 16 * ks;
        uint32_t aH[4];
        LDSM_X4(aH, sbase + SM_PH + aRow * 528 + (k0 + halfOff) * 2);
#pragma unroll
        for (int np = 0; np < 4; np++) {
            uint32_t baddr = sbase + SM_VH + (uint32_t)(k0 + (l & 15)) * 272 +
                             (uint32_t)(d0 + 16 * np + halfOff) * 2;
            uint32_t bH[4];
            LDSM_X4T(bH, baddr);
            mma_fp16(o[2 * np],     aH, bH[0], bH[1]);
            mma_fp16(o[2 * np + 1], aH, bH[2], bH[3]);
        }
    }

    float* Ob = O + ((size_t)b * NN + i0) * DD;
#pragma unroll
    for (int nt = 0; nt < 8; nt++) {
        int col = d0 + 8 * nt + 2 * t;
        *(float2*)&Ob[(size_t)rowA * DD + col] = make_float2(o[nt][0], o[nt][1]);
        *(float2*)&Ob[(size_t)rowB * DD + col] = make_float2(o[nt][2], o[nt][3]);
    }
}

// ---------------------------------------------------------------------------
extern "C" void kernel_launch(void* const* d_in, const int* in_sizes, int n_in,
                              void* d_out, int out_size) {
    (void)in_sizes; (void)n_in; (void)out_size;
    const float* mirror    = (const float*)d_in[0];
    const float* satellite = (const float*)d_in[1];
    const void*  mask      = d_in[2];
    const float* Wq1 = (const float*)d_in[3];
    const float* Wk1 = (const float*)d_in[4];
    const float* Wq2 = (const float*)d_in[5];
    const float* Wk2 = (const float*)d_in[6];
    float* sat_out = (float*)d_out;
    float* mir_out = (float*)d_out + BND;

    cudaFuncSetAttribute(gemm_T_fused,    cudaFuncAttributeMaxDynamicSharedMemorySize, GT_SMEM);
    cudaFuncSetAttribute(gemm_K2C_kernel, cudaFuncAttributeMaxDynamicSharedMemorySize, GK_SMEM);
    cudaFuncSetAttribute(attn_kernel,     cudaFuncAttributeMaxDynamicSharedMemorySize, SMEM_ATTN);

    decode_compact_kernel<<<BB, 256>>>(mask);
    prep_w_kernel<<<dim3(128, 2), 512>>>(Wq1, Wk1, Wq2, Wk2);

    gemm_T_fused<<<296, 256, GT_SMEM>>>(mirror, satellite, sat_out);
    gemm_K2C_kernel<<<296, 256, GK_SMEM>>>();
    attn_kernel<<<dim3(NN / 128, BB), 512, SMEM_ATTN>>>(mir_out);
}

// round 17
// speedup vs baseline: 2.1457x; 1.1004x over previous
#include <cuda_runtime.h>
#include <cuda_fp16.h>
#include <cstdint>

// Problem constants
#define BB 512
#define NN 256
#define DD 128
#define BND ((size_t)BB * NN * DD)

static __device__ __half g_W1h[DD * DD];
static __device__ __half g_W2h[DD * DD], g_W2l[DD * DD];
static __device__ __half g_Mh[BND];                  // mirror hi
static __device__ __half g_Sh[BND];                  // sat_out hi
static __device__ __half g_Kh[BND], g_Kl[BND];       // K2C split (COMPACT rows)
static __device__ int g_idx[BB * NN];                // compact pos -> j
static __device__ int g_nv[BB];                      // valid count per batch
static __device__ int g_items[BB * 4];               // dense K2C work list
static __device__ int g_nitems;

#define SCALE 0.08838834764831845f  // 1/sqrt(128)

// ============================ PTX helpers ==================================
__device__ __forceinline__ uint32_t smem_u32(const void* p) {
    uint32_t a;
    asm("{ .reg .u64 t; cvta.to.shared.u64 t, %1; cvt.u32.u64 %0, t; }" : "=r"(a) : "l"(p));
    return a;
}

#define LDSM_X4(r, a) \
    asm volatile("ldmatrix.sync.aligned.m8n8.x4.shared.b16 {%0,%1,%2,%3}, [%4];" \
        : "=r"((r)[0]), "=r"((r)[1]), "=r"((r)[2]), "=r"((r)[3]) : "r"(a))
#define LDSM_X4T(r, a) \
    asm volatile("ldmatrix.sync.aligned.m8n8.x4.trans.shared.b16 {%0,%1,%2,%3}, [%4];" \
        : "=r"((r)[0]), "=r"((r)[1]), "=r"((r)[2]), "=r"((r)[3]) : "r"(a))

#define CP_ASYNC16(dst, src) \
    asm volatile("cp.async.cg.shared.global [%0], [%1], 16;" :: "r"(dst), "l"(src) : "memory")
#define CP_COMMIT() asm volatile("cp.async.commit_group;" ::: "memory")
#define CP_WAIT0()  asm volatile("cp.async.wait_group 0;" ::: "memory")

__device__ __forceinline__ void mma_fp16(float* c, const uint32_t* a, uint32_t b0, uint32_t b1) {
    asm volatile(
        "mma.sync.aligned.m16n8k16.row.col.f32.f16.f16.f32 "
        "{%0,%1,%2,%3}, {%4,%5,%6,%7}, {%8,%9}, {%0,%1,%2,%3};"
        : "+f"(c[0]), "+f"(c[1]), "+f"(c[2]), "+f"(c[3])
        : "r"(a[0]), "r"(a[1]), "r"(a[2]), "r"(a[3]), "r"(b0), "r"(b1));
}

__device__ __forceinline__ void split_pack(float x, float y, uint32_t& h, uint32_t& l) {
    __half hx = __float2half(x);
    __half hy = __float2half(y);
    __half lx = __float2half(x - __half2float(hx));
    __half ly = __float2half(y - __half2float(hy));
    __half2 hh; hh.x = hx; hh.y = hy;
    __half2 ll; ll.x = lx; ll.y = ly;
    h = *(uint32_t*)&hh;
    l = *(uint32_t*)&ll;
}

__device__ __forceinline__ uint32_t pack_hi(float x, float y) {
    __half2 hh; hh.x = __float2half(x); hh.y = __float2half(y);
    return *(uint32_t*)&hh;
}

// ======================= weight contraction (scaled + split) ===============
// Runs FIRST; block (0,0) also zeroes the K2C work-list counter.
__global__ void prep_w_kernel(const float* __restrict__ Wq1, const float* __restrict__ Wk1,
                              const float* __restrict__ Wq2, const float* __restrict__ Wk2) {
    if (blockIdx.x == 0 && blockIdx.y == 0 && threadIdx.x == 0) g_nitems = 0;
    int a = blockIdx.x;
    int c = threadIdx.x & 127, kc = threadIdx.x >> 7;
    __shared__ float red[512];
    const float* X = (blockIdx.y == 0) ? Wq1 : Wq2;
    const float* Y = (blockIdx.y == 0) ? Wk1 : Wk2;
    float acc = 0.f;
#pragma unroll 8
    for (int k = kc * 32; k < kc * 32 + 32; k++)
        acc = fmaf(X[k * DD + c], Y[k * DD + a], acc);
    red[kc * 128 + c] = acc;
    __syncthreads();
    if (kc == 0) {
        float v = (red[c] + red[128 + c]) + (red[256 + c] + red[384 + c]);
        v *= SCALE;
        __half h = __float2half(v);
        __half lo = __float2half(v - __half2float(h));
        int idx = a * DD + c;
        if (blockIdx.y == 0) { g_W1h[idx] = h; }
        else                 { g_W2h[idx] = h; g_W2l[idx] = lo; }
    }
}

// ======================= mask decode + compaction (self-detecting) =========
__global__ void decode_compact_kernel(const void* __restrict__ m) {
    int b = blockIdx.x;
    int tid = threadIdx.x;
    int w = tid >> 5, l = tid & 31;
    __shared__ int wcnt[8], woff[8], s_w1;
    if (tid == 0) s_w1 = 0;
    __syncthreads();
    if (tid < 64) {
        unsigned int wd = ((const unsigned int*)m)[b * 64 + tid];
        if (wd != 0u && wd != 1u && wd != 0x3F800000u) s_w1 = 1;
    }
    __syncthreads();
    int width1 = s_w1;

    int i = b * NN + tid;
    int valid;
    if (width1) valid = (((const unsigned char*)m)[i] != 0);
    else        valid = (((const unsigned int*)m)[i] != 0u);
    unsigned bal = __ballot_sync(0xffffffffu, valid);
    int pre = __popc(bal & ((1u << l) - 1u));
    if (l == 31) wcnt[w] = __popc(bal);
    g_idx[i] = 0;   // prefill pads with a safe (valid) index
    __syncthreads();
    if (tid == 0) {
        int s = 0;
        for (int k = 0; k < 8; k++) { woff[k] = s; s += wcnt[k]; }
        g_nv[b] = s;
        int nq = (s + 63) >> 6;
        int base = atomicAdd(&g_nitems, nq);
        for (int q = 0; q < nq; q++) g_items[base + q] = (b << 2) | q;
    }
    __syncthreads();
    if (valid) g_idx[b * NN + woff[w] + pre] = tid;
}

// ======================= fused: M convert + T GEMM + gate + sat_out ========
#define GT_A    0          // Mh tile: 64 x 272 B
#define GT_WH   17408      // W1h: 128 x 272 B
#define GT_S    52224      // S fp32: 64 x 132 floats (528 B rows)
#define GT_SMEM 86016

__global__ __launch_bounds__(256, 2)
void gemm_T_fused(const float* __restrict__ M, const float* __restrict__ S,
                  float* __restrict__ SO) {
    extern __shared__ char smem[];
    __shared__ float s_red[128];
    uint32_t sbase = smem_u32(smem);
    float* sS = (float*)(smem + GT_S);
    int tid = threadIdx.x;
    int w = tid >> 5, l = tid & 31;

    // stage W1h ONCE
    for (int idx = tid; idx < 2048; idx += 256) {
        int row = idx >> 4, c8 = idx & 15;
        *(uint4*)(smem + GT_WH + row * 272 + c8 * 16) =
            *(const uint4*)(g_W1h + row * DD + c8 * 8);
    }

    int mw = w & 3, nwp = w >> 2;
    int r0 = mw * 16, c0 = nwp * 64;
    int g = l >> 2, t = l & 3;
    uint32_t halfOff = (uint32_t)((l >> 4) << 3);

    for (int item = blockIdx.x; item < 2048; item += gridDim.x) {
        size_t n0 = (size_t)item * 64;

        // S -> smem via cp.async
        for (int idx = tid; idx < 2048; idx += 256) {
            int row = idx >> 5, c4 = idx & 31;
            CP_ASYNC16(sbase + GT_S + row * 528 + c4 * 16,
                       S + (n0 + row) * DD + c4 * 4);
        }
        CP_COMMIT();

        // M fp32 -> fp16 hi (global + smem tile), overlapping the S DMA
        for (int idx = tid; idx < 4096; idx += 256) {
            int row = idx >> 6, c2 = idx & 63;
            float2 v = ((const float2*)(M + (n0 + row) * DD))[c2];
            uint32_t h = pack_hi(v.x, v.y);
            ((uint32_t*)(g_Mh + (n0 + row) * DD))[c2] = h;
            *(uint32_t*)(smem + GT_A + row * 272 + c2 * 4) = h;
        }
        CP_WAIT0();
        __syncthreads();

        float acc[8][4];
#pragma unroll
        for (int j = 0; j < 8; j++)
#pragma unroll
            for (int q = 0; q < 4; q++) acc[j][q] = 0.f;

#pragma unroll 1
        for (int ks = 0; ks < 8; ks++) {
            int k0 = 16 * ks;
            uint32_t aH[4];
            LDSM_X4(aH, sbase + GT_A + (r0 + (l & 15)) * 272 + (k0 + halfOff) * 2);
#pragma unroll
            for (int np = 0; np < 4; np++) {
                uint32_t baddr = sbase + GT_WH + (uint32_t)(k0 + (l & 15)) * 272 +
                                 (uint32_t)(c0 + 16 * np + halfOff) * 2;
                uint32_t bH[4];
                LDSM_X4T(bH, baddr);
                mma_fp16(acc[2 * np],     aH, bH[0], bH[1]);
                mma_fp16(acc[2 * np + 1], aH, bH[2], bH[3]);
            }
        }

        // --- epilogue: alpha = rowdot(S, T) [smem], sat_out + hi split ---
        int rowA = r0 + g, rowB = rowA + 8;
        float p0 = 0.f, p1 = 0.f;
#pragma unroll
        for (int nt = 0; nt < 8; nt++) {
            int col = c0 + nt * 8 + 2 * t;
            float2 sa = *(const float2*)&sS[rowA * 132 + col];
            float2 sb = *(const float2*)&sS[rowB * 132 + col];
            p0 += sa.x * acc[nt][0] + sa.y * acc[nt][1];
            p1 += sb.x * acc[nt][2] + sb.y * acc[nt][3];
        }
        p0 += __shfl_xor_sync(0xffffffffu, p0, 1);
        p0 += __shfl_xor_sync(0xffffffffu, p0, 2);
        p1 += __shfl_xor_sync(0xffffffffu, p1, 1);
        p1 += __shfl_xor_sync(0xffffffffu, p1, 2);
        if (t == 0) {
            s_red[nwp * 64 + rowA] = p0;
            s_red[nwp * 64 + rowB] = p1;
        }
        __syncthreads();

        float alA = s_red[rowA] + s_red[64 + rowA];
        float alB = s_red[rowB] + s_red[64 + rowB];
        size_t rA = n0 + rowA, rB = n0 + rowB;
#pragma unroll
        for (int nt = 0; nt < 8; nt++) {
            int col = c0 + nt * 8 + 2 * t;
            float2 sa = *(const float2*)&sS[rowA * 132 + col];
            __half2 mh = *(const __half2*)(smem + GT_A + rowA * 272 + col * 2);
            float2 ma = __half22float2(mh);
            float2 oa;
            oa.x = fmaf(alA, ma.x - sa.x, sa.x);
            oa.y = fmaf(alA, ma.y - sa.y, sa.y);
            *(float2*)(SO + rA * DD + col) = oa;
            *(uint32_t*)(g_Sh + rA * DD + col) = pack_hi(oa.x, oa.y);

            float2 sb = *(const float2*)&sS[rowB * 132 + col];
            __half2 mhb = *(const __half2*)(smem + GT_A + rowB * 272 + col * 2);
            float2 mb = __half22float2(mhb);
            float2 ob;
            ob.x = fmaf(alB, mb.x - sb.x, sb.x);
            ob.y = fmaf(alB, mb.y - sb.y, sb.y);
            *(float2*)(SO + rB * DD + col) = ob;
            *(uint32_t*)(g_Sh + rB * DD + col) = pack_hi(ob.x, ob.y);
        }
        __syncthreads();   // iter-n reads done before iter-n+1 staging
    }
}

// ======================= K2C GEMM (2-term, dense list, 32x32 warp tile) ====
#define GK_A0   0
#define GK_A1   17408
#define GK_WH   34816
#define GK_WL   69632
#define GK_SMEM 104448

__global__ __launch_bounds__(256, 2)
void gemm_K2C_kernel() {
    extern __shared__ char smem[];
    uint32_t sbase = smem_u32(smem);
    int tid = threadIdx.x;
    int w = tid >> 5, l = tid & 31;

    // stage W2 split ONCE (first loop-top syncthreads publishes it)
    for (int idx = tid; idx < 2048; idx += 256) {
        int row = idx >> 4, c8 = idx & 15;
        *(uint4*)(smem + GK_WH + row * 272 + c8 * 16) = *(const uint4*)(g_W2h + row * DD + c8 * 8);
        *(uint4*)(smem + GK_WL + row * 272 + c8 * 16) = *(const uint4*)(g_W2l + row * DD + c8 * 8);
    }

    int mw = w & 1, nwp = w >> 1;          // 2 m-warps x 4 n-warps
    int r0 = mw * 32, c0 = nwp * 32;
    int g = l >> 2, t = l & 3;
    uint32_t halfOff = (uint32_t)((l >> 4) << 3);

    const int G = gridDim.x;
    int n_items = g_nitems;
    int item = blockIdx.x;
    int buf = 0;

    if (item < n_items) {
        int code = g_items[item];
        int b = code >> 2, pos0 = (code & 3) * 64;
        for (int idx = tid; idx < 1024; idx += 256) {
            int row = idx >> 4, c8 = idx & 15;
            int j = g_idx[b * NN + pos0 + row];
            CP_ASYNC16(sbase + GK_A0 + row * 272 + c8 * 16,
                       g_Sh + ((size_t)b * NN + j) * DD + c8 * 8);
        }
        CP_COMMIT();
    }

    while (item < n_items) {
        int next = item + G;

        CP_WAIT0();
        __syncthreads();   // A[buf] visible; prior MMA readers of A[buf^1] done

        if (next < n_items) {
            int code = g_items[next];
            int nb = code >> 2, npos0 = (code & 3) * 64;
            uint32_t dst = sbase + ((buf ^ 1) ? GK_A1 : GK_A0);
            for (int idx = tid; idx < 1024; idx += 256) {
                int row = idx >> 4, c8 = idx & 15;
                int j = g_idx[nb * NN + npos0 + row];
                CP_ASYNC16(dst + row * 272 + c8 * 16,
                           g_Sh + ((size_t)nb * NN + j) * DD + c8 * 8);
            }
            CP_COMMIT();
        }

        int code = g_items[item];
        int b = code >> 2, pos0 = (code & 3) * 64;
        uint32_t abase = sbase + (buf ? GK_A1 : GK_A0);

        float acc[2][4][4];
#pragma unroll
        for (int mt = 0; mt < 2; mt++)
#pragma unroll
            for (int j = 0; j < 4; j++)
#pragma unroll
                for (int q = 0; q < 4; q++) acc[mt][j][q] = 0.f;

#pragma unroll 1
        for (int ks = 0; ks < 8; ks++) {
            int k0 = 16 * ks;
            uint32_t aH0[4], aH1[4];
            uint32_t aaddr = abase + (r0 + (l & 15)) * 272 + (k0 + halfOff) * 2;
            LDSM_X4(aH0, aaddr);
            LDSM_X4(aH1, aaddr + 16 * 272);
#pragma unroll
            for (int np = 0; np < 2; np++) {
                uint32_t baddr = sbase + GK_WH + (uint32_t)(k0 + (l & 15)) * 272 +
                                 (uint32_t)(c0 + 16 * np + halfOff) * 2;
                uint32_t bH[4], bL[4];
                LDSM_X4T(bH, baddr);
                LDSM_X4T(bL, baddr + (GK_WL - GK_WH));
                mma_fp16(acc[0][2 * np],     aH0, bH[0], bH[1]);
                mma_fp16(acc[0][2 * np],     aH0, bL[0], bL[1]);
                mma_fp16(acc[0][2 * np + 1], aH0, bH[2], bH[3]);
                mma_fp16(acc[0][2 * np + 1], aH0, bL[2], bL[3]);
                mma_fp16(acc[1][2 * np],     aH1, bH[0], bH[1]);
                mma_fp16(acc[1][2 * np],     aH1, bL[0], bL[1]);
                mma_fp16(acc[1][2 * np + 1], aH1, bH[2], bH[3]);
                mma_fp16(acc[1][2 * np + 1], aH1, bL[2], bL[3]);
            }
        }

#pragma unroll
        for (int mt = 0; mt < 2; mt++)
#pragma unroll
            for (int nt = 0; nt < 4; nt++) {
                size_t rowA = (size_t)b * NN + pos0 + r0 + mt * 16 + g;
                size_t rowB = rowA + 8;
                int col = c0 + nt * 8 + 2 * t;
                uint32_t h, lo;
                split_pack(acc[mt][nt][0], acc[mt][nt][1], h, lo);
                *(uint32_t*)(g_Kh + rowA * DD + col) = h;
                *(uint32_t*)(g_Kl + rowA * DD + col) = lo;
                split_pack(acc[mt][nt][2], acc[mt][nt][3], h, lo);
                *(uint32_t*)(g_Kh + rowB * DD + col) = h;
                *(uint32_t*)(g_Kl + rowB * DD + col) = lo;
            }
        item = next;
        buf ^= 1;
    }
}

// ======================= fused attention (compacted keys) ==================
#define SM_QH  0
#define SM_KH  34816
#define SM_KL  104448
#define SM_PH  0
#define SM_VH  69632
#define SMEM_ATTN 174080

#define BETA_CHUNK(ACC, CBASE, NSTEPS) do {                                         \
    _Pragma("unroll")                                                               \
    for (int ks = 0; ks < 8; ks++) {                                                \
        int k0 = 16 * ks;                                                           \
        uint32_t aH[4];                                                             \
        LDSM_X4(aH, sbase + SM_QH + aRow * 272 + (k0 + halfOff) * 2);               \
        _Pragma("unroll")                                                           \
        for (int np = 0; np < 4; np++) {                                            \
            if (np >= (NSTEPS)) break;                                              \
            uint32_t baddr = sbase + SM_KH +                                        \
                (uint32_t)((CBASE) + nw * 64 + 16 * np + bRowBase) * 272 +          \
                (k0 + bColHalf) * 2;                                                \
            uint32_t bH[4], bL[4];                                                  \
            LDSM_X4(bH, baddr);                                                     \
            LDSM_X4(bL, baddr + (SM_KL - SM_KH));                                   \
            mma_fp16(ACC[2 * np],     aH, bH[0], bH[1]);                            \
            mma_fp16(ACC[2 * np],     aH, bL[0], bL[1]);                            \
            mma_fp16(ACC[2 * np + 1], aH, bH[2], bH[3]);                            \
            mma_fp16(ACC[2 * np + 1], aH, bL[2], bL[3]);                            \
        }                                                                           \
    }                                                                               \
} while (0)

__global__ __launch_bounds__(512, 1)
void attn_kernel(float* __restrict__ O) {
    extern __shared__ char smem[];
    __shared__ float s_bias[256];
    __shared__ float s_red[512];
    __shared__ int s_idx[256];
    uint32_t sbase = smem_u32(smem);

    int tid = threadIdx.x;
    int w = tid >> 5, l = tid & 31;
    int g = l >> 2, t = l & 3;
    int mw = w & 7, nw = w >> 3;
    int b = blockIdx.y;
    int i0 = blockIdx.x * 128;
    size_t boff = (size_t)b * NN * DD;

    int nv = g_nv[b];
    int kpadN = (nv + 15) & ~15;

    if (tid < 256) {
        s_idx[tid] = g_idx[b * NN + tid];
        s_bias[tid] = (tid < nv) ? 0.f : -1e30f;
    }

    // stage Q hi (cp.async)
    for (int idx = tid; idx < 128 * 16; idx += 512) {
        int row = idx >> 4, c8 = idx & 15;
        CP_ASYNC16(sbase + SM_QH + row * 272 + c8 * 16,
                   g_Mh + boff + (size_t)(i0 + row) * DD + c8 * 8);
    }
    // stage K compact rows [0, kpadN) (cp.async; zero pads via plain stores)
    {
        uint4 z = make_uint4(0, 0, 0, 0);
        for (int idx = tid; idx < kpadN * 16; idx += 512) {
            int row = idx >> 4, c8 = idx & 15;
            if (row < nv) {
                size_t src = boff + (size_t)row * DD + c8 * 8;
                CP_ASYNC16(sbase + SM_KH + row * 272 + c8 * 16, g_Kh + src);
                CP_ASYNC16(sbase + SM_KL + row * 272 + c8 * 16, g_Kl + src);
            } else {
                *(uint4*)(smem + SM_KH + row * 272 + c8 * 16) = z;
                *(uint4*)(smem + SM_KL + row * 272 + c8 * 16) = z;
            }
        }
    }
    CP_COMMIT();
    CP_WAIT0();
    __syncthreads();

    // --- beta GEMM over valid 16-col tiles only (2-term: Qh*(Kh+Kl)) ---
    uint32_t aRow = (uint32_t)(16 * mw + (l & 15));
    uint32_t halfOff = (uint32_t)((l >> 4) << 3);
    uint32_t bRowBase = (uint32_t)(((l >> 4) << 3) + (l & 7));
    uint32_t bColHalf = (uint32_t)(((l >> 3) & 1) << 3);

    int base0 = nw * 64, base1 = 128 + nw * 64;
    int ns0 = min(4, max(0, (kpadN - base0) >> 4));
    int ns1 = min(4, max(0, (kpadN - base1) >> 4));

    float acc0[8][4], acc1[8][4];
#pragma unroll
    for (int j = 0; j < 8; j++)
#pragma unroll
        for (int q = 0; q < 4; q++) { acc0[j][q] = 0.f; acc1[j][q] = 0.f; }

    if (ns0 > 0) BETA_CHUNK(acc0, 0, ns0);
    if (ns1 > 0) BETA_CHUNK(acc1, 128, ns1);

    // --- masked softmax (rows rowA, rowB in 0..127) ---
    int rowA = 16 * mw + g, rowB = rowA + 8;
    float mx0 = -3.0e38f, mx1 = -3.0e38f;
#pragma unroll
    for (int j = 0; j < 8; j++) {
        float2 bv = *(const float2*)&s_bias[nw * 64 + j * 8 + 2 * t];
        acc0[j][0] += bv.x; acc0[j][1] += bv.y;
        acc0[j][2] += bv.x; acc0[j][3] += bv.y;
        mx0 = fmaxf(mx0, fmaxf(acc0[j][0], acc0[j][1]));
        mx1 = fmaxf(mx1, fmaxf(acc0[j][2], acc0[j][3]));
    }
    if (kpadN > 128) {
#pragma unroll
        for (int j = 0; j < 8; j++) {
            float2 bv = *(const float2*)&s_bias[128 + nw * 64 + j * 8 + 2 * t];
            acc1[j][0] += bv.x; acc1[j][1] += bv.y;
            acc1[j][2] += bv.x; acc1[j][3] += bv.y;
            mx0 = fmaxf(mx0, fmaxf(acc1[j][0], acc1[j][1]));
            mx1 = fmaxf(mx1, fmaxf(acc1[j][2], acc1[j][3]));
        }
    }
    mx0 = fmaxf(mx0, __shfl_xor_sync(0xffffffffu, mx0, 1));
    mx0 = fmaxf(mx0, __shfl_xor_sync(0xffffffffu, mx0, 2));
    mx1 = fmaxf(mx1, __shfl_xor_sync(0xffffffffu, mx1, 1));
    mx1 = fmaxf(mx1, __shfl_xor_sync(0xffffffffu, mx1, 2));
    if (t == 0) {
        s_red[nw * 128 + rowA] = mx0;
        s_red[nw * 128 + rowB] = mx1;
    }
    __syncthreads();   // <-- every thread past beta: K region retired

    // --- prefetch V (gathered, hi only) into dead K region via cp.async ---
    {
        uint4 z = make_uint4(0, 0, 0, 0);
        for (int idx = tid; idx < kpadN * 16; idx += 512) {
            int row = idx >> 4, c8 = idx & 15;
            if (row < nv) {
                CP_ASYNC16(sbase + SM_VH + row * 272 + c8 * 16,
                           g_Mh + boff + (size_t)s_idx[row] * DD + c8 * 8);
            } else {
                *(uint4*)(smem + SM_VH + row * 272 + c8 * 16) = z;
            }
        }
        CP_COMMIT();
    }

    // --- softmax continues while V streams in ---
    float M0 = fmaxf(s_red[rowA], s_red[128 + rowA]);
    float M1 = fmaxf(s_red[rowB], s_red[128 + rowB]);
    float s0 = 0.f, s1 = 0.f;
#pragma unroll
    for (int j = 0; j < 8; j++) {
        acc0[j][0] = __expf(acc0[j][0] - M0); s0 += acc0[j][0];
        acc0[j][1] = __expf(acc0[j][1] - M0); s0 += acc0[j][1];
        acc0[j][2] = __expf(acc0[j][2] - M1); s1 += acc0[j][2];
        acc0[j][3] = __expf(acc0[j][3] - M1); s1 += acc0[j][3];
    }
    if (kpadN > 128) {
#pragma unroll
        for (int j = 0; j < 8; j++) {
            acc1[j][0] = __expf(acc1[j][0] - M0); s0 += acc1[j][0];
            acc1[j][1] = __expf(acc1[j][1] - M0); s0 += acc1[j][1];
            acc1[j][2] = __expf(acc1[j][2] - M1); s1 += acc1[j][2];
            acc1[j][3] = __expf(acc1[j][3] - M1); s1 += acc1[j][3];
        }
    }
    s0 += __shfl_xor_sync(0xffffffffu, s0, 1);
    s0 += __shfl_xor_sync(0xffffffffu, s0, 2);
    s1 += __shfl_xor_sync(0xffffffffu, s1, 1);
    s1 += __shfl_xor_sync(0xffffffffu, s1, 2);
    __syncthreads();
    if (t == 0) {
        s_red[256 + nw * 128 + rowA] = s0;
        s_red[256 + nw * 128 + rowB] = s1;
    }
    __syncthreads();
    float inv0 = __fdividef(1.f, s_red[256 + rowA] + s_red[256 + 128 + rowA]);
    float inv1 = __fdividef(1.f, s_red[256 + rowB] + s_red[256 + 128 + rowB]);

    // --- write P (fp16 hi only) over dead Q + K-head region ---
    {
        char* ph = smem + SM_PH;
#pragma unroll
        for (int j = 0; j < 8; j++) {
            int col = nw * 64 + j * 8 + 2 * t;
            *(uint32_t*)(ph + rowA * 528 + col * 2) = pack_hi(acc0[j][0] * inv0, acc0[j][1] * inv0);
            *(uint32_t*)(ph + rowB * 528 + col * 2) = pack_hi(acc0[j][2] * inv1, acc0[j][3] * inv1);
        }
        if (kpadN > 128) {
#pragma unroll
            for (int j = 0; j < 8; j++) {
                int col = 128 + nw * 64 + j * 8 + 2 * t;
                *(uint32_t*)(ph + rowA * 528 + col * 2) = pack_hi(acc1[j][0] * inv0, acc1[j][1] * inv0);
                *(uint32_t*)(ph + rowB * 528 + col * 2) = pack_hi(acc1[j][2] * inv1, acc1[j][3] * inv1);
            }
        }
    }
    CP_WAIT0();      // V fully resident
    __syncthreads(); // P + V visible to all warps

    // --- PV GEMM: 1-term (P hi * V hi), k up to kpadN ---
    int d0 = 64 * nw;
    float o[8][4];
#pragma unroll
    for (int i = 0; i < 8; i++)
#pragma unroll
        for (int j = 0; j < 4; j++) o[i][j] = 0.f;

    int ksteps = kpadN >> 4;
#pragma unroll 1
    for (int ks = 0; ks < ksteps; ks++) {
        int k0 = 16 * ks;
        uint32_t aH[4];
        LDSM_X4(aH, sbase + SM_PH + aRow * 528 + (k0 + halfOff) * 2);
#pragma unroll
        for (int np = 0; np < 4; np++) {
            uint32_t baddr = sbase + SM_VH + (uint32_t)(k0 + (l & 15)) * 272 +
                             (uint32_t)(d0 + 16 * np + halfOff) * 2;
            uint32_t bH[4];
            LDSM_X4T(bH, baddr);
            mma_fp16(o[2 * np],     aH, bH[0], bH[1]);
            mma_fp16(o[2 * np + 1], aH, bH[2], bH[3]);
        }
    }

    float* Ob = O + ((size_t)b * NN + i0) * DD;
#pragma unroll
    for (int nt = 0; nt < 8; nt++) {
        int col = d0 + 8 * nt + 2 * t;
        *(float2*)&Ob[(size_t)rowA * DD + col] = make_float2(o[nt][0], o[nt][1]);
        *(float2*)&Ob[(size_t)rowB * DD + col] = make_float2(o[nt][2], o[nt][3]);
    }
}

// ---------------------------------------------------------------------------
extern "C" void kernel_launch(void* const* d_in, const int* in_sizes, int n_in,
                              void* d_out, int out_size) {
    (void)in_sizes; (void)n_in; (void)out_size;
    const float* mirror    = (const float*)d_in[0];
    const float* satellite = (const float*)d_in[1];
    const void*  mask      = d_in[2];
    const float* Wq1 = (const float*)d_in[3];
    const float* Wk1 = (const float*)d_in[4];
    const float* Wq2 = (const float*)d_in[5];
    const float* Wk2 = (const float*)d_in[6];
    float* sat_out = (float*)d_out;
    float* mir_out = (float*)d_out + BND;

    cudaFuncSetAttribute(gemm_T_fused,    cudaFuncAttributeMaxDynamicSharedMemorySize, GT_SMEM);
    cudaFuncSetAttribute(gemm_K2C_kernel, cudaFuncAttributeMaxDynamicSharedMemorySize, GK_SMEM);
    cudaFuncSetAttribute(attn_kernel,     cudaFuncAttributeMaxDynamicSharedMemorySize, SMEM_ATTN);

    prep_w_kernel<<<dim3(128, 2), 512>>>(Wq1, Wk1, Wq2, Wk2);   // also zeroes g_nitems
    decode_compact_kernel<<<BB, 256>>>(mask);                   // appends work items

    gemm_T_fused<<<296, 256, GT_SMEM>>>(mirror, satellite, sat_out);
    gemm_K2C_kernel<<<296, 256, GK_SMEM>>>();
    attn_kernel<<<dim3(NN / 128, BB), 512, SMEM_ATTN>>>(mir_out);
}